// round 4
// baseline (speedup 1.0000x reference)
#include <cuda_runtime.h>

// ---------------------------------------------------------------------------
// Problem constants
// ---------------------------------------------------------------------------
#define BB  4
#define TT  1024
#define DD  256
#define HH  8
#define CC  16
#define BT  (BB*TT)          // 4096

typedef unsigned long long ull;

__device__ __forceinline__ ull pk2(float lo, float hi) {
    ull r; asm("mov.b64 %0, {%1, %2};" : "=l"(r) : "f"(lo), "f"(hi)); return r;
}
__device__ __forceinline__ void upk2(ull v, float& lo, float& hi) {
    asm("mov.b64 {%0, %1}, %2;" : "=f"(lo), "=f"(hi) : "l"(v));
}
#define FMA2(d, a, b, c) asm("fma.rn.f32x2 %0, %1, %2, %3;" : "=l"(d) : "l"(a), "l"(b), "l"(c))

// ---------------------------------------------------------------------------
// Scratch
// ---------------------------------------------------------------------------
__device__ float g_qraw[BT*DD];
__device__ float g_kraw[BT*DD];
__device__ float g_vraw[BT*DD];
__device__ float g_q[BT*DD];     // [(b*H+h)*T + t]*32 + k   (normalized)
__device__ float g_k[BT*DD];
__device__ float g_v[BT*DD];
__device__ float g_att[BT*DD];   // [bt*256 + h*32 + c]
__device__ float g_y[BT*DD];
__device__ float g_zz[BT*DD];
__device__ float g_ff[BT*DD];
__device__ float g_md[BB*TT*TT]; // fused masked-dist: mask ? 4.0 : d
__device__ float g_coef[HH*34];  // per head: K0,K1, beta[16], delta[16]
__device__ float2 g_lut[HH*1024];// per head per cell: (-A, -B) of local segment
__device__ int   g_mask_flags;

// ---------------------------------------------------------------------------
// bias_h(d) = K0 + K1*d + sum_c beta_c * |d - delta_c|
// (lrelu(h) = 0.505*h + 0.495*|h| for slope 0.01)
// ---------------------------------------------------------------------------
__global__ void prep_kernel(const float* __restrict__ pw1, const float* __restrict__ pb1,
                            const float* __restrict__ pw2, const float* __restrict__ pb2)
{
    if (threadIdx.x == 0) g_mask_flags = 0;
    int h = threadIdx.x >> 4;
    int c = threadIdx.x & 15;
    if (h >= HH) return;
    float w1 = pw1[h*CC + c], b1 = pb1[h*CC + c], w2 = pw2[h*CC + c];
    float beta, delta, k0add, k1add;
    if (w1 != 0.0f) {
        beta  = 0.495f * w2 * fabsf(w1);
        delta = -b1 / w1;
        k0add = 0.505f * w2 * b1;
        k1add = 0.505f * w2 * w1;
    } else {
        beta = 0.0f; delta = 0.0f;
        k0add = w2 * (0.505f * b1 + 0.495f * fabsf(b1));
        k1add = 0.0f;
    }
    #pragma unroll
    for (int off = 1; off < 16; off <<= 1) {
        k0add += __shfl_xor_sync(0xffffffffu, k0add, off);
        k1add += __shfl_xor_sync(0xffffffffu, k1add, off);
    }
    g_coef[h*34 + 2  + c] = beta;
    g_coef[h*34 + 18 + c] = delta;
    if (c == 0) {
        g_coef[h*34 + 0] = pb2[h] + k0add;
        g_coef[h*34 + 1] = k1add;
    }
}

// Build per-head 1024-cell piecewise-linear LUT over d in [0,1):
// cell i stores (-A, -B) with bias(d) = A + B*d on that cell (segment at midpoint).
__global__ void lut_kernel()
{
    int i = blockIdx.x * blockDim.x + threadIdx.x;   // 0..8191
    int h = i >> 10, cell = i & 1023;
    float m = (cell + 0.5f) * (1.0f / 1024.0f);
    float A = g_coef[h*34 + 0];
    float B = g_coef[h*34 + 1];
    #pragma unroll
    for (int c = 0; c < 16; c++) {
        float be = g_coef[h*34 + 2 + c], de = g_coef[h*34 + 18 + c];
        float s = (m >= de) ? 1.0f : -1.0f;
        B += be * s;
        A -= be * de * s;
    }
    g_lut[i] = make_float2(-A, -B);
}

// ---------------------------------------------------------------------------
// Mask dtype sniffer (first 256KB of words; safe under all dtype hypotheses).
// ---------------------------------------------------------------------------
__global__ void detect_kernel(const unsigned* __restrict__ w)
{
    int i = blockIdx.x * blockDim.x + threadIdx.x;
    unsigned x = w[i];
    int f = 0;
    if (x == 0x3F800000u)               f = 2;
    else if ((x & 0xFFFFu) == 0x3F80u)  f = 4;
    else if (x > 1u)                    f = 1;
    if (f) atomicOr(&g_mask_flags, f);
}

// ---------------------------------------------------------------------------
// Fuse mask into distances once: md = mask ? 4.0 : d. (d is uniform [0,1).)
// ---------------------------------------------------------------------------
__global__ __launch_bounds__(256) void maskfuse_kernel(const float* __restrict__ rd,
                                                       const void* __restrict__ maskp)
{
    int i = blockIdx.x * 256 + threadIdx.x;
    size_t base = (size_t)i * 4;
    int mf = g_mask_flags;
    int mode = (mf & 4) ? 3 : (mf & 2) ? 2 : (mf & 1) ? 1 : 0;
    float4 d4 = *(const float4*)&rd[base];
    int m0, m1, m2, m3;
    if (mode == 0) {
        int4 m = *(const int4*)((const int*)maskp + base);
        m0 = m.x != 0; m1 = m.y != 0; m2 = m.z != 0; m3 = m.w != 0;
    } else if (mode == 1) {
        uchar4 m = *(const uchar4*)((const unsigned char*)maskp + base);
        m0 = m.x != 0; m1 = m.y != 0; m2 = m.z != 0; m3 = m.w != 0;
    } else if (mode == 2) {
        float4 m = *(const float4*)((const float*)maskp + base);
        m0 = m.x != 0.0f; m1 = m.y != 0.0f; m2 = m.z != 0.0f; m3 = m.w != 0.0f;
    } else {
        ushort4 m = *(const ushort4*)((const unsigned short*)maskp + base);
        m0 = m.x != 0; m1 = m.y != 0; m2 = m.z != 0; m3 = m.w != 0;
    }
    d4.x = m0 ? 4.0f : d4.x;
    d4.y = m1 ? 4.0f : d4.y;
    d4.z = m2 ? 4.0f : d4.z;
    d4.w = m3 ? 4.0f : d4.w;
    *(float4*)&g_md[base] = d4;
}

// ---------------------------------------------------------------------------
// SGEMM: C[4096,256] = A[4096,256] @ Bw[256,256]^T (+bias) (+lrelu)
// 64x64 tiles, BK=32, 256 threads, 4x4 microtile.
// A stored DUPLICATED in smem so inner loop is 3 LDS.128 + 8 FMA2 per kk.
// ---------------------------------------------------------------------------
__global__ __launch_bounds__(256) void sgemm64(const float* __restrict__ A,
                                               const float* __restrict__ Bw0,
                                               const float* __restrict__ Bw1,
                                               const float* __restrict__ Bw2,
                                               const float* __restrict__ bias,
                                               float* __restrict__ C0,
                                               float* __restrict__ C1,
                                               float* __restrict__ C2,
                                               int act)
{
    __shared__ float Asd[32*140];   // [k][dup-row 128 + pad]
    __shared__ float Bs [32*68];    // [k][col 64 + pad]
    const float* Bw = (blockIdx.z == 0) ? Bw0 : (blockIdx.z == 1) ? Bw1 : Bw2;
    float*       C  = (blockIdx.z == 0) ? C0  : (blockIdx.z == 1) ? C1  : C2;
    int tid = threadIdx.x;
    int ty = tid >> 4, tx = tid & 15;
    int m0 = blockIdx.x * 64, n0 = blockIdx.y * 64;
    ull acc2[4][2];
    #pragma unroll
    for (int i = 0; i < 4; i++) { acc2[i][0] = 0ull; acc2[i][1] = 0ull; }
    for (int kt = 0; kt < 256; kt += 32) {
        #pragma unroll
        for (int r = 0; r < 2; r++) {
            int id = tid + r * 256;
            int row = id >> 3, fc = id & 7;
            float4 a4 = *(const float4*)&A [(size_t)(m0 + row) * 256 + kt + fc * 4];
            *(float2*)&Asd[(fc*4+0)*140 + row*2] = make_float2(a4.x, a4.x);
            *(float2*)&Asd[(fc*4+1)*140 + row*2] = make_float2(a4.y, a4.y);
            *(float2*)&Asd[(fc*4+2)*140 + row*2] = make_float2(a4.z, a4.z);
            *(float2*)&Asd[(fc*4+3)*140 + row*2] = make_float2(a4.w, a4.w);
            float4 b4 = *(const float4*)&Bw[(size_t)(n0 + row) * 256 + kt + fc * 4];
            Bs[(fc*4+0)*68 + row] = b4.x; Bs[(fc*4+1)*68 + row] = b4.y;
            Bs[(fc*4+2)*68 + row] = b4.z; Bs[(fc*4+3)*68 + row] = b4.w;
        }
        __syncthreads();
        #pragma unroll
        for (int kk = 0; kk < 32; kk++) {
            ulonglong2 a01 = *(const ulonglong2*)&Asd[kk*140 + ty*8];
            ulonglong2 a23 = *(const ulonglong2*)&Asd[kk*140 + ty*8 + 4];
            ulonglong2 bp  = *(const ulonglong2*)&Bs [kk*68  + tx*4];
            FMA2(acc2[0][0], a01.x, bp.x, acc2[0][0]);
            FMA2(acc2[0][1], a01.x, bp.y, acc2[0][1]);
            FMA2(acc2[1][0], a01.y, bp.x, acc2[1][0]);
            FMA2(acc2[1][1], a01.y, bp.y, acc2[1][1]);
            FMA2(acc2[2][0], a23.x, bp.x, acc2[2][0]);
            FMA2(acc2[2][1], a23.x, bp.y, acc2[2][1]);
            FMA2(acc2[3][0], a23.y, bp.x, acc2[3][0]);
            FMA2(acc2[3][1], a23.y, bp.y, acc2[3][1]);
        }
        __syncthreads();
    }
    float bb[4];
    #pragma unroll
    for (int j = 0; j < 4; j++) bb[j] = bias ? bias[n0 + tx*4 + j] : 0.0f;
    #pragma unroll
    for (int i = 0; i < 4; i++) {
        float av[4];
        upk2(acc2[i][0], av[0], av[1]);
        upk2(acc2[i][1], av[2], av[3]);
        float4 o;
        float* po = &o.x;
        #pragma unroll
        for (int j = 0; j < 4; j++) {
            float v = av[j] + bb[j];
            if (act) v = (v >= 0.0f) ? v : 0.01f * v;
            po[j] = v;
        }
        *(float4*)&C[(size_t)(m0 + ty*4 + i) * 256 + n0 + tx*4] = o;
    }
}

// ---------------------------------------------------------------------------
// L2-normalize q,k along DK and transpose into [(b*H+h)*T+t]*32 layout.
// ---------------------------------------------------------------------------
__global__ __launch_bounds__(256) void qkv_finish_kernel()
{
    int gw   = (blockIdx.x * 256 + threadIdx.x) >> 5;
    int lane = threadIdx.x & 31;
    int bt = gw >> 3, h = gw & 7;
    int b  = bt >> 10, t = bt & 1023;
    size_t src = (size_t)bt * 256 + h * 32 + lane;
    size_t dst = (((size_t)(b * HH + h) * TT) + t) * 32 + lane;
    float qv = g_qraw[src], kv = g_kraw[src], vv = g_vraw[src];
    float sq = qv * qv, sk = kv * kv;
    #pragma unroll
    for (int off = 16; off; off >>= 1) {
        sq += __shfl_xor_sync(0xffffffffu, sq, off);
        sk += __shfl_xor_sync(0xffffffffu, sk, off);
    }
    g_q[dst] = qv / fmaxf(sqrtf(sq), 1e-12f);
    g_k[dst] = kv / fmaxf(sqrtf(sk), 1e-12f);
    g_v[dst] = vv;
}

// ---------------------------------------------------------------------------
// Attention. Dynamic smem layout (floats):
//   sQd  [32][132]  q dup-rows          @ 0       (4224)
//   sK   [32][68]   k col-major         @ 4224    (2176)
//   sVd  [64][68]   v dup-cols          @ 6400    (4352)
//   sPT  [64][68]   md tile, then P^T   @ 10752   (4352)
//   sLUT float2[1024]                   @ 15104   (2048)
// total 17152 floats = 68608 bytes
// ---------------------------------------------------------------------------
#define OFF_QD  0
#define OFF_K   4224
#define OFF_VD  6400
#define OFF_PT  10752
#define OFF_LUT 15104
#define ATTN_SMEM (17152*4)

__global__ __launch_bounds__(256) void attn_kernel()
{
    extern __shared__ float sm[];
    float* sQd = sm + OFF_QD;
    float* sK  = sm + OFF_K;
    float* sVd = sm + OFF_VD;
    float* sPT = sm + OFF_PT;
    float2* sLUT = (float2*)(sm + OFF_LUT);

    int tid = threadIdx.x;
    int ty = tid >> 4, tx = tid & 15;
    int bh = blockIdx.y;
    int b = bh >> 3, h = bh & 7;
    int t0 = blockIdx.x << 6;
    const float* qb = g_q + (size_t)bh * (TT * 32);
    const float* kb = g_k + (size_t)bh * (TT * 32);
    const float* vb = g_v + (size_t)bh * (TT * 32);

    // load Q tile duplicated
    #pragma unroll
    for (int r = 0; r < 2; r++) {
        int id = tid + r * 256;
        int row = id >> 3, fc = id & 7;
        float4 q4 = *(const float4*)&qb[(size_t)(t0 + row) * 32 + fc * 4];
        *(float2*)&sQd[(fc*4+0)*132 + row*2] = make_float2(q4.x, q4.x);
        *(float2*)&sQd[(fc*4+1)*132 + row*2] = make_float2(q4.y, q4.y);
        *(float2*)&sQd[(fc*4+2)*132 + row*2] = make_float2(q4.z, q4.z);
        *(float2*)&sQd[(fc*4+3)*132 + row*2] = make_float2(q4.w, q4.w);
    }
    // load per-head LUT (8KB)
    #pragma unroll
    for (int r = 0; r < 4; r++) {
        int i = tid + r * 256;
        sLUT[i] = g_lut[h * 1024 + i];
    }
    __syncthreads();

    ull oacc[2][2];      // [row-pair][col]  rows packed
    oacc[0][0] = oacc[0][1] = oacc[1][0] = oacc[1][1] = 0ull;
    float rs[4] = {0.f, 0.f, 0.f, 0.f};
    size_t mrow_base = (size_t)b * TT * TT + (size_t)t0 * TT;

    #pragma unroll 1
    for (int st = 0; st < 16; st++) {
        int s0 = st << 6;
        #pragma unroll
        for (int r = 0; r < 2; r++) {
            int id = tid + r * 256;
            int row = id >> 3, fc = id & 7;
            float4 k4 = *(const float4*)&kb[(size_t)(s0 + row) * 32 + fc * 4];
            sK[(fc*4+0)*68 + row] = k4.x; sK[(fc*4+1)*68 + row] = k4.y;
            sK[(fc*4+2)*68 + row] = k4.z; sK[(fc*4+3)*68 + row] = k4.w;
            float4 v4 = *(const float4*)&vb[(size_t)(s0 + row) * 32 + fc * 4];
            *(float4*)&sVd[row*68 + fc*8]     = make_float4(v4.x, v4.x, v4.y, v4.y);
            *(float4*)&sVd[row*68 + fc*8 + 4] = make_float4(v4.z, v4.z, v4.w, v4.w);
        }
        const float* db = g_md + mrow_base + s0;
        #pragma unroll
        for (int r = 0; r < 4; r++) {
            int id = tid + r * 256;
            int row = id >> 4, fc = id & 15;
            float4 d4 = *(const float4*)&db[(size_t)row * TT + fc * 4];
            *(float4*)&sPT[row*68 + fc*4] = d4;
        }
        __syncthreads();

        // pull masked-dist values into registers
        float dv[4][4];
        #pragma unroll
        for (int i = 0; i < 4; i++) {
            float4 d4 = *(const float4*)&sPT[(ty*4+i)*68 + tx*4];
            dv[i][0] = d4.x; dv[i][1] = d4.y; dv[i][2] = d4.z; dv[i][3] = d4.w;
        }
        __syncthreads();   // md fully consumed before transposed overwrite

        // bias via LUT: acc starts at -(A + B*d)
        ull acc2[4][2];
        #pragma unroll
        for (int i = 0; i < 4; i++) {
            #pragma unroll
            for (int p = 0; p < 2; p++) {
                float d0 = dv[i][2*p], d1 = dv[i][2*p+1];
                int i0 = min(__float2int_rd(d0 * 1024.0f), 1023);
                int i1 = min(__float2int_rd(d1 * 1024.0f), 1023);
                float2 ab0 = sLUT[i0];
                float2 ab1 = sLUT[i1];
                acc2[i][p] = pk2(fmaf(ab0.y, d0, ab0.x), fmaf(ab1.y, d1, ab1.x));
            }
        }
        // QK
        #pragma unroll
        for (int kk = 0; kk < 32; kk++) {
            ulonglong2 a01 = *(const ulonglong2*)&sQd[kk*132 + ty*8];
            ulonglong2 a23 = *(const ulonglong2*)&sQd[kk*132 + ty*8 + 4];
            ulonglong2 bp  = *(const ulonglong2*)&sK [kk*68  + tx*4];
            FMA2(acc2[0][0], a01.x, bp.x, acc2[0][0]);
            FMA2(acc2[0][1], a01.x, bp.y, acc2[0][1]);
            FMA2(acc2[1][0], a01.y, bp.x, acc2[1][0]);
            FMA2(acc2[1][1], a01.y, bp.y, acc2[1][1]);
            FMA2(acc2[2][0], a23.x, bp.x, acc2[2][0]);
            FMA2(acc2[2][1], a23.x, bp.y, acc2[2][1]);
            FMA2(acc2[3][0], a23.y, bp.x, acc2[3][0]);
            FMA2(acc2[3][1], a23.y, bp.y, acc2[3][1]);
        }
        // z = masked ? 0 : exp(logit); store transposed
        float zz[4][4];
        #pragma unroll
        for (int i = 0; i < 4; i++) {
            float l0, l1, l2, l3;
            upk2(acc2[i][0], l0, l1);
            upk2(acc2[i][1], l2, l3);
            float z0 = (dv[i][0] > 2.0f) ? 0.0f : __expf(l0);
            float z1 = (dv[i][1] > 2.0f) ? 0.0f : __expf(l1);
            float z2 = (dv[i][2] > 2.0f) ? 0.0f : __expf(l2);
            float z3 = (dv[i][3] > 2.0f) ? 0.0f : __expf(l3);
            rs[i] += (z0 + z1) + (z2 + z3);
            zz[i][0] = z0; zz[i][1] = z1; zz[i][2] = z2; zz[i][3] = z3;
        }
        #pragma unroll
        for (int j = 0; j < 4; j++)
            *(float4*)&sPT[(tx*4+j)*68 + ty*4] =
                make_float4(zz[0][j], zz[1][j], zz[2][j], zz[3][j]);
        __syncthreads();

        // O += P @ V  (rows packed in pairs, V duplicated)
        #pragma unroll
        for (int s = 0; s < 64; s++) {
            ulonglong2 pp = *(const ulonglong2*)&sPT[s*68 + ty*4];
            ulonglong2 vd = *(const ulonglong2*)&sVd[s*68 + tx*4];
            FMA2(oacc[0][0], pp.x, vd.x, oacc[0][0]);
            FMA2(oacc[0][1], pp.x, vd.y, oacc[0][1]);
            FMA2(oacc[1][0], pp.y, vd.x, oacc[1][0]);
            FMA2(oacc[1][1], pp.y, vd.y, oacc[1][1]);
        }
        __syncthreads();
    }

    // finalize: reduce rowsums across the 16 tx lanes, divide, store
    float inv[4];
    #pragma unroll
    for (int i = 0; i < 4; i++) {
        float s = rs[i];
        #pragma unroll
        for (int off = 1; off < 16; off <<= 1)
            s += __shfl_xor_sync(0xffffffffu, s, off);
        inv[i] = 1.0f / (s + 1e-5f);
    }
    float o00,o10,o01,o11,o20,o30,o21,o31;
    upk2(oacc[0][0], o00, o10);   // rows 0,1 col0
    upk2(oacc[0][1], o01, o11);   // rows 0,1 col1
    upk2(oacc[1][0], o20, o30);
    upk2(oacc[1][1], o21, o31);
    float ov[4][2] = {{o00,o01},{o10,o11},{o20,o21},{o30,o31}};
    #pragma unroll
    for (int i = 0; i < 4; i++) {
        int t = t0 + ty*4 + i;
        float2 o2 = make_float2(ov[i][0] * inv[i], ov[i][1] * inv[i]);
        *(float2*)&g_att[((size_t)b * TT + t) * DD + h * 32 + tx*2] = o2;
    }
}

// ---------------------------------------------------------------------------
// out = LayerNorm(a + b) * g + beta.  One warp per row of 256.
// ---------------------------------------------------------------------------
__global__ __launch_bounds__(256) void ln_kernel(const float* __restrict__ a,
                                                 const float* __restrict__ b,
                                                 const float* __restrict__ g,
                                                 const float* __restrict__ be,
                                                 float* __restrict__ out)
{
    int w    = (blockIdx.x * 256 + threadIdx.x) >> 5;
    int lane = threadIdx.x & 31;
    const float* ap = a + (size_t)w * 256;
    const float* bp = b + (size_t)w * 256;
    float v[8]; float s = 0.0f;
    #pragma unroll
    for (int u = 0; u < 8; u++) { v[u] = ap[lane + 32*u] + bp[lane + 32*u]; s += v[u]; }
    #pragma unroll
    for (int off = 16; off; off >>= 1) s += __shfl_xor_sync(0xffffffffu, s, off);
    float mu = s * (1.0f / 256.0f);
    float vs = 0.0f;
    #pragma unroll
    for (int u = 0; u < 8; u++) { float d = v[u] - mu; vs = fmaf(d, d, vs); }
    #pragma unroll
    for (int off = 16; off; off >>= 1) vs += __shfl_xor_sync(0xffffffffu, vs, off);
    float rstd = rsqrtf(vs * (1.0f / 256.0f) + 1e-5f);
    #pragma unroll
    for (int u = 0; u < 8; u++) {
        int col = lane + 32*u;
        out[(size_t)w * 256 + col] = (v[u] - mu) * rstd * g[col] + be[col];
    }
}

// ---------------------------------------------------------------------------
// Launch
// ---------------------------------------------------------------------------
extern "C" void kernel_launch(void* const* d_in, const int* in_sizes, int n_in,
                              void* d_out, int out_size)
{
    const float* x    = (const float*)d_in[0];
    const void*  mask = d_in[1];
    const float* rel  = (const float*)d_in[2];
    const float* Wq   = (const float*)d_in[3];
    const float* Wk   = (const float*)d_in[4];
    const float* Wv   = (const float*)d_in[5];
    const float* pw1  = (const float*)d_in[6];
    const float* pb1  = (const float*)d_in[7];
    const float* pw2  = (const float*)d_in[8];
    const float* pb2  = (const float*)d_in[9];
    const float* Wo   = (const float*)d_in[10];
    const float* bo   = (const float*)d_in[11];
    const float* Wf   = (const float*)d_in[12];
    const float* bfv  = (const float*)d_in[13];
    const float* g1   = (const float*)d_in[14];
    const float* be1  = (const float*)d_in[15];
    const float* g2   = (const float*)d_in[16];
    const float* be2  = (const float*)d_in[17];

    float *qraw, *kraw, *vraw, *att, *y, *zz, *ff;
    cudaGetSymbolAddress((void**)&qraw, g_qraw);
    cudaGetSymbolAddress((void**)&kraw, g_kraw);
    cudaGetSymbolAddress((void**)&vraw, g_vraw);
    cudaGetSymbolAddress((void**)&att,  g_att);
    cudaGetSymbolAddress((void**)&y,    g_y);
    cudaGetSymbolAddress((void**)&zz,   g_zz);
    cudaGetSymbolAddress((void**)&ff,   g_ff);

    static int smem_set = 0;
    if (!smem_set) {
        cudaFuncSetAttribute(attn_kernel, cudaFuncAttributeMaxDynamicSharedMemorySize,
                             ATTN_SMEM);
        smem_set = 1;
    }

    prep_kernel<<<1, 128>>>(pw1, pb1, pw2, pb2);
    lut_kernel<<<8, 1024>>>();
    detect_kernel<<<256, 256>>>((const unsigned*)mask);
    maskfuse_kernel<<<4096, 256>>>(rel, mask);

    sgemm64<<<dim3(64, 4, 3), 256>>>(x, Wq, Wk, Wv, nullptr, qraw, kraw, vraw, 0);
    qkv_finish_kernel<<<4096, 256>>>();

    attn_kernel<<<dim3(16, 32), 256, ATTN_SMEM>>>();

    sgemm64<<<dim3(64, 4, 1), 256>>>(att, Wo, Wo, Wo, bo, y, y, y, 0);
    ln_kernel<<<512, 256>>>(x, y, g1, be1, zz);
    sgemm64<<<dim3(64, 4, 1), 256>>>(zz, Wf, Wf, Wf, bfv, ff, ff, ff, 1);
    ln_kernel<<<512, 256>>>(zz, ff, g2, be2, (float*)d_out);
}

// round 5
// speedup vs baseline: 1.3771x; 1.3771x over previous
#include <cuda_runtime.h>

// ---------------------------------------------------------------------------
// Problem constants
// ---------------------------------------------------------------------------
#define BB  4
#define TT  1024
#define DD  256
#define HH  8
#define CC  16
#define BT  (BB*TT)          // 4096

typedef unsigned long long ull;

__device__ __forceinline__ ull pk2(float lo, float hi) {
    ull r; asm("mov.b64 %0, {%1, %2};" : "=l"(r) : "f"(lo), "f"(hi)); return r;
}
__device__ __forceinline__ void upk2(ull v, float& lo, float& hi) {
    asm("mov.b64 {%0, %1}, %2;" : "=f"(lo), "=f"(hi) : "l"(v));
}
#define FMA2(d, a, b, c) asm("fma.rn.f32x2 %0, %1, %2, %3;" : "=l"(d) : "l"(a), "l"(b), "l"(c))

// ---------------------------------------------------------------------------
// Scratch
// ---------------------------------------------------------------------------
__device__ float g_qraw[BT*DD];
__device__ float g_kraw[BT*DD];
__device__ float g_vraw[BT*DD];
__device__ float g_q[BT*DD];     // [(b*H+h)*T + t]*32 + k   (normalized)
__device__ float g_k[BT*DD];
__device__ float g_v[BT*DD];
__device__ float g_att[BT*DD];   // [bt*256 + h*32 + c]
__device__ float g_y[BT*DD];
__device__ float g_zz[BT*DD];
__device__ float g_ff[BT*DD];
__device__ unsigned short g_mdx[BB*TT*TT]; // u16: mask ? 2047 : min(int(d*1024),1023)
__device__ float g_coef[HH*34];  // per head: K0,K1, beta[16], delta[16]
__device__ float g_lutv[HH*1024];// per head per cell: -bias(midpoint)
__device__ int   g_mask_flags;

// ---------------------------------------------------------------------------
// bias_h(d) = K0 + K1*d + sum_c beta_c * |d - delta_c|
// (lrelu(h) = 0.505*h + 0.495*|h| for slope 0.01)
// ---------------------------------------------------------------------------
__global__ void prep_kernel(const float* __restrict__ pw1, const float* __restrict__ pb1,
                            const float* __restrict__ pw2, const float* __restrict__ pb2)
{
    if (threadIdx.x == 0) g_mask_flags = 0;
    int h = threadIdx.x >> 4;
    int c = threadIdx.x & 15;
    if (h >= HH) return;
    float w1 = pw1[h*CC + c], b1 = pb1[h*CC + c], w2 = pw2[h*CC + c];
    float beta, delta, k0add, k1add;
    if (w1 != 0.0f) {
        beta  = 0.495f * w2 * fabsf(w1);
        delta = -b1 / w1;
        k0add = 0.505f * w2 * b1;
        k1add = 0.505f * w2 * w1;
    } else {
        beta = 0.0f; delta = 0.0f;
        k0add = w2 * (0.505f * b1 + 0.495f * fabsf(b1));
        k1add = 0.0f;
    }
    #pragma unroll
    for (int off = 1; off < 16; off <<= 1) {
        k0add += __shfl_xor_sync(0xffffffffu, k0add, off);
        k1add += __shfl_xor_sync(0xffffffffu, k1add, off);
    }
    g_coef[h*34 + 2  + c] = beta;
    g_coef[h*34 + 18 + c] = delta;
    if (c == 0) {
        g_coef[h*34 + 0] = pb2[h] + k0add;
        g_coef[h*34 + 1] = k1add;
    }
}

// Per-head 1024-cell LUT of -bias evaluated at cell midpoints.
__global__ void lut_kernel()
{
    int i = blockIdx.x * blockDim.x + threadIdx.x;   // 0..8191
    int h = i >> 10, cell = i & 1023;
    float m = (cell + 0.5f) * (1.0f / 1024.0f);
    float v = g_coef[h*34 + 0] + g_coef[h*34 + 1] * m;
    #pragma unroll
    for (int c = 0; c < 16; c++) {
        float be = g_coef[h*34 + 2 + c], de = g_coef[h*34 + 18 + c];
        v += be * fabsf(m - de);
    }
    g_lutv[i] = -v;
}

// ---------------------------------------------------------------------------
// Mask dtype sniffer (first 256KB of words; safe under all dtype hypotheses).
// ---------------------------------------------------------------------------
__global__ void detect_kernel(const unsigned* __restrict__ w)
{
    int i = blockIdx.x * blockDim.x + threadIdx.x;
    unsigned x = w[i];
    int f = 0;
    if (x == 0x3F800000u)               f = 2;
    else if ((x & 0xFFFFu) == 0x3F80u)  f = 4;
    else if (x > 1u)                    f = 1;
    if (f) atomicOr(&g_mask_flags, f);
}

// ---------------------------------------------------------------------------
// Fuse mask + quantize distance: v = mask ? 2047 : min(int(d*1024),1023) (u16)
// ---------------------------------------------------------------------------
__global__ __launch_bounds__(256) void maskfuse_kernel(const float* __restrict__ rd,
                                                       const void* __restrict__ maskp)
{
    int i = blockIdx.x * 256 + threadIdx.x;
    size_t base = (size_t)i * 4;
    int mf = g_mask_flags;
    int mode = (mf & 4) ? 3 : (mf & 2) ? 2 : (mf & 1) ? 1 : 0;
    float4 d4 = *(const float4*)&rd[base];
    int m0, m1, m2, m3;
    if (mode == 0) {
        int4 m = *(const int4*)((const int*)maskp + base);
        m0 = m.x != 0; m1 = m.y != 0; m2 = m.z != 0; m3 = m.w != 0;
    } else if (mode == 1) {
        uchar4 m = *(const uchar4*)((const unsigned char*)maskp + base);
        m0 = m.x != 0; m1 = m.y != 0; m2 = m.z != 0; m3 = m.w != 0;
    } else if (mode == 2) {
        float4 m = *(const float4*)((const float*)maskp + base);
        m0 = m.x != 0.0f; m1 = m.y != 0.0f; m2 = m.z != 0.0f; m3 = m.w != 0.0f;
    } else {
        ushort4 m = *(const ushort4*)((const unsigned short*)maskp + base);
        m0 = m.x != 0; m1 = m.y != 0; m2 = m.z != 0; m3 = m.w != 0;
    }
    int i0 = min(max(__float2int_rd(d4.x * 1024.0f), 0), 1023);
    int i1 = min(max(__float2int_rd(d4.y * 1024.0f), 0), 1023);
    int i2 = min(max(__float2int_rd(d4.z * 1024.0f), 0), 1023);
    int i3 = min(max(__float2int_rd(d4.w * 1024.0f), 0), 1023);
    ushort4 o;
    o.x = (unsigned short)(m0 ? 2047 : i0);
    o.y = (unsigned short)(m1 ? 2047 : i1);
    o.z = (unsigned short)(m2 ? 2047 : i2);
    o.w = (unsigned short)(m3 ? 2047 : i3);
    *(ushort4*)&g_mdx[base] = o;
}

// ---------------------------------------------------------------------------
// SGEMM: C[4096,256] = A[4096,256] @ Bw[256,256]^T (+bias) (+lrelu)
// 64x64 tiles, BK=32, 256 threads, 4x4 microtile, packed f32x2 FMA.
// blockIdx.z selects among 3 (Bw, C) pairs so QKV runs as one launch.
// (identical to the 330us-round version)
// ---------------------------------------------------------------------------
__global__ __launch_bounds__(256) void sgemm64(const float* __restrict__ A,
                                               const float* __restrict__ Bw0,
                                               const float* __restrict__ Bw1,
                                               const float* __restrict__ Bw2,
                                               const float* __restrict__ bias,
                                               float* __restrict__ C0,
                                               float* __restrict__ C1,
                                               float* __restrict__ C2,
                                               int act)
{
    __shared__ float As[32][68];
    __shared__ float Bs[32][68];
    const float* Bw = (blockIdx.z == 0) ? Bw0 : (blockIdx.z == 1) ? Bw1 : Bw2;
    float*       C  = (blockIdx.z == 0) ? C0  : (blockIdx.z == 1) ? C1  : C2;
    int tid = threadIdx.x;
    int ty = tid >> 4, tx = tid & 15;
    int m0 = blockIdx.x * 64, n0 = blockIdx.y * 64;
    ull acc2[4][2];
    #pragma unroll
    for (int i = 0; i < 4; i++) { acc2[i][0] = 0ull; acc2[i][1] = 0ull; }
    for (int kt = 0; kt < 256; kt += 32) {
        #pragma unroll
        for (int r = 0; r < 2; r++) {
            int id = tid + r * 256;
            int row = id >> 3, fc = id & 7;
            float4 a4 = *(const float4*)&A [(size_t)(m0 + row) * 256 + kt + fc * 4];
            As[fc*4+0][row] = a4.x; As[fc*4+1][row] = a4.y;
            As[fc*4+2][row] = a4.z; As[fc*4+3][row] = a4.w;
            float4 b4 = *(const float4*)&Bw[(size_t)(n0 + row) * 256 + kt + fc * 4];
            Bs[fc*4+0][row] = b4.x; Bs[fc*4+1][row] = b4.y;
            Bs[fc*4+2][row] = b4.z; Bs[fc*4+3][row] = b4.w;
        }
        __syncthreads();
        #pragma unroll
        for (int kk = 0; kk < 32; kk++) {
            float4 a4 = *(const float4*)&As[kk][ty*4];
            ulonglong2 bp = *(const ulonglong2*)&Bs[kk][tx*4];
            float a[4] = {a4.x, a4.y, a4.z, a4.w};
            #pragma unroll
            for (int i = 0; i < 4; i++) {
                ull aB = pk2(a[i], a[i]);
                FMA2(acc2[i][0], aB, bp.x, acc2[i][0]);
                FMA2(acc2[i][1], aB, bp.y, acc2[i][1]);
            }
        }
        __syncthreads();
    }
    float bb[4];
    #pragma unroll
    for (int j = 0; j < 4; j++) bb[j] = bias ? bias[n0 + tx*4 + j] : 0.0f;
    #pragma unroll
    for (int i = 0; i < 4; i++) {
        float av[4];
        upk2(acc2[i][0], av[0], av[1]);
        upk2(acc2[i][1], av[2], av[3]);
        float4 o;
        float* po = &o.x;
        #pragma unroll
        for (int j = 0; j < 4; j++) {
            float v = av[j] + bb[j];
            if (act) v = (v >= 0.0f) ? v : 0.01f * v;
            po[j] = v;
        }
        *(float4*)&C[(size_t)(m0 + ty*4 + i) * 256 + n0 + tx*4] = o;
    }
}

// ---------------------------------------------------------------------------
// L2-normalize q,k along DK and transpose into [(b*H+h)*T+t]*32 layout.
// ---------------------------------------------------------------------------
__global__ __launch_bounds__(256) void qkv_finish_kernel()
{
    int gw   = (blockIdx.x * 256 + threadIdx.x) >> 5;
    int lane = threadIdx.x & 31;
    int bt = gw >> 3, h = gw & 7;
    int b  = bt >> 10, t = bt & 1023;
    size_t src = (size_t)bt * 256 + h * 32 + lane;
    size_t dst = (((size_t)(b * HH + h) * TT) + t) * 32 + lane;
    float qv = g_qraw[src], kv = g_kraw[src], vv = g_vraw[src];
    float sq = qv * qv, sk = kv * kv;
    #pragma unroll
    for (int off = 16; off; off >>= 1) {
        sq += __shfl_xor_sync(0xffffffffu, sq, off);
        sk += __shfl_xor_sync(0xffffffffu, sk, off);
    }
    g_q[dst] = qv / fmaxf(sqrtf(sq), 1e-12f);
    g_k[dst] = kv / fmaxf(sqrtf(sk), 1e-12f);
    g_v[dst] = vv;
}

// ---------------------------------------------------------------------------
// Attention: one CTA per (b,h, 64-row q tile). Streams 64-wide s tiles.
// Single-pass no-max softmax. Bias via per-head smem value-LUT indexed by the
// pre-quantized masked-dist u16 (loaded straight from global, no staging).
// Static smem: sQ 8704 + sK 8704 + sV 9216 + sP 17408 + sLUT 4096 = 48128 B
// ---------------------------------------------------------------------------
__global__ __launch_bounds__(256) void attn_kernel()
{
    __shared__ float sQ[32][68];
    __shared__ float sK[32][68];
    __shared__ float sV[64][36];
    __shared__ float sP[64][68];
    __shared__ float sLUT[1024];

    int tid = threadIdx.x;
    int ty = tid >> 4, tx = tid & 15;
    int bh = blockIdx.y;
    int b = bh >> 3, h = bh & 7;
    int t0 = blockIdx.x << 6;
    const float* qb = g_q + (size_t)bh * (TT * 32);
    const float* kb = g_k + (size_t)bh * (TT * 32);
    const float* vb = g_v + (size_t)bh * (TT * 32);

    #pragma unroll
    for (int r = 0; r < 2; r++) {
        int id = tid + r * 256;
        int row = id >> 3, fc = id & 7;
        float4 q4 = *(const float4*)&qb[(size_t)(t0 + row) * 32 + fc * 4];
        sQ[fc*4+0][row] = q4.x; sQ[fc*4+1][row] = q4.y;
        sQ[fc*4+2][row] = q4.z; sQ[fc*4+3][row] = q4.w;
    }
    #pragma unroll
    for (int r = 0; r < 4; r++) {
        int i = tid + r * 256;
        sLUT[i] = g_lutv[h * 1024 + i];
    }
    __syncthreads();

    float oacc[4][2] = {};
    float rs[4] = {0.f, 0.f, 0.f, 0.f};
    size_t mrow_base = (size_t)b * TT * TT + (size_t)t0 * TT;

    #pragma unroll 1
    for (int st = 0; st < 16; st++) {
        int s0 = st << 6;
        // md indices for this thread's own 4x4 microtile: coalesced LDG, issued
        // first so latency overlaps the K/V smem staging below.
        const unsigned short* db = g_mdx + mrow_base + s0;
        ushort4 mv[4];
        #pragma unroll
        for (int i = 0; i < 4; i++)
            mv[i] = *(const ushort4*)&db[(size_t)(ty*4 + i) * TT + tx*4];

        #pragma unroll
        for (int r = 0; r < 2; r++) {
            int id = tid + r * 256;
            int row = id >> 3, fc = id & 7;
            float4 k4 = *(const float4*)&kb[(size_t)(s0 + row) * 32 + fc * 4];
            sK[fc*4+0][row] = k4.x; sK[fc*4+1][row] = k4.y;
            sK[fc*4+2][row] = k4.z; sK[fc*4+3][row] = k4.w;
            float4 v4 = *(const float4*)&vb[(size_t)(s0 + row) * 32 + fc * 4];
            *(float4*)&sV[row][fc * 4] = v4;
        }
        __syncthreads();

        // ---- acc = -bias (LUT gather), then QK ----
        ull acc2[4][2];
        #pragma unroll
        for (int i = 0; i < 4; i++) {
            float b0 = sLUT[mv[i].x & 1023];
            float b1 = sLUT[mv[i].y & 1023];
            float b2 = sLUT[mv[i].z & 1023];
            float b3 = sLUT[mv[i].w & 1023];
            acc2[i][0] = pk2(b0, b1);
            acc2[i][1] = pk2(b2, b3);
        }
        #pragma unroll
        for (int kk = 0; kk < 32; kk++) {
            float4 a4 = *(const float4*)&sQ[kk][ty*4];
            ulonglong2 bp = *(const ulonglong2*)&sK[kk][tx*4];
            float a[4] = {a4.x, a4.y, a4.z, a4.w};
            #pragma unroll
            for (int i = 0; i < 4; i++) {
                ull aB = pk2(a[i], a[i]);
                FMA2(acc2[i][0], aB, bp.x, acc2[i][0]);
                FMA2(acc2[i][1], aB, bp.y, acc2[i][1]);
            }
        }
        // ---- z = masked ? 0 : exp(logit) ----
        #pragma unroll
        for (int i = 0; i < 4; i++) {
            float l0, l1, l2, l3;
            upk2(acc2[i][0], l0, l1);
            upk2(acc2[i][1], l2, l3);
            float z0 = (mv[i].x >= 1024) ? 0.0f : __expf(l0);
            float z1 = (mv[i].y >= 1024) ? 0.0f : __expf(l1);
            float z2 = (mv[i].z >= 1024) ? 0.0f : __expf(l2);
            float z3 = (mv[i].w >= 1024) ? 0.0f : __expf(l3);
            rs[i] += (z0 + z1) + (z2 + z3);
            *(float4*)&sP[ty*4 + i][tx*4] = make_float4(z0, z1, z2, z3);
        }
        __syncthreads();

        // ---- O += P @ V ----
        #pragma unroll
        for (int s4 = 0; s4 < 64; s4 += 4) {
            float4 pr[4];
            #pragma unroll
            for (int i = 0; i < 4; i++) pr[i] = *(const float4*)&sP[ty*4 + i][s4];
            #pragma unroll
            for (int u = 0; u < 4; u++) {
                float2 vv = *(const float2*)&sV[s4 + u][tx*2];
                #pragma unroll
                for (int i = 0; i < 4; i++) {
                    float p = (&pr[i].x)[u];
                    oacc[i][0] = fmaf(p, vv.x, oacc[i][0]);
                    oacc[i][1] = fmaf(p, vv.y, oacc[i][1]);
                }
            }
        }
        __syncthreads();
    }

    #pragma unroll
    for (int i = 0; i < 4; i++) {
        float s = rs[i];
        #pragma unroll
        for (int off = 1; off < 16; off <<= 1)
            s += __shfl_xor_sync(0xffffffffu, s, off);
        float inv = 1.0f / (s + 1e-5f);
        int t = t0 + ty*4 + i;
        float2 o2 = make_float2(oacc[i][0] * inv, oacc[i][1] * inv);
        *(float2*)&g_att[((size_t)b * TT + t) * DD + h * 32 + tx*2] = o2;
    }
}

// ---------------------------------------------------------------------------
// out = LayerNorm(a + b) * g + beta.  One warp per row of 256.
// ---------------------------------------------------------------------------
__global__ __launch_bounds__(256) void ln_kernel(const float* __restrict__ a,
                                                 const float* __restrict__ b,
                                                 const float* __restrict__ g,
                                                 const float* __restrict__ be,
                                                 float* __restrict__ out)
{
    int w    = (blockIdx.x * 256 + threadIdx.x) >> 5;
    int lane = threadIdx.x & 31;
    const float* ap = a + (size_t)w * 256;
    const float* bp = b + (size_t)w * 256;
    float v[8]; float s = 0.0f;
    #pragma unroll
    for (int u = 0; u < 8; u++) { v[u] = ap[lane + 32*u] + bp[lane + 32*u]; s += v[u]; }
    #pragma unroll
    for (int off = 16; off; off >>= 1) s += __shfl_xor_sync(0xffffffffu, s, off);
    float mu = s * (1.0f / 256.0f);
    float vs = 0.0f;
    #pragma unroll
    for (int u = 0; u < 8; u++) { float d = v[u] - mu; vs = fmaf(d, d, vs); }
    #pragma unroll
    for (int off = 16; off; off >>= 1) vs += __shfl_xor_sync(0xffffffffu, vs, off);
    float rstd = rsqrtf(vs * (1.0f / 256.0f) + 1e-5f);
    #pragma unroll
    for (int u = 0; u < 8; u++) {
        int col = lane + 32*u;
        out[(size_t)w * 256 + col] = (v[u] - mu) * rstd * g[col] + be[col];
    }
}

// ---------------------------------------------------------------------------
// Launch
// ---------------------------------------------------------------------------
extern "C" void kernel_launch(void* const* d_in, const int* in_sizes, int n_in,
                              void* d_out, int out_size)
{
    const float* x    = (const float*)d_in[0];
    const void*  mask = d_in[1];
    const float* rel  = (const float*)d_in[2];
    const float* Wq   = (const float*)d_in[3];
    const float* Wk   = (const float*)d_in[4];
    const float* Wv   = (const float*)d_in[5];
    const float* pw1  = (const float*)d_in[6];
    const float* pb1  = (const float*)d_in[7];
    const float* pw2  = (const float*)d_in[8];
    const float* pb2  = (const float*)d_in[9];
    const float* Wo   = (const float*)d_in[10];
    const float* bo   = (const float*)d_in[11];
    const float* Wf   = (const float*)d_in[12];
    const float* bfv  = (const float*)d_in[13];
    const float* g1   = (const float*)d_in[14];
    const float* be1  = (const float*)d_in[15];
    const float* g2   = (const float*)d_in[16];
    const float* be2  = (const float*)d_in[17];

    float *qraw, *kraw, *vraw, *att, *y, *zz, *ff;
    cudaGetSymbolAddress((void**)&qraw, g_qraw);
    cudaGetSymbolAddress((void**)&kraw, g_kraw);
    cudaGetSymbolAddress((void**)&vraw, g_vraw);
    cudaGetSymbolAddress((void**)&att,  g_att);
    cudaGetSymbolAddress((void**)&y,    g_y);
    cudaGetSymbolAddress((void**)&zz,   g_zz);
    cudaGetSymbolAddress((void**)&ff,   g_ff);

    prep_kernel<<<1, 128>>>(pw1, pb1, pw2, pb2);
    lut_kernel<<<8, 1024>>>();
    detect_kernel<<<256, 256>>>((const unsigned*)mask);
    maskfuse_kernel<<<4096, 256>>>(rel, mask);

    sgemm64<<<dim3(64, 4, 3), 256>>>(x, Wq, Wk, Wv, nullptr, qraw, kraw, vraw, 0);
    qkv_finish_kernel<<<4096, 256>>>();

    attn_kernel<<<dim3(16, 32), 256>>>();

    sgemm64<<<dim3(64, 4, 1), 256>>>(att, Wo, Wo, Wo, bo, y, y, y, 0);
    ln_kernel<<<512, 256>>>(x, y, g1, be1, zz);
    sgemm64<<<dim3(64, 4, 1), 256>>>(zz, Wf, Wf, Wf, bfv, ff, ff, ff, 1);
    ln_kernel<<<512, 256>>>(zz, ff, g2, be2, (float*)d_out);
}

// round 7
// speedup vs baseline: 1.6717x; 1.2139x over previous
#include <cuda_runtime.h>
#include <cuda_bf16.h>

#define BB  4
#define TT  1024
#define DD  256
#define HH  8
#define CC  16
#define BT  (BB*TT)

typedef unsigned long long ull;

__device__ __forceinline__ ull pk2(float lo, float hi) {
    ull r; asm("mov.b64 %0, {%1, %2};" : "=l"(r) : "f"(lo), "f"(hi)); return r;
}
__device__ __forceinline__ void upk2(ull v, float& lo, float& hi) {
    asm("mov.b64 {%0, %1}, %2;" : "=f"(lo), "=f"(hi) : "l"(v));
}
#define FMA2(d, a, b, c) asm("fma.rn.f32x2 %0, %1, %2, %3;" : "=l"(d) : "l"(a), "l"(b), "l"(c))

__device__ __forceinline__ unsigned smem_u32(const void* p) {
    unsigned a;
    asm("{ .reg .u64 t; cvta.to.shared.u64 t, %1; cvt.u32.u64 %0, t; }" : "=r"(a) : "l"(p));
    return a;
}
__device__ __forceinline__ void ldsm4(unsigned* r, unsigned addr) {
    asm volatile("ldmatrix.sync.aligned.m8n8.x4.shared.b16 {%0,%1,%2,%3}, [%4];"
                 : "=r"(r[0]), "=r"(r[1]), "=r"(r[2]), "=r"(r[3]) : "r"(addr));
}
__device__ __forceinline__ void mma16816(float* c, const unsigned* a, const unsigned* b) {
    asm volatile("mma.sync.aligned.m16n8k16.row.col.f32.bf16.bf16.f32 "
                 "{%0,%1,%2,%3}, {%4,%5,%6,%7}, {%8,%9}, {%0,%1,%2,%3};"
                 : "+f"(c[0]), "+f"(c[1]), "+f"(c[2]), "+f"(c[3])
                 : "r"(a[0]), "r"(a[1]), "r"(a[2]), "r"(a[3]), "r"(b[0]), "r"(b[1]));
}

// ---------------- scratch ----------------
__device__ float g_qraw[BT*DD];
__device__ float g_kraw[BT*DD];
__device__ float g_vraw[BT*DD];
__device__ float g_q[BT*DD];
__device__ float g_k[BT*DD];
__device__ float g_v[BT*DD];
__device__ float g_y[BT*DD];
__device__ float g_zz[BT*DD];
__device__ unsigned short g_mdx[BB*TT*TT];
__device__ float g_coef[HH*34];
__device__ float g_lutv[HH*1024];
__device__ int   g_mask_flags;
__device__ __nv_bfloat16 g_xhi[BT*DD],  g_xlo[BT*DD];
__device__ __nv_bfloat16 g_athi[BT*DD], g_atlo[BT*DD];
__device__ __nv_bfloat16 g_zhi[BT*DD],  g_zlo[BT*DD];
__device__ __nv_bfloat16 g_whi[5*DD*DD], g_wlo[5*DD*DD];

__global__ void prep_kernel(const float* __restrict__ pw1, const float* __restrict__ pb1,
                            const float* __restrict__ pw2, const float* __restrict__ pb2)
{
    if (threadIdx.x == 0) g_mask_flags = 0;
    int h = threadIdx.x >> 4;
    int c = threadIdx.x & 15;
    if (h >= HH) return;
    float w1 = pw1[h*CC + c], b1 = pb1[h*CC + c], w2 = pw2[h*CC + c];
    float beta, delta, k0add, k1add;
    if (w1 != 0.0f) {
        beta  = 0.495f * w2 * fabsf(w1);
        delta = -b1 / w1;
        k0add = 0.505f * w2 * b1;
        k1add = 0.505f * w2 * w1;
    } else {
        beta = 0.0f; delta = 0.0f;
        k0add = w2 * (0.505f * b1 + 0.495f * fabsf(b1));
        k1add = 0.0f;
    }
    #pragma unroll
    for (int off = 1; off < 16; off <<= 1) {
        k0add += __shfl_xor_sync(0xffffffffu, k0add, off);
        k1add += __shfl_xor_sync(0xffffffffu, k1add, off);
    }
    g_coef[h*34 + 2  + c] = beta;
    g_coef[h*34 + 18 + c] = delta;
    if (c == 0) {
        g_coef[h*34 + 0] = pb2[h] + k0add;
        g_coef[h*34 + 1] = k1add;
    }
}

__global__ void lut_kernel()
{
    int i = blockIdx.x * blockDim.x + threadIdx.x;
    int h = i >> 10, cell = i & 1023;
    float m = (cell + 0.5f) * (1.0f / 1024.0f);
    float v = g_coef[h*34 + 0] + g_coef[h*34 + 1] * m;
    #pragma unroll
    for (int c = 0; c < 16; c++) {
        float be = g_coef[h*34 + 2 + c], de = g_coef[h*34 + 18 + c];
        v += be * fabsf(m - de);
    }
    g_lutv[i] = -v;
}

__global__ void detect_kernel(const unsigned* __restrict__ w)
{
    int i = blockIdx.x * blockDim.x + threadIdx.x;
    unsigned x = w[i];
    int f = 0;
    if (x == 0x3F800000u)               f = 2;
    else if ((x & 0xFFFFu) == 0x3F80u)  f = 4;
    else if (x > 1u)                    f = 1;
    if (f) atomicOr(&g_mask_flags, f);
}

__global__ __launch_bounds__(256) void maskfuse_kernel(const float* __restrict__ rd,
                                                       const void* __restrict__ maskp)
{
    int i = blockIdx.x * 256 + threadIdx.x;
    size_t base = (size_t)i * 4;
    int mf = g_mask_flags;
    int mode = (mf & 4) ? 3 : (mf & 2) ? 2 : (mf & 1) ? 1 : 0;
    float4 d4 = *(const float4*)&rd[base];
    int m0, m1, m2, m3;
    if (mode == 0) {
        int4 m = *(const int4*)((const int*)maskp + base);
        m0 = m.x != 0; m1 = m.y != 0; m2 = m.z != 0; m3 = m.w != 0;
    } else if (mode == 1) {
        uchar4 m = *(const uchar4*)((const unsigned char*)maskp + base);
        m0 = m.x != 0; m1 = m.y != 0; m2 = m.z != 0; m3 = m.w != 0;
    } else if (mode == 2) {
        float4 m = *(const float4*)((const float*)maskp + base);
        m0 = m.x != 0.0f; m1 = m.y != 0.0f; m2 = m.z != 0.0f; m3 = m.w != 0.0f;
    } else {
        ushort4 m = *(const ushort4*)((const unsigned short*)maskp + base);
        m0 = m.x != 0; m1 = m.y != 0; m2 = m.z != 0; m3 = m.w != 0;
    }
    int i0 = min(max(__float2int_rd(d4.x * 1024.0f), 0), 1023);
    int i1 = min(max(__float2int_rd(d4.y * 1024.0f), 0), 1023);
    int i2 = min(max(__float2int_rd(d4.z * 1024.0f), 0), 1023);
    int i3 = min(max(__float2int_rd(d4.w * 1024.0f), 0), 1023);
    ushort4 o;
    o.x = (unsigned short)(m0 ? 2047 : i0);
    o.y = (unsigned short)(m1 ? 2047 : i1);
    o.z = (unsigned short)(m2 ? 2047 : i2);
    o.w = (unsigned short)(m3 ? 2047 : i3);
    *(ushort4*)&g_mdx[base] = o;
}

__global__ __launch_bounds__(256) void split_kernel(const float* __restrict__ src,
                                                    __nv_bfloat16* __restrict__ hi,
                                                    __nv_bfloat16* __restrict__ lo)
{
    int i = blockIdx.x * 256 + threadIdx.x;
    float2 v = *(const float2*)&src[(size_t)i * 2];
    __nv_bfloat16 hx = __float2bfloat16(v.x), hy = __float2bfloat16(v.y);
    __nv_bfloat162 h2; h2.x = hx; h2.y = hy;
    __nv_bfloat162 l2;
    l2.x = __float2bfloat16(v.x - __bfloat162float(hx));
    l2.y = __float2bfloat16(v.y - __bfloat162float(hy));
    *(__nv_bfloat162*)&hi[(size_t)i * 2] = h2;
    *(__nv_bfloat162*)&lo[(size_t)i * 2] = l2;
}

__global__ __launch_bounds__(256) void splitw_kernel(const float* __restrict__ w0,
                                                     const float* __restrict__ w1,
                                                     const float* __restrict__ w2,
                                                     const float* __restrict__ w3,
                                                     const float* __restrict__ w4)
{
    int i = blockIdx.x * 256 + threadIdx.x;
    size_t e = (size_t)i * 2;
    int w = (int)(e >> 16);
    size_t off = e & 65535;
    const float* src = (w == 0) ? w0 : (w == 1) ? w1 : (w == 2) ? w2 : (w == 3) ? w3 : w4;
    float2 v = *(const float2*)&src[off];
    __nv_bfloat16 hx = __float2bfloat16(v.x), hy = __float2bfloat16(v.y);
    __nv_bfloat162 h2; h2.x = hx; h2.y = hy;
    __nv_bfloat162 l2;
    l2.x = __float2bfloat16(v.x - __bfloat162float(hx));
    l2.y = __float2bfloat16(v.y - __bfloat162float(hy));
    *(__nv_bfloat162*)&g_whi[e] = h2;
    *(__nv_bfloat162*)&g_wlo[e] = l2;
}

// ---------------------------------------------------------------------------
// HMMA GEMM (bf16x3): C[4096,256] = A @ W^T (+bias)(+lrelu)
// CTA: 128x64 tile, 8 warps in 4(M)x2(N), warp tile 32x32, K chunks of 64.
// A/W staged hi+lo in smem with 72-bf16 row stride (conflict-free ldmatrix).
// 3 products into shared fp32 acc: AhiWhi + AhiWlo + AloWhi.
// smem bytes: AHI 0 (18432) | ALO 18432 | WHI 36864 (9216) | WLO 46080 | total 55296
// ---------------------------------------------------------------------------
#define MM_AHI 0
#define MM_ALO 18432
#define MM_WHI 36864
#define MM_WLO 46080
#define MM_SMEM 55296

__global__ __launch_bounds__(256) void tcmma(const __nv_bfloat16* __restrict__ Ahi,
                                             const __nv_bfloat16* __restrict__ Alo,
                                             int widx0,
                                             const float* __restrict__ bias,
                                             float* __restrict__ C0,
                                             float* __restrict__ C1,
                                             float* __restrict__ C2,
                                             int act)
{
    extern __shared__ char sm[];
    unsigned smb = smem_u32(sm);
    int tid = threadIdx.x;
    int lane = tid & 31;
    int wid = tid >> 5;
    int wm = wid & 3;          // M sub-tile (32 rows)
    int wn = wid >> 2;         // N sub-tile (32 cols)
    int m0 = blockIdx.x * 128, n0 = blockIdx.y * 64;
    int z = blockIdx.z;
    const __nv_bfloat16* Whi = g_whi + (size_t)(widx0 + z) * (DD*DD);
    const __nv_bfloat16* Wlo = g_wlo + (size_t)(widx0 + z) * (DD*DD);
    float* C = (z == 0) ? C0 : (z == 1) ? C1 : C2;

    float acc[2][4][4];
    #pragma unroll
    for (int a = 0; a < 2; a++)
        #pragma unroll
        for (int b = 0; b < 4; b++)
            #pragma unroll
            for (int c = 0; c < 4; c++) acc[a][b][c] = 0.0f;

    for (int kc = 0; kc < 4; kc++) {
        // stage A chunk: 128 rows x 64 cols, hi+lo
        #pragma unroll
        for (int it = 0; it < 4; it++) {
            int v = tid + it * 256;
            int row = v >> 3, cg = (v & 7) * 8;
            size_t gofs = (size_t)(m0 + row) * 256 + kc * 64 + cg;
            *(uint4*)(sm + MM_AHI + row*144 + cg*2) = *(const uint4*)&Ahi[gofs];
            *(uint4*)(sm + MM_ALO + row*144 + cg*2) = *(const uint4*)&Alo[gofs];
        }
        // stage W chunk: 64 rows x 64 cols, hi+lo
        #pragma unroll
        for (int it = 0; it < 2; it++) {
            int v = tid + it * 256;
            int row = v >> 3, cg = (v & 7) * 8;
            size_t gofs = (size_t)(n0 + row) * 256 + kc * 64 + cg;
            *(uint4*)(sm + MM_WHI + row*144 + cg*2) = *(const uint4*)&Whi[gofs];
            *(uint4*)(sm + MM_WLO + row*144 + cg*2) = *(const uint4*)&Wlo[gofs];
        }
        __syncthreads();

        #pragma unroll
        for (int ks = 0; ks < 4; ks++) {
            int kb = ks * 16;
            unsigned ah[2][4], al[2][4], bh[2][4], bl[2][4];
            #pragma unroll
            for (int mi = 0; mi < 2; mi++) {
                int row = wm*32 + mi*16 + (lane & 15);
                unsigned ad = smb + MM_AHI + row*144 + (kb + ((lane >> 4) << 3)) * 2;
                ldsm4(ah[mi], ad);
                ldsm4(al[mi], ad + (MM_ALO - MM_AHI));
            }
            #pragma unroll
            for (int gi = 0; gi < 2; gi++) {
                int nrow = wn*32 + gi*16 + (lane & 7) + ((lane >> 4) & 1) * 8;
                unsigned bd = smb + MM_WHI + nrow*144 + (kb + (((lane >> 3) & 1) << 3)) * 2;
                ldsm4(bh[gi], bd);
                ldsm4(bl[gi], bd + (MM_WLO - MM_WHI));
            }
            #pragma unroll
            for (int mi = 0; mi < 2; mi++) {
                #pragma unroll
                for (int ni = 0; ni < 4; ni++) {
                    int gi = ni >> 1, hf = (ni & 1) * 2;
                    mma16816(acc[mi][ni], ah[mi], &bh[gi][hf]);
                    mma16816(acc[mi][ni], ah[mi], &bl[gi][hf]);
                    mma16816(acc[mi][ni], al[mi], &bh[gi][hf]);
                }
            }
        }
        __syncthreads();
    }

    // epilogue: c frag -> C; rows (t/4, t/4+8), cols 2*(t%4)+{0,1}
    int rbase = m0 + wm*32 + (lane >> 2);
    int cbase = n0 + wn*32 + (lane & 3) * 2;
    #pragma unroll
    for (int mi = 0; mi < 2; mi++) {
        #pragma unroll
        for (int ni = 0; ni < 4; ni++) {
            int col = cbase + ni*8;
            float b0 = bias ? bias[col] : 0.0f;
            float b1 = bias ? bias[col + 1] : 0.0f;
            float v0 = acc[mi][ni][0] + b0;
            float v1 = acc[mi][ni][1] + b1;
            float v2 = acc[mi][ni][2] + b0;
            float v3 = acc[mi][ni][3] + b1;
            if (act) {
                v0 = (v0 >= 0.0f) ? v0 : 0.01f * v0;
                v1 = (v1 >= 0.0f) ? v1 : 0.01f * v1;
                v2 = (v2 >= 0.0f) ? v2 : 0.01f * v2;
                v3 = (v3 >= 0.0f) ? v3 : 0.01f * v3;
            }
            int row = rbase + mi*16;
            *(float2*)&C[(size_t)row * 256 + col]       = make_float2(v0, v1);
            *(float2*)&C[(size_t)(row + 8) * 256 + col] = make_float2(v2, v3);
        }
    }
}

__global__ __launch_bounds__(256) void qkv_finish_kernel()
{
    int gw   = (blockIdx.x * 256 + threadIdx.x) >> 5;
    int lane = threadIdx.x & 31;
    int bt = gw >> 3, h = gw & 7;
    int b  = bt >> 10, t = bt & 1023;
    size_t src = (size_t)bt * 256 + h * 32 + lane;
    size_t dst = (((size_t)(b * HH + h) * TT) + t) * 32 + lane;
    float qv = g_qraw[src], kv = g_kraw[src], vv = g_vraw[src];
    float sq = qv * qv, sk = kv * kv;
    #pragma unroll
    for (int off = 16; off; off >>= 1) {
        sq += __shfl_xor_sync(0xffffffffu, sq, off);
        sk += __shfl_xor_sync(0xffffffffu, sk, off);
    }
    g_q[dst] = qv / fmaxf(sqrtf(sq), 1e-12f);
    g_k[dst] = kv / fmaxf(sqrtf(sk), 1e-12f);
    g_v[dst] = vv;
}

__global__ __launch_bounds__(256) void attn_kernel()
{
    __shared__ float sQ[32][68];
    __shared__ float sK[32][68];
    __shared__ float sV[64][36];
    __shared__ float sP[64][68];
    __shared__ float sLUT[1024];

    int tid = threadIdx.x;
    int ty = tid >> 4, tx = tid & 15;
    int bh = blockIdx.y;
    int b = bh >> 3, h = bh & 7;
    int t0 = blockIdx.x << 6;
    const float* qb = g_q + (size_t)bh * (TT * 32);
    const float* kb = g_k + (size_t)bh * (TT * 32);
    const float* vb = g_v + (size_t)bh * (TT * 32);

    #pragma unroll
    for (int r = 0; r < 2; r++) {
        int id = tid + r * 256;
        int row = id >> 3, fc = id & 7;
        float4 q4 = *(const float4*)&qb[(size_t)(t0 + row) * 32 + fc * 4];
        sQ[fc*4+0][row] = q4.x; sQ[fc*4+1][row] = q4.y;
        sQ[fc*4+2][row] = q4.z; sQ[fc*4+3][row] = q4.w;
    }
    #pragma unroll
    for (int r = 0; r < 4; r++) {
        int i = tid + r * 256;
        sLUT[i] = g_lutv[h * 1024 + i];
    }
    __syncthreads();

    float oacc[4][2] = {};
    float rs[4] = {0.f, 0.f, 0.f, 0.f};
    size_t mrow_base = (size_t)b * TT * TT + (size_t)t0 * TT;

    #pragma unroll 1
    for (int st = 0; st < 16; st++) {
        int s0 = st << 6;
        const unsigned short* db = g_mdx + mrow_base + s0;
        ushort4 mv[4];
        #pragma unroll
        for (int i = 0; i < 4; i++)
            mv[i] = *(const ushort4*)&db[(size_t)(ty*4 + i) * TT + tx*4];

        #pragma unroll
        for (int r = 0; r < 2; r++) {
            int id = tid + r * 256;
            int row = id >> 3, fc = id & 7;
            float4 k4 = *(const float4*)&kb[(size_t)(s0 + row) * 32 + fc * 4];
            sK[fc*4+0][row] = k4.x; sK[fc*4+1][row] = k4.y;
            sK[fc*4+2][row] = k4.z; sK[fc*4+3][row] = k4.w;
            float4 v4 = *(const float4*)&vb[(size_t)(s0 + row) * 32 + fc * 4];
            *(float4*)&sV[row][fc * 4] = v4;
        }
        __syncthreads();

        ull acc2[4][2];
        #pragma unroll
        for (int i = 0; i < 4; i++) {
            float b0 = sLUT[mv[i].x & 1023];
            float b1 = sLUT[mv[i].y & 1023];
            float b2 = sLUT[mv[i].z & 1023];
            float b3 = sLUT[mv[i].w & 1023];
            acc2[i][0] = pk2(b0, b1);
            acc2[i][1] = pk2(b2, b3);
        }
        #pragma unroll
        for (int kk = 0; kk < 32; kk++) {
            float4 a4 = *(const float4*)&sQ[kk][ty*4];
            ulonglong2 bp = *(const ulonglong2*)&sK[kk][tx*4];
            float a[4] = {a4.x, a4.y, a4.z, a4.w};
            #pragma unroll
            for (int i = 0; i < 4; i++) {
                ull aB = pk2(a[i], a[i]);
                FMA2(acc2[i][0], aB, bp.x, acc2[i][0]);
                FMA2(acc2[i][1], aB, bp.y, acc2[i][1]);
            }
        }
        #pragma unroll
        for (int i = 0; i < 4; i++) {
            float l0, l1, l2, l3;
            upk2(acc2[i][0], l0, l1);
            upk2(acc2[i][1], l2, l3);
            float z0 = (mv[i].x >= 1024) ? 0.0f : __expf(l0);
            float z1 = (mv[i].y >= 1024) ? 0.0f : __expf(l1);
            float z2 = (mv[i].z >= 1024) ? 0.0f : __expf(l2);
            float z3 = (mv[i].w >= 1024) ? 0.0f : __expf(l3);
            rs[i] += (z0 + z1) + (z2 + z3);
            *(float4*)&sP[ty*4 + i][tx*4] = make_float4(z0, z1, z2, z3);
        }
        __syncthreads();

        #pragma unroll
        for (int s4 = 0; s4 < 64; s4 += 4) {
            float4 pr[4];
            #pragma unroll
            for (int i = 0; i < 4; i++) pr[i] = *(const float4*)&sP[ty*4 + i][s4];
            #pragma unroll
            for (int u = 0; u < 4; u++) {
                float2 vv = *(const float2*)&sV[s4 + u][tx*2];
                #pragma unroll
                for (int i = 0; i < 4; i++) {
                    float p = (&pr[i].x)[u];
                    oacc[i][0] = fmaf(p, vv.x, oacc[i][0]);
                    oacc[i][1] = fmaf(p, vv.y, oacc[i][1]);
                }
            }
        }
        __syncthreads();
    }

    #pragma unroll
    for (int i = 0; i < 4; i++) {
        float s = rs[i];
        #pragma unroll
        for (int off = 1; off < 16; off <<= 1)
            s += __shfl_xor_sync(0xffffffffu, s, off);
        float inv = 1.0f / (s + 1e-5f);
        int t = t0 + ty*4 + i;
        float ox = oacc[i][0] * inv, oy = oacc[i][1] * inv;
        size_t oi = ((size_t)b * TT + t) * DD + h * 32 + tx*2;
        __nv_bfloat16 hx = __float2bfloat16(ox), hy = __float2bfloat16(oy);
        __nv_bfloat162 h2; h2.x = hx; h2.y = hy;
        __nv_bfloat162 l2;
        l2.x = __float2bfloat16(ox - __bfloat162float(hx));
        l2.y = __float2bfloat16(oy - __bfloat162float(hy));
        *(__nv_bfloat162*)&g_athi[oi] = h2;
        *(__nv_bfloat162*)&g_atlo[oi] = l2;
    }
}

__global__ __launch_bounds__(256) void ln_kernel(const float* __restrict__ a,
                                                 const float* __restrict__ b,
                                                 const float* __restrict__ g,
                                                 const float* __restrict__ be,
                                                 float* __restrict__ out)
{
    int w    = (blockIdx.x * 256 + threadIdx.x) >> 5;
    int lane = threadIdx.x & 31;
    const float* ap = a + (size_t)w * 256;
    const float* bp = b + (size_t)w * 256;
    float v[8]; float s = 0.0f;
    #pragma unroll
    for (int u = 0; u < 8; u++) { v[u] = ap[lane + 32*u] + bp[lane + 32*u]; s += v[u]; }
    #pragma unroll
    for (int off = 16; off; off >>= 1) s += __shfl_xor_sync(0xffffffffu, s, off);
    float mu = s * (1.0f / 256.0f);
    float vs = 0.0f;
    #pragma unroll
    for (int u = 0; u < 8; u++) { float d = v[u] - mu; vs = fmaf(d, d, vs); }
    #pragma unroll
    for (int off = 16; off; off >>= 1) vs += __shfl_xor_sync(0xffffffffu, vs, off);
    float rstd = rsqrtf(vs * (1.0f / 256.0f) + 1e-5f);
    #pragma unroll
    for (int u = 0; u < 8; u++) {
        int col = lane + 32*u;
        out[(size_t)w * 256 + col] = (v[u] - mu) * rstd * g[col] + be[col];
    }
}

extern "C" void kernel_launch(void* const* d_in, const int* in_sizes, int n_in,
                              void* d_out, int out_size)
{
    const float* x    = (const float*)d_in[0];
    const void*  mask = d_in[1];
    const float* rel  = (const float*)d_in[2];
    const float* Wq   = (const float*)d_in[3];
    const float* Wk   = (const float*)d_in[4];
    const float* Wv   = (const float*)d_in[5];
    const float* pw1  = (const float*)d_in[6];
    const float* pb1  = (const float*)d_in[7];
    const float* pw2  = (const float*)d_in[8];
    const float* pb2  = (const float*)d_in[9];
    const float* Wo   = (const float*)d_in[10];
    const float* bo   = (const float*)d_in[11];
    const float* Wf   = (const float*)d_in[12];
    const float* bfv  = (const float*)d_in[13];
    const float* g1   = (const float*)d_in[14];
    const float* be1  = (const float*)d_in[15];
    const float* g2   = (const float*)d_in[16];
    const float* be2  = (const float*)d_in[17];

    float *qraw, *kraw, *vraw, *y, *zz;
    __nv_bfloat16 *xhi, *xlo, *athi, *atlo, *zhi, *zlo;
    cudaGetSymbolAddress((void**)&qraw, g_qraw);
    cudaGetSymbolAddress((void**)&kraw, g_kraw);
    cudaGetSymbolAddress((void**)&vraw, g_vraw);
    cudaGetSymbolAddress((void**)&y,    g_y);
    cudaGetSymbolAddress((void**)&zz,   g_zz);
    cudaGetSymbolAddress((void**)&xhi,  g_xhi);
    cudaGetSymbolAddress((void**)&xlo,  g_xlo);
    cudaGetSymbolAddress((void**)&athi, g_athi);
    cudaGetSymbolAddress((void**)&atlo, g_atlo);
    cudaGetSymbolAddress((void**)&zhi,  g_zhi);
    cudaGetSymbolAddress((void**)&zlo,  g_zlo);

    cudaFuncSetAttribute(tcmma, cudaFuncAttributeMaxDynamicSharedMemorySize, MM_SMEM);

    prep_kernel<<<1, 128>>>(pw1, pb1, pw2, pb2);
    lut_kernel<<<8, 1024>>>();
    detect_kernel<<<256, 256>>>((const unsigned*)mask);
    maskfuse_kernel<<<4096, 256>>>(rel, mask);
    splitw_kernel<<<640, 256>>>(Wq, Wk, Wv, Wo, Wf);
    split_kernel<<<2048, 256>>>(x, xhi, xlo);

    tcmma<<<dim3(32, 4, 3), 256, MM_SMEM>>>(xhi, xlo, 0, nullptr, qraw, kraw, vraw, 0);
    qkv_finish_kernel<<<4096, 256>>>();

    attn_kernel<<<dim3(16, 32), 256>>>();

    tcmma<<<dim3(32, 4, 1), 256, MM_SMEM>>>(athi, atlo, 3, bo, y, y, y, 0);
    ln_kernel<<<512, 256>>>(x, y, g1, be1, zz);
    split_kernel<<<2048, 256>>>(zz, zhi, zlo);
    // reuse qraw as FFN scratch (no longer needed at this point)
    tcmma<<<dim3(32, 4, 1), 256, MM_SMEM>>>(zhi, zlo, 4, bfv, qraw, qraw, qraw, 1);
    ln_kernel<<<512, 256>>>(zz, qraw, g2, be2, (float*)d_out);
}

// round 8
// speedup vs baseline: 2.1401x; 1.2802x over previous
#include <cuda_runtime.h>
#include <cuda_bf16.h>

#define BB  4
#define TT  1024
#define DD  256
#define HH  8
#define CC  16
#define BT  (BB*TT)

typedef unsigned long long ull;

__device__ __forceinline__ unsigned smem_u32(const void* p) {
    unsigned a;
    asm("{ .reg .u64 t; cvta.to.shared.u64 t, %1; cvt.u32.u64 %0, t; }" : "=r"(a) : "l"(p));
    return a;
}
__device__ __forceinline__ void ldsm4(unsigned* r, unsigned addr) {
    asm volatile("ldmatrix.sync.aligned.m8n8.x4.shared.b16 {%0,%1,%2,%3}, [%4];"
                 : "=r"(r[0]), "=r"(r[1]), "=r"(r[2]), "=r"(r[3]) : "r"(addr));
}
__device__ __forceinline__ void mma16816(float* c, const unsigned* a, const unsigned* b) {
    asm volatile("mma.sync.aligned.m16n8k16.row.col.f32.bf16.bf16.f32 "
                 "{%0,%1,%2,%3}, {%4,%5,%6,%7}, {%8,%9}, {%0,%1,%2,%3};"
                 : "+f"(c[0]), "+f"(c[1]), "+f"(c[2]), "+f"(c[3])
                 : "r"(a[0]), "r"(a[1]), "r"(a[2]), "r"(a[3]), "r"(b[0]), "r"(b[1]));
}
// pack two f32 -> bf16x2 register: low 16 bits = lo, high = hi
__device__ __forceinline__ unsigned cvt2bf(float hi, float lo) {
    unsigned r;
    asm("cvt.rn.bf16x2.f32 %0, %1, %2;" : "=r"(r) : "f"(hi), "f"(lo));
    return r;
}

// ---------------- scratch ----------------
__device__ float g_qraw[BT*DD];
__device__ float g_kraw[BT*DD];
__device__ float g_vraw[BT*DD];
__device__ float g_y[BT*DD];
__device__ float g_zz[BT*DD];
__device__ unsigned short g_mdx[BB*TT*TT];
__device__ float g_coef[HH*34];
__device__ float g_lutv[HH*1024];
__device__ int   g_mask_flags;
__device__ __nv_bfloat16 g_xhi[BT*DD],  g_xlo[BT*DD];
__device__ __nv_bfloat16 g_athi[BT*DD], g_atlo[BT*DD];
__device__ __nv_bfloat16 g_zhi[BT*DD],  g_zlo[BT*DD];
__device__ __nv_bfloat16 g_whi[5*DD*DD], g_wlo[5*DD*DD];
// attention operands, bf16 hi/lo
__device__ __nv_bfloat16 g_qhib[BT*32], g_qlob[BT*32];   // [bh*T + t]*32 + k  (x8 heads folded: BT*32*H... )
__device__ __nv_bfloat16 g_khib[BT*32*1], g_klob[BT*32*1];
__device__ __nv_bfloat16 g_vthi[32*HH*BB*TT], g_vtlo[32*HH*BB*TT]; // [bh][32][1024]

// NOTE: q/k arrays sized: 32 bh * 1024 t * 32 k = 1,048,576 elements = BT*DD? BT*32*8 = BT*256.
// Declared sizes above are wrong-dimensional; fix with full-size arrays:
__device__ __nv_bfloat16 g_qh2[HH*BB*TT*32], g_ql2[HH*BB*TT*32];
__device__ __nv_bfloat16 g_kh2[HH*BB*TT*32], g_kl2[HH*BB*TT*32];

__global__ void prep_kernel(const float* __restrict__ pw1, const float* __restrict__ pb1,
                            const float* __restrict__ pw2, const float* __restrict__ pb2)
{
    if (threadIdx.x == 0) g_mask_flags = 0;
    int h = threadIdx.x >> 4;
    int c = threadIdx.x & 15;
    if (h >= HH) return;
    float w1 = pw1[h*CC + c], b1 = pb1[h*CC + c], w2 = pw2[h*CC + c];
    float beta, delta, k0add, k1add;
    if (w1 != 0.0f) {
        beta  = 0.495f * w2 * fabsf(w1);
        delta = -b1 / w1;
        k0add = 0.505f * w2 * b1;
        k1add = 0.505f * w2 * w1;
    } else {
        beta = 0.0f; delta = 0.0f;
        k0add = w2 * (0.505f * b1 + 0.495f * fabsf(b1));
        k1add = 0.0f;
    }
    #pragma unroll
    for (int off = 1; off < 16; off <<= 1) {
        k0add += __shfl_xor_sync(0xffffffffu, k0add, off);
        k1add += __shfl_xor_sync(0xffffffffu, k1add, off);
    }
    g_coef[h*34 + 2  + c] = beta;
    g_coef[h*34 + 18 + c] = delta;
    if (c == 0) {
        g_coef[h*34 + 0] = pb2[h] + k0add;
        g_coef[h*34 + 1] = k1add;
    }
}

__global__ void lut_kernel()
{
    int i = blockIdx.x * blockDim.x + threadIdx.x;
    int h = i >> 10, cell = i & 1023;
    float m = (cell + 0.5f) * (1.0f / 1024.0f);
    float v = g_coef[h*34 + 0] + g_coef[h*34 + 1] * m;
    #pragma unroll
    for (int c = 0; c < 16; c++) {
        float be = g_coef[h*34 + 2 + c], de = g_coef[h*34 + 18 + c];
        v += be * fabsf(m - de);
    }
    g_lutv[i] = -v;
}

__global__ void detect_kernel(const unsigned* __restrict__ w)
{
    int i = blockIdx.x * blockDim.x + threadIdx.x;
    unsigned x = w[i];
    int f = 0;
    if (x == 0x3F800000u)               f = 2;
    else if ((x & 0xFFFFu) == 0x3F80u)  f = 4;
    else if (x > 1u)                    f = 1;
    if (f) atomicOr(&g_mask_flags, f);
}

__global__ __launch_bounds__(256) void maskfuse_kernel(const float* __restrict__ rd,
                                                       const void* __restrict__ maskp)
{
    int i = blockIdx.x * 256 + threadIdx.x;
    size_t base = (size_t)i * 4;
    int mf = g_mask_flags;
    int mode = (mf & 4) ? 3 : (mf & 2) ? 2 : (mf & 1) ? 1 : 0;
    float4 d4 = *(const float4*)&rd[base];
    int m0, m1, m2, m3;
    if (mode == 0) {
        int4 m = *(const int4*)((const int*)maskp + base);
        m0 = m.x != 0; m1 = m.y != 0; m2 = m.z != 0; m3 = m.w != 0;
    } else if (mode == 1) {
        uchar4 m = *(const uchar4*)((const unsigned char*)maskp + base);
        m0 = m.x != 0; m1 = m.y != 0; m2 = m.z != 0; m3 = m.w != 0;
    } else if (mode == 2) {
        float4 m = *(const float4*)((const float*)maskp + base);
        m0 = m.x != 0.0f; m1 = m.y != 0.0f; m2 = m.z != 0.0f; m3 = m.w != 0.0f;
    } else {
        ushort4 m = *(const ushort4*)((const unsigned short*)maskp + base);
        m0 = m.x != 0; m1 = m.y != 0; m2 = m.z != 0; m3 = m.w != 0;
    }
    int i0 = min(max(__float2int_rd(d4.x * 1024.0f), 0), 1023);
    int i1 = min(max(__float2int_rd(d4.y * 1024.0f), 0), 1023);
    int i2 = min(max(__float2int_rd(d4.z * 1024.0f), 0), 1023);
    int i3 = min(max(__float2int_rd(d4.w * 1024.0f), 0), 1023);
    ushort4 o;
    o.x = (unsigned short)(m0 ? 2047 : i0);
    o.y = (unsigned short)(m1 ? 2047 : i1);
    o.z = (unsigned short)(m2 ? 2047 : i2);
    o.w = (unsigned short)(m3 ? 2047 : i3);
    *(ushort4*)&g_mdx[base] = o;
}

__global__ __launch_bounds__(256) void split_kernel(const float* __restrict__ src,
                                                    __nv_bfloat16* __restrict__ hi,
                                                    __nv_bfloat16* __restrict__ lo)
{
    int i = blockIdx.x * 256 + threadIdx.x;
    float2 v = *(const float2*)&src[(size_t)i * 2];
    __nv_bfloat16 hx = __float2bfloat16(v.x), hy = __float2bfloat16(v.y);
    __nv_bfloat162 h2; h2.x = hx; h2.y = hy;
    __nv_bfloat162 l2;
    l2.x = __float2bfloat16(v.x - __bfloat162float(hx));
    l2.y = __float2bfloat16(v.y - __bfloat162float(hy));
    *(__nv_bfloat162*)&hi[(size_t)i * 2] = h2;
    *(__nv_bfloat162*)&lo[(size_t)i * 2] = l2;
}

__global__ __launch_bounds__(256) void splitw_kernel(const float* __restrict__ w0,
                                                     const float* __restrict__ w1,
                                                     const float* __restrict__ w2,
                                                     const float* __restrict__ w3,
                                                     const float* __restrict__ w4)
{
    int i = blockIdx.x * 256 + threadIdx.x;
    size_t e = (size_t)i * 2;
    int w = (int)(e >> 16);
    size_t off = e & 65535;
    const float* src = (w == 0) ? w0 : (w == 1) ? w1 : (w == 2) ? w2 : (w == 3) ? w3 : w4;
    float2 v = *(const float2*)&src[off];
    __nv_bfloat16 hx = __float2bfloat16(v.x), hy = __float2bfloat16(v.y);
    __nv_bfloat162 h2; h2.x = hx; h2.y = hy;
    __nv_bfloat162 l2;
    l2.x = __float2bfloat16(v.x - __bfloat162float(hx));
    l2.y = __float2bfloat16(v.y - __bfloat162float(hy));
    *(__nv_bfloat162*)&g_whi[e] = h2;
    *(__nv_bfloat162*)&g_wlo[e] = l2;
}

// ---------------------------------------------------------------------------
// HMMA GEMM (bf16x3) - unchanged from the 236us round
// ---------------------------------------------------------------------------
#define MM_AHI 0
#define MM_ALO 18432
#define MM_WHI 36864
#define MM_WLO 46080
#define MM_SMEM 55296

__global__ __launch_bounds__(256) void tcmma(const __nv_bfloat16* __restrict__ Ahi,
                                             const __nv_bfloat16* __restrict__ Alo,
                                             int widx0,
                                             const float* __restrict__ bias,
                                             float* __restrict__ C0,
                                             float* __restrict__ C1,
                                             float* __restrict__ C2,
                                             int act)
{
    extern __shared__ char sm[];
    unsigned smb = smem_u32(sm);
    int tid = threadIdx.x;
    int lane = tid & 31;
    int wid = tid >> 5;
    int wm = wid & 3;
    int wn = wid >> 2;
    int m0 = blockIdx.x * 128, n0 = blockIdx.y * 64;
    int z = blockIdx.z;
    const __nv_bfloat16* Whi = g_whi + (size_t)(widx0 + z) * (DD*DD);
    const __nv_bfloat16* Wlo = g_wlo + (size_t)(widx0 + z) * (DD*DD);
    float* C = (z == 0) ? C0 : (z == 1) ? C1 : C2;

    float acc[2][4][4];
    #pragma unroll
    for (int a = 0; a < 2; a++)
        #pragma unroll
        for (int b = 0; b < 4; b++)
            #pragma unroll
            for (int c = 0; c < 4; c++) acc[a][b][c] = 0.0f;

    for (int kc = 0; kc < 4; kc++) {
        #pragma unroll
        for (int it = 0; it < 4; it++) {
            int v = tid + it * 256;
            int row = v >> 3, cg = (v & 7) * 8;
            size_t gofs = (size_t)(m0 + row) * 256 + kc * 64 + cg;
            *(uint4*)(sm + MM_AHI + row*144 + cg*2) = *(const uint4*)&Ahi[gofs];
            *(uint4*)(sm + MM_ALO + row*144 + cg*2) = *(const uint4*)&Alo[gofs];
        }
        #pragma unroll
        for (int it = 0; it < 2; it++) {
            int v = tid + it * 256;
            int row = v >> 3, cg = (v & 7) * 8;
            size_t gofs = (size_t)(n0 + row) * 256 + kc * 64 + cg;
            *(uint4*)(sm + MM_WHI + row*144 + cg*2) = *(const uint4*)&Whi[gofs];
            *(uint4*)(sm + MM_WLO + row*144 + cg*2) = *(const uint4*)&Wlo[gofs];
        }
        __syncthreads();

        #pragma unroll
        for (int ks = 0; ks < 4; ks++) {
            int kb = ks * 16;
            unsigned ah[2][4], al[2][4], bh[2][4], bl[2][4];
            #pragma unroll
            for (int mi = 0; mi < 2; mi++) {
                int row = wm*32 + mi*16 + (lane & 15);
                unsigned ad = smb + MM_AHI + row*144 + (kb + ((lane >> 4) << 3)) * 2;
                ldsm4(ah[mi], ad);
                ldsm4(al[mi], ad + (MM_ALO - MM_AHI));
            }
            #pragma unroll
            for (int gi = 0; gi < 2; gi++) {
                int nrow = wn*32 + gi*16 + (lane & 7) + ((lane >> 4) & 1) * 8;
                unsigned bd = smb + MM_WHI + nrow*144 + (kb + (((lane >> 3) & 1) << 3)) * 2;
                ldsm4(bh[gi], bd);
                ldsm4(bl[gi], bd + (MM_WLO - MM_WHI));
            }
            #pragma unroll
            for (int mi = 0; mi < 2; mi++) {
                #pragma unroll
                for (int ni = 0; ni < 4; ni++) {
                    int gi = ni >> 1, hf = (ni & 1) * 2;
                    mma16816(acc[mi][ni], ah[mi], &bh[gi][hf]);
                    mma16816(acc[mi][ni], ah[mi], &bl[gi][hf]);
                    mma16816(acc[mi][ni], al[mi], &bh[gi][hf]);
                }
            }
        }
        __syncthreads();
    }

    int rbase = m0 + wm*32 + (lane >> 2);
    int cbase = n0 + wn*32 + (lane & 3) * 2;
    #pragma unroll
    for (int mi = 0; mi < 2; mi++) {
        #pragma unroll
        for (int ni = 0; ni < 4; ni++) {
            int col = cbase + ni*8;
            float b0 = bias ? bias[col] : 0.0f;
            float b1 = bias ? bias[col + 1] : 0.0f;
            float v0 = acc[mi][ni][0] + b0;
            float v1 = acc[mi][ni][1] + b1;
            float v2 = acc[mi][ni][2] + b0;
            float v3 = acc[mi][ni][3] + b1;
            if (act) {
                v0 = (v0 >= 0.0f) ? v0 : 0.01f * v0;
                v1 = (v1 >= 0.0f) ? v1 : 0.01f * v1;
                v2 = (v2 >= 0.0f) ? v2 : 0.01f * v2;
                v3 = (v3 >= 0.0f) ? v3 : 0.01f * v3;
            }
            int row = rbase + mi*16;
            *(float2*)&C[(size_t)row * 256 + col]       = make_float2(v0, v1);
            *(float2*)&C[(size_t)(row + 8) * 256 + col] = make_float2(v2, v3);
        }
    }
}

// ---------------------------------------------------------------------------
// L2-normalize q,k and emit bf16 hi/lo in [bh][t][32] layout.
// ---------------------------------------------------------------------------
__global__ __launch_bounds__(256) void qkv_finish_kernel()
{
    int gw   = (blockIdx.x * 256 + threadIdx.x) >> 5;
    int lane = threadIdx.x & 31;
    int bt = gw >> 3, h = gw & 7;
    int b  = bt >> 10, t = bt & 1023;
    size_t src = (size_t)bt * 256 + h * 32 + lane;
    size_t dst = (((size_t)(b * HH + h) * TT) + t) * 32 + lane;
    float qv = g_qraw[src], kv = g_kraw[src];
    float sq = qv * qv, sk = kv * kv;
    #pragma unroll
    for (int off = 16; off; off >>= 1) {
        sq += __shfl_xor_sync(0xffffffffu, sq, off);
        sk += __shfl_xor_sync(0xffffffffu, sk, off);
    }
    float qn = qv / fmaxf(sqrtf(sq), 1e-12f);
    float kn = kv / fmaxf(sqrtf(sk), 1e-12f);
    __nv_bfloat16 qh = __float2bfloat16(qn);
    __nv_bfloat16 kh = __float2bfloat16(kn);
    g_qh2[dst] = qh;
    g_ql2[dst] = __float2bfloat16(qn - __bfloat162float(qh));
    g_kh2[dst] = kh;
    g_kl2[dst] = __float2bfloat16(kn - __bfloat162float(kh));
}

// ---------------------------------------------------------------------------
// V transpose + split: g_vraw [bt][h*32+c] -> g_vthi/lo [bh][c][t]
// grid (16, 32): (64-token chunk, bh)
// ---------------------------------------------------------------------------
__global__ __launch_bounds__(256) void vtrans_kernel()
{
    __shared__ float sT[32*72];
    int tid = threadIdx.x;
    int bh = blockIdx.y, b = bh >> 3, h = bh & 7;
    int t0 = blockIdx.x << 6;
    {
        int row = tid >> 2, cg = (tid & 3) * 8;
        const float* src = &g_vraw[((size_t)(b*1024) + t0 + row) * 256 + h * 32 + cg];
        float4 a = *(const float4*)src;
        float4 c = *(const float4*)(src + 4);
        sT[(cg+0)*72 + row] = a.x; sT[(cg+1)*72 + row] = a.y;
        sT[(cg+2)*72 + row] = a.z; sT[(cg+3)*72 + row] = a.w;
        sT[(cg+4)*72 + row] = c.x; sT[(cg+5)*72 + row] = c.y;
        sT[(cg+6)*72 + row] = c.z; sT[(cg+7)*72 + row] = c.w;
    }
    __syncthreads();
    {
        int c = tid >> 3, sg = (tid & 7) * 8;
        float v[8];
        #pragma unroll
        for (int j = 0; j < 8; j++) v[j] = sT[c*72 + sg + j];
        unsigned hp[4], lp[4];
        #pragma unroll
        for (int j = 0; j < 4; j++) {
            unsigned hh = cvt2bf(v[2*j+1], v[2*j]);
            float f0 = __uint_as_float(hh << 16);
            float f1 = __uint_as_float(hh & 0xFFFF0000u);
            hp[j] = hh;
            lp[j] = cvt2bf(v[2*j+1] - f1, v[2*j] - f0);
        }
        size_t o = ((size_t)bh * 32 + c) * 1024 + t0 + sg;
        *(uint4*)&g_vthi[o] = make_uint4(hp[0], hp[1], hp[2], hp[3]);
        *(uint4*)&g_vtlo[o] = make_uint4(lp[0], lp[1], lp[2], lp[3]);
    }
}

// ---------------------------------------------------------------------------
// HMMA attention. CTA = (64 q rows) x (b,h). 8 warps = 4(q) x 2(s-half).
// smem layout (bytes):
//  QHI 0 (64x80=5120) | QLO 5120 | KHI 10240 | KLO 15360
//  VTHI 20480 (32x144=4608) | VTLO 25088 | LUT 29696 (4096) -> 33792
// post-loop reduce: sO f32[64][34] at 0 (8704B), sRS f32[64] at 10240.
// ---------------------------------------------------------------------------
#define AT_QHI 0
#define AT_QLO 5120
#define AT_KHI 10240
#define AT_KLO 15360
#define AT_VTHI 20480
#define AT_VTLO 25088
#define AT_LUT 29696

__global__ __launch_bounds__(256) void attn_mma_kernel()
{
    __shared__ __align__(16) char SM_[33792];
    unsigned smb = smem_u32(SM_);
    float* sLUT = (float*)(SM_ + AT_LUT);

    int tid = threadIdx.x;
    int lane = tid & 31;
    int wid = tid >> 5;
    int wq = wid & 3;
    int ws = wid >> 2;
    int bh = blockIdx.y, b = bh >> 3, h = bh & 7;
    int t0 = blockIdx.x << 6;

    #pragma unroll
    for (int r = 0; r < 4; r++)
        sLUT[tid + r*256] = g_lutv[h*1024 + tid + r*256];
    {   // stage Q hi/lo (once)
        int row = tid >> 2, cg = (tid & 3) * 8;
        size_t gofs = (((size_t)bh * TT) + t0 + row) * 32 + cg;
        *(uint4*)(SM_ + AT_QHI + row*80 + cg*2) = *(const uint4*)&g_qh2[gofs];
        *(uint4*)(SM_ + AT_QLO + row*80 + cg*2) = *(const uint4*)&g_ql2[gofs];
    }
    __syncthreads();

    float oacc[4][4];
    #pragma unroll
    for (int i = 0; i < 4; i++)
        #pragma unroll
        for (int j = 0; j < 4; j++) oacc[i][j] = 0.0f;
    float zs0 = 0.0f, zs8 = 0.0f;

    int qrow_f = (lane >> 2);            // fragment row within 16
    int ccol_f = (lane & 3) * 2;         // fragment col pair base

    #pragma unroll 1
    for (int st = 0; st < 16; st++) {
        int s0 = st << 6;
        // md indices at fragment coordinates (register-resident)
        ushort2 md[4][2];
        {
            size_t mb = (size_t)b * TT * TT;
            int gr = t0 + wq*16 + qrow_f;
            int gcb = s0 + ws*32 + ccol_f;
            #pragma unroll
            for (int ni = 0; ni < 4; ni++) {
                md[ni][0] = *(const ushort2*)&g_mdx[mb + (size_t)gr * TT + gcb + ni*8];
                md[ni][1] = *(const ushort2*)&g_mdx[mb + (size_t)(gr+8) * TT + gcb + ni*8];
            }
        }
        {   // stage K hi/lo
            int row = tid >> 2, cg = (tid & 3) * 8;
            size_t gofs = (((size_t)bh * TT) + s0 + row) * 32 + cg;
            *(uint4*)(SM_ + AT_KHI + row*80 + cg*2) = *(const uint4*)&g_kh2[gofs];
            *(uint4*)(SM_ + AT_KLO + row*80 + cg*2) = *(const uint4*)&g_kl2[gofs];
        }
        {   // stage VT hi/lo
            int c = tid >> 3, sg = (tid & 7) * 8;
            size_t gofs = ((size_t)bh * 32 + c) * 1024 + s0 + sg;
            *(uint4*)(SM_ + AT_VTHI + c*144 + sg*2) = *(const uint4*)&g_vthi[gofs];
            *(uint4*)(SM_ + AT_VTLO + c*144 + sg*2) = *(const uint4*)&g_vtlo[gofs];
        }
        __syncthreads();

        // ---- QK: S[16 x 32] per warp, bf16x3 ----
        float sacc[4][4];
        #pragma unroll
        for (int i = 0; i < 4; i++)
            #pragma unroll
            for (int j = 0; j < 4; j++) sacc[i][j] = 0.0f;

        #pragma unroll
        for (int ks = 0; ks < 2; ks++) {
            int kb = ks * 16;
            unsigned ah[4], al[4], bhf[2][4], blf[2][4];
            {
                int row = wq*16 + (lane & 15);
                unsigned ad = smb + AT_QHI + row*80 + (kb + ((lane >> 4) << 3)) * 2;
                ldsm4(ah, ad);
                ldsm4(al, ad + (AT_QLO - AT_QHI));
            }
            #pragma unroll
            for (int gi = 0; gi < 2; gi++) {
                int nrow = ws*32 + gi*16 + (lane & 7) + ((lane >> 4) & 1) * 8;
                unsigned bd = smb + AT_KHI + nrow*80 + (kb + (((lane >> 3) & 1) << 3)) * 2;
                ldsm4(bhf[gi], bd);
                ldsm4(blf[gi], bd + (AT_KLO - AT_KHI));
            }
            #pragma unroll
            for (int ni = 0; ni < 4; ni++) {
                int gi = ni >> 1, hf = (ni & 1) * 2;
                mma16816(sacc[ni], ah, &bhf[gi][hf]);
                mma16816(sacc[ni], ah, &blf[gi][hf]);
                mma16816(sacc[ni], al, &bhf[gi][hf]);
            }
        }

        // ---- bias + exp + pack P (hi/lo) ----
        unsigned phi[8], plo[8];
        #pragma unroll
        for (int ni = 0; ni < 4; ni++) {
            ushort2 m0 = md[ni][0], m1 = md[ni][1];
            float z0 = (m0.x >= 1024) ? 0.0f : __expf(sacc[ni][0] + sLUT[m0.x & 1023]);
            float z1 = (m0.y >= 1024) ? 0.0f : __expf(sacc[ni][1] + sLUT[m0.y & 1023]);
            float z2 = (m1.x >= 1024) ? 0.0f : __expf(sacc[ni][2] + sLUT[m1.x & 1023]);
            float z3 = (m1.y >= 1024) ? 0.0f : __expf(sacc[ni][3] + sLUT[m1.y & 1023]);
            zs0 += z0 + z1;
            zs8 += z2 + z3;
            unsigned p01 = cvt2bf(z1, z0);
            unsigned p23 = cvt2bf(z3, z2);
            phi[ni*2]   = p01;
            phi[ni*2+1] = p23;
            float f0 = __uint_as_float(p01 << 16), f1 = __uint_as_float(p01 & 0xFFFF0000u);
            float f2 = __uint_as_float(p23 << 16), f3 = __uint_as_float(p23 & 0xFFFF0000u);
            plo[ni*2]   = cvt2bf(z1 - f1, z0 - f0);
            plo[ni*2+1] = cvt2bf(z3 - f3, z2 - f2);
        }

        // ---- PV: O += P @ V^T(B-operand), bf16x3 ----
        #pragma unroll
        for (int kf = 0; kf < 2; kf++) {
            unsigned vbh[2][4], vbl[2][4];
            #pragma unroll
            for (int gi = 0; gi < 2; gi++) {
                int nrow = gi*16 + (lane & 7) + ((lane >> 4) & 1) * 8;
                int col = ws*32 + kf*16 + (((lane >> 3) & 1) << 3);
                unsigned bd = smb + AT_VTHI + nrow*144 + col*2;
                ldsm4(vbh[gi], bd);
                ldsm4(vbl[gi], bd + (AT_VTLO - AT_VTHI));
            }
            #pragma unroll
            for (int ni = 0; ni < 4; ni++) {
                int gi = ni >> 1, hf = (ni & 1) * 2;
                mma16816(oacc[ni], &phi[4*kf], &vbh[gi][hf]);
                mma16816(oacc[ni], &plo[4*kf], &vbh[gi][hf]);
                mma16816(oacc[ni], &phi[4*kf], &vbl[gi][hf]);
            }
        }
        __syncthreads();
    }

    // quad-reduce rowsums (sum over fragment col groups)
    zs0 += __shfl_xor_sync(0xffffffffu, zs0, 1);
    zs0 += __shfl_xor_sync(0xffffffffu, zs0, 2);
    zs8 += __shfl_xor_sync(0xffffffffu, zs8, 1);
    zs8 += __shfl_xor_sync(0xffffffffu, zs8, 2);

    float* sO  = (float*)(SM_ + 0);        // [64][34]
    float* sRS = (float*)(SM_ + AT_KHI);   // [64]
    int r = wq*16 + qrow_f;
    if (ws == 1) {
        if ((lane & 3) == 0) {
            sRS[r]     = zs0;
            sRS[r + 8] = zs8;
        }
        #pragma unroll
        for (int ni = 0; ni < 4; ni++) {
            int c = ni*8 + ccol_f;
            *(float2*)&sO[r*34 + c]     = make_float2(oacc[ni][0], oacc[ni][1]);
            *(float2*)&sO[(r+8)*34 + c] = make_float2(oacc[ni][2], oacc[ni][3]);
        }
    }
    __syncthreads();
    if (ws == 0) {
        float inv0 = 1.0f / (zs0 + sRS[r]     + 1e-5f);
        float inv8 = 1.0f / (zs8 + sRS[r + 8] + 1e-5f);
        size_t o0 = ((size_t)b * TT + t0 + r)     * DD + h * 32;
        size_t o8 = ((size_t)b * TT + t0 + r + 8) * DD + h * 32;
        #pragma unroll
        for (int ni = 0; ni < 4; ni++) {
            int c = ni*8 + ccol_f;
            float2 p0 = *(const float2*)&sO[r*34 + c];
            float2 p8 = *(const float2*)&sO[(r+8)*34 + c];
            float v0 = (oacc[ni][0] + p0.x) * inv0;
            float v1 = (oacc[ni][1] + p0.y) * inv0;
            float v2 = (oacc[ni][2] + p8.x) * inv8;
            float v3 = (oacc[ni][3] + p8.y) * inv8;
            unsigned h0 = cvt2bf(v1, v0);
            unsigned h8 = cvt2bf(v3, v2);
            float f0 = __uint_as_float(h0 << 16), f1 = __uint_as_float(h0 & 0xFFFF0000u);
            float f2 = __uint_as_float(h8 << 16), f3 = __uint_as_float(h8 & 0xFFFF0000u);
            *(unsigned*)&g_athi[o0 + c] = h0;
            *(unsigned*)&g_atlo[o0 + c] = cvt2bf(v1 - f1, v0 - f0);
            *(unsigned*)&g_athi[o8 + c] = h8;
            *(unsigned*)&g_atlo[o8 + c] = cvt2bf(v3 - f3, v2 - f2);
        }
    }
}

__global__ __launch_bounds__(256) void ln_kernel(const float* __restrict__ a,
                                                 const float* __restrict__ b,
                                                 const float* __restrict__ g,
                                                 const float* __restrict__ be,
                                                 float* __restrict__ out)
{
    int w    = (blockIdx.x * 256 + threadIdx.x) >> 5;
    int lane = threadIdx.x & 31;
    const float* ap = a + (size_t)w * 256;
    const float* bp = b + (size_t)w * 256;
    float v[8]; float s = 0.0f;
    #pragma unroll
    for (int u = 0; u < 8; u++) { v[u] = ap[lane + 32*u] + bp[lane + 32*u]; s += v[u]; }
    #pragma unroll
    for (int off = 16; off; off >>= 1) s += __shfl_xor_sync(0xffffffffu, s, off);
    float mu = s * (1.0f / 256.0f);
    float vs = 0.0f;
    #pragma unroll
    for (int u = 0; u < 8; u++) { float d = v[u] - mu; vs = fmaf(d, d, vs); }
    #pragma unroll
    for (int off = 16; off; off >>= 1) vs += __shfl_xor_sync(0xffffffffu, vs, off);
    float rstd = rsqrtf(vs * (1.0f / 256.0f) + 1e-5f);
    #pragma unroll
    for (int u = 0; u < 8; u++) {
        int col = lane + 32*u;
        out[(size_t)w * 256 + col] = (v[u] - mu) * rstd * g[col] + be[col];
    }
}

extern "C" void kernel_launch(void* const* d_in, const int* in_sizes, int n_in,
                              void* d_out, int out_size)
{
    const float* x    = (const float*)d_in[0];
    const void*  mask = d_in[1];
    const float* rel  = (const float*)d_in[2];
    const float* pw1  = (const float*)d_in[6];
    const float* pb1  = (const float*)d_in[7];
    const float* pw2  = (const float*)d_in[8];
    const float* pb2  = (const float*)d_in[9];
    const float* bo   = (const float*)d_in[11];
    const float* bfv  = (const float*)d_in[13];
    const float* g1   = (const float*)d_in[14];
    const float* be1  = (const float*)d_in[15];
    const float* g2   = (const float*)d_in[16];
    const float* be2  = (const float*)d_in[17];

    float *qraw, *kraw, *vraw, *y, *zz;
    __nv_bfloat16 *xhi, *xlo, *athi, *atlo, *zhi, *zlo;
    cudaGetSymbolAddress((void**)&qraw, g_qraw);
    cudaGetSymbolAddress((void**)&kraw, g_kraw);
    cudaGetSymbolAddress((void**)&vraw, g_vraw);
    cudaGetSymbolAddress((void**)&y,    g_y);
    cudaGetSymbolAddress((void**)&zz,   g_zz);
    cudaGetSymbolAddress((void**)&xhi,  g_xhi);
    cudaGetSymbolAddress((void**)&xlo,  g_xlo);
    cudaGetSymbolAddress((void**)&athi, g_athi);
    cudaGetSymbolAddress((void**)&atlo, g_atlo);
    cudaGetSymbolAddress((void**)&zhi,  g_zhi);
    cudaGetSymbolAddress((void**)&zlo,  g_zlo);

    cudaFuncSetAttribute(tcmma, cudaFuncAttributeMaxDynamicSharedMemorySize, MM_SMEM);

    prep_kernel<<<1, 128>>>(pw1, pb1, pw2, pb2);
    lut_kernel<<<8, 1024>>>();
    detect_kernel<<<256, 256>>>((const unsigned*)mask);
    maskfuse_kernel<<<4096, 256>>>(rel, mask);
    splitw_kernel<<<640, 256>>>((const float*)d_in[3], (const float*)d_in[4],
                                (const float*)d_in[5], (const float*)d_in[10],
                                (const float*)d_in[12]);
    split_kernel<<<2048, 256>>>(x, xhi, xlo);

    tcmma<<<dim3(32, 4, 3), 256, MM_SMEM>>>(xhi, xlo, 0, nullptr, qraw, kraw, vraw, 0);
    qkv_finish_kernel<<<4096, 256>>>();
    vtrans_kernel<<<dim3(16, 32), 256>>>();

    attn_mma_kernel<<<dim3(16, 32), 256>>>();

    tcmma<<<dim3(32, 4, 1), 256, MM_SMEM>>>(athi, atlo, 3, bo, y, y, y, 0);
    ln_kernel<<<512, 256>>>(x, y, g1, be1, zz);
    split_kernel<<<2048, 256>>>(zz, zhi, zlo);
    tcmma<<<dim3(32, 4, 1), 256, MM_SMEM>>>(zhi, zlo, 4, bfv, qraw, qraw, qraw, 1);
    ln_kernel<<<512, 256>>>(zz, qraw, g2, be2, (float*)d_out);
}

// round 9
// speedup vs baseline: 2.2390x; 1.0462x over previous
#include <cuda_runtime.h>
#include <cuda_bf16.h>

#define BB  4
#define TT  1024
#define DD  256
#define HH  8
#define CC  16
#define BT  (BB*TT)

typedef unsigned long long ull;

__device__ __forceinline__ unsigned smem_u32(const void* p) {
    unsigned a;
    asm("{ .reg .u64 t; cvta.to.shared.u64 t, %1; cvt.u32.u64 %0, t; }" : "=r"(a) : "l"(p));
    return a;
}
__device__ __forceinline__ void ldsm4(unsigned* r, unsigned addr) {
    asm volatile("ldmatrix.sync.aligned.m8n8.x4.shared.b16 {%0,%1,%2,%3}, [%4];"
                 : "=r"(r[0]), "=r"(r[1]), "=r"(r[2]), "=r"(r[3]) : "r"(addr));
}
__device__ __forceinline__ void mma16816(float* c, const unsigned* a, const unsigned* b) {
    asm volatile("mma.sync.aligned.m16n8k16.row.col.f32.bf16.bf16.f32 "
                 "{%0,%1,%2,%3}, {%4,%5,%6,%7}, {%8,%9}, {%0,%1,%2,%3};"
                 : "+f"(c[0]), "+f"(c[1]), "+f"(c[2]), "+f"(c[3])
                 : "r"(a[0]), "r"(a[1]), "r"(a[2]), "r"(a[3]), "r"(b[0]), "r"(b[1]));
}
// pack two f32 -> bf16x2 register: low 16 bits = lo, high = hi
__device__ __forceinline__ unsigned cvt2bf(float hi, float lo) {
    unsigned r;
    asm("cvt.rn.bf16x2.f32 %0, %1, %2;" : "=r"(r) : "f"(hi), "f"(lo));
    return r;
}

// ---------------- scratch ----------------
__device__ float g_qraw[BT*DD];          // also FFN scratch
__device__ float g_vraw[BT*DD];
__device__ float g_y[BT*DD];
__device__ float g_zz[BT*DD];
__device__ unsigned short g_mdx[BB*TT*TT];
__device__ float g_coef[HH*34];
__device__ float g_lutv[HH*1024];
__device__ int   g_mask_flags;
__device__ __nv_bfloat16 g_xhi[BT*DD],  g_xlo[BT*DD];
__device__ __nv_bfloat16 g_athi[BT*DD], g_atlo[BT*DD];
__device__ __nv_bfloat16 g_zhi[BT*DD],  g_zlo[BT*DD];
__device__ __nv_bfloat16 g_whi[5*DD*DD], g_wlo[5*DD*DD];
// attention operands, bf16 hi/lo
__device__ __nv_bfloat16 g_vthi[32*HH*BB*TT], g_vtlo[32*HH*BB*TT]; // [bh][32][1024]
__device__ __nv_bfloat16 g_qh2[HH*BB*TT*32], g_ql2[HH*BB*TT*32];   // [bh][t][32]
__device__ __nv_bfloat16 g_kh2[HH*BB*TT*32], g_kl2[HH*BB*TT*32];

__global__ void prep_kernel(const float* __restrict__ pw1, const float* __restrict__ pb1,
                            const float* __restrict__ pw2, const float* __restrict__ pb2)
{
    if (threadIdx.x == 0) g_mask_flags = 0;
    int h = threadIdx.x >> 4;
    int c = threadIdx.x & 15;
    if (h >= HH) return;
    float w1 = pw1[h*CC + c], b1 = pb1[h*CC + c], w2 = pw2[h*CC + c];
    float beta, delta, k0add, k1add;
    if (w1 != 0.0f) {
        beta  = 0.495f * w2 * fabsf(w1);
        delta = -b1 / w1;
        k0add = 0.505f * w2 * b1;
        k1add = 0.505f * w2 * w1;
    } else {
        beta = 0.0f; delta = 0.0f;
        k0add = w2 * (0.505f * b1 + 0.495f * fabsf(b1));
        k1add = 0.0f;
    }
    #pragma unroll
    for (int off = 1; off < 16; off <<= 1) {
        k0add += __shfl_xor_sync(0xffffffffu, k0add, off);
        k1add += __shfl_xor_sync(0xffffffffu, k1add, off);
    }
    g_coef[h*34 + 2  + c] = beta;
    g_coef[h*34 + 18 + c] = delta;
    if (c == 0) {
        g_coef[h*34 + 0] = pb2[h] + k0add;
        g_coef[h*34 + 1] = k1add;
    }
}

__global__ void lut_kernel()
{
    int i = blockIdx.x * blockDim.x + threadIdx.x;
    int h = i >> 10, cell = i & 1023;
    float m = (cell + 0.5f) * (1.0f / 1024.0f);
    float v = g_coef[h*34 + 0] + g_coef[h*34 + 1] * m;
    #pragma unroll
    for (int c = 0; c < 16; c++) {
        float be = g_coef[h*34 + 2 + c], de = g_coef[h*34 + 18 + c];
        v += be * fabsf(m - de);
    }
    g_lutv[i] = -v;
}

__global__ void detect_kernel(const unsigned* __restrict__ w)
{
    int i = blockIdx.x * blockDim.x + threadIdx.x;
    unsigned x = w[i];
    int f = 0;
    if (x == 0x3F800000u)               f = 2;
    else if ((x & 0xFFFFu) == 0x3F80u)  f = 4;
    else if (x > 1u)                    f = 1;
    if (f) atomicOr(&g_mask_flags, f);
}

__global__ __launch_bounds__(256) void maskfuse_kernel(const float* __restrict__ rd,
                                                       const void* __restrict__ maskp)
{
    int i = blockIdx.x * 256 + threadIdx.x;
    size_t base = (size_t)i * 4;
    int mf = g_mask_flags;
    int mode = (mf & 4) ? 3 : (mf & 2) ? 2 : (mf & 1) ? 1 : 0;
    float4 d4 = *(const float4*)&rd[base];
    int m0, m1, m2, m3;
    if (mode == 0) {
        int4 m = *(const int4*)((const int*)maskp + base);
        m0 = m.x != 0; m1 = m.y != 0; m2 = m.z != 0; m3 = m.w != 0;
    } else if (mode == 1) {
        uchar4 m = *(const uchar4*)((const unsigned char*)maskp + base);
        m0 = m.x != 0; m1 = m.y != 0; m2 = m.z != 0; m3 = m.w != 0;
    } else if (mode == 2) {
        float4 m = *(const float4*)((const float*)maskp + base);
        m0 = m.x != 0.0f; m1 = m.y != 0.0f; m2 = m.z != 0.0f; m3 = m.w != 0.0f;
    } else {
        ushort4 m = *(const ushort4*)((const unsigned short*)maskp + base);
        m0 = m.x != 0; m1 = m.y != 0; m2 = m.z != 0; m3 = m.w != 0;
    }
    int i0 = min(max(__float2int_rd(d4.x * 1024.0f), 0), 1023);
    int i1 = min(max(__float2int_rd(d4.y * 1024.0f), 0), 1023);
    int i2 = min(max(__float2int_rd(d4.z * 1024.0f), 0), 1023);
    int i3 = min(max(__float2int_rd(d4.w * 1024.0f), 0), 1023);
    ushort4 o;
    o.x = (unsigned short)(m0 ? 2047 : i0);
    o.y = (unsigned short)(m1 ? 2047 : i1);
    o.z = (unsigned short)(m2 ? 2047 : i2);
    o.w = (unsigned short)(m3 ? 2047 : i3);
    *(ushort4*)&g_mdx[base] = o;
}

__global__ __launch_bounds__(256) void split_kernel(const float* __restrict__ src,
                                                    __nv_bfloat16* __restrict__ hi,
                                                    __nv_bfloat16* __restrict__ lo)
{
    int i = blockIdx.x * 256 + threadIdx.x;
    float2 v = *(const float2*)&src[(size_t)i * 2];
    __nv_bfloat16 hx = __float2bfloat16(v.x), hy = __float2bfloat16(v.y);
    __nv_bfloat162 h2; h2.x = hx; h2.y = hy;
    __nv_bfloat162 l2;
    l2.x = __float2bfloat16(v.x - __bfloat162float(hx));
    l2.y = __float2bfloat16(v.y - __bfloat162float(hy));
    *(__nv_bfloat162*)&hi[(size_t)i * 2] = h2;
    *(__nv_bfloat162*)&lo[(size_t)i * 2] = l2;
}

__global__ __launch_bounds__(256) void splitw_kernel(const float* __restrict__ w0,
                                                     const float* __restrict__ w1,
                                                     const float* __restrict__ w2,
                                                     const float* __restrict__ w3,
                                                     const float* __restrict__ w4)
{
    int i = blockIdx.x * 256 + threadIdx.x;
    size_t e = (size_t)i * 2;
    int w = (int)(e >> 16);
    size_t off = e & 65535;
    const float* src = (w == 0) ? w0 : (w == 1) ? w1 : (w == 2) ? w2 : (w == 3) ? w3 : w4;
    float2 v = *(const float2*)&src[off];
    __nv_bfloat16 hx = __float2bfloat16(v.x), hy = __float2bfloat16(v.y);
    __nv_bfloat162 h2; h2.x = hx; h2.y = hy;
    __nv_bfloat162 l2;
    l2.x = __float2bfloat16(v.x - __bfloat162float(hx));
    l2.y = __float2bfloat16(v.y - __bfloat162float(hy));
    *(__nv_bfloat162*)&g_whi[e] = h2;
    *(__nv_bfloat162*)&g_wlo[e] = l2;
}

// ---------------------------------------------------------------------------
// HMMA GEMM (bf16x3): C[4096,256] = A @ W^T
// qkv=1, z<2: fused L2-normalize + bf16 hi/lo split to q/k attention layout.
// otherwise: fp32 out (+bias)(+lrelu).
// ---------------------------------------------------------------------------
#define MM_AHI 0
#define MM_ALO 18432
#define MM_WHI 36864
#define MM_WLO 46080
#define MM_SMEM 55296

__global__ __launch_bounds__(256) void tcmma(const __nv_bfloat16* __restrict__ Ahi,
                                             const __nv_bfloat16* __restrict__ Alo,
                                             int widx0,
                                             const float* __restrict__ bias,
                                             float* __restrict__ C0,
                                             float* __restrict__ C1,
                                             float* __restrict__ C2,
                                             int act, int qkv)
{
    extern __shared__ char sm[];
    unsigned smb = smem_u32(sm);
    int tid = threadIdx.x;
    int lane = tid & 31;
    int wid = tid >> 5;
    int wm = wid & 3;
    int wn = wid >> 2;
    int m0 = blockIdx.x * 128, n0 = blockIdx.y * 64;
    int z = blockIdx.z;
    const __nv_bfloat16* Whi = g_whi + (size_t)(widx0 + z) * (DD*DD);
    const __nv_bfloat16* Wlo = g_wlo + (size_t)(widx0 + z) * (DD*DD);
    float* C = (z == 0) ? C0 : (z == 1) ? C1 : C2;

    float acc[2][4][4];
    #pragma unroll
    for (int a = 0; a < 2; a++)
        #pragma unroll
        for (int b = 0; b < 4; b++)
            #pragma unroll
            for (int c = 0; c < 4; c++) acc[a][b][c] = 0.0f;

    for (int kc = 0; kc < 4; kc++) {
        #pragma unroll
        for (int it = 0; it < 4; it++) {
            int v = tid + it * 256;
            int row = v >> 3, cg = (v & 7) * 8;
            size_t gofs = (size_t)(m0 + row) * 256 + kc * 64 + cg;
            *(uint4*)(sm + MM_AHI + row*144 + cg*2) = *(const uint4*)&Ahi[gofs];
            *(uint4*)(sm + MM_ALO + row*144 + cg*2) = *(const uint4*)&Alo[gofs];
        }
        #pragma unroll
        for (int it = 0; it < 2; it++) {
            int v = tid + it * 256;
            int row = v >> 3, cg = (v & 7) * 8;
            size_t gofs = (size_t)(n0 + row) * 256 + kc * 64 + cg;
            *(uint4*)(sm + MM_WHI + row*144 + cg*2) = *(const uint4*)&Whi[gofs];
            *(uint4*)(sm + MM_WLO + row*144 + cg*2) = *(const uint4*)&Wlo[gofs];
        }
        __syncthreads();

        #pragma unroll
        for (int ks = 0; ks < 4; ks++) {
            int kb = ks * 16;
            unsigned ah[2][4], al[2][4], bh[2][4], bl[2][4];
            #pragma unroll
            for (int mi = 0; mi < 2; mi++) {
                int row = wm*32 + mi*16 + (lane & 15);
                unsigned ad = smb + MM_AHI + row*144 + (kb + ((lane >> 4) << 3)) * 2;
                ldsm4(ah[mi], ad);
                ldsm4(al[mi], ad + (MM_ALO - MM_AHI));
            }
            #pragma unroll
            for (int gi = 0; gi < 2; gi++) {
                int nrow = wn*32 + gi*16 + (lane & 7) + ((lane >> 4) & 1) * 8;
                unsigned bd = smb + MM_WHI + nrow*144 + (kb + (((lane >> 3) & 1) << 3)) * 2;
                ldsm4(bh[gi], bd);
                ldsm4(bl[gi], bd + (MM_WLO - MM_WHI));
            }
            #pragma unroll
            for (int mi = 0; mi < 2; mi++) {
                #pragma unroll
                for (int ni = 0; ni < 4; ni++) {
                    int gi = ni >> 1, hf = (ni & 1) * 2;
                    mma16816(acc[mi][ni], ah[mi], &bh[gi][hf]);
                    mma16816(acc[mi][ni], ah[mi], &bl[gi][hf]);
                    mma16816(acc[mi][ni], al[mi], &bh[gi][hf]);
                }
            }
        }
        __syncthreads();
    }

    if (qkv && z != 2) {
        // fused: per-row L2 norm (warp tile = exactly one head's 32 cols),
        // bf16 hi/lo split, write in attention layout [bh][t][32].
        __nv_bfloat16* dsthi = (z == 0) ? g_qh2 : g_kh2;
        __nv_bfloat16* dstlo = (z == 0) ? g_ql2 : g_kl2;
        int head = blockIdx.y * 2 + wn;
        #pragma unroll
        for (int mi = 0; mi < 2; mi++) {
            #pragma unroll
            for (int rr = 0; rr < 2; rr++) {
                float v[8];
                #pragma unroll
                for (int ni = 0; ni < 4; ni++) {
                    v[ni*2]   = acc[mi][ni][rr*2];
                    v[ni*2+1] = acc[mi][ni][rr*2+1];
                }
                float ss = 0.0f;
                #pragma unroll
                for (int j = 0; j < 8; j++) ss = fmaf(v[j], v[j], ss);
                ss += __shfl_xor_sync(0xffffffffu, ss, 1);
                ss += __shfl_xor_sync(0xffffffffu, ss, 2);
                float inv = 1.0f / fmaxf(sqrtf(ss), 1e-12f);
                int row = m0 + wm*32 + mi*16 + rr*8 + (lane >> 2);
                int b = row >> 10, t = row & 1023;
                size_t base = (((size_t)(b*8 + head)) * 1024 + t) * 32 + (lane & 3) * 2;
                #pragma unroll
                for (int ni = 0; ni < 4; ni++) {
                    float v0 = v[ni*2] * inv, v1 = v[ni*2+1] * inv;
                    unsigned hh = cvt2bf(v1, v0);
                    float f0 = __uint_as_float(hh << 16), f1 = __uint_as_float(hh & 0xFFFF0000u);
                    *(unsigned*)&dsthi[base + ni*8] = hh;
                    *(unsigned*)&dstlo[base + ni*8] = cvt2bf(v1 - f1, v0 - f0);
                }
            }
        }
        return;
    }

    int rbase = m0 + wm*32 + (lane >> 2);
    int cbase = n0 + wn*32 + (lane & 3) * 2;
    #pragma unroll
    for (int mi = 0; mi < 2; mi++) {
        #pragma unroll
        for (int ni = 0; ni < 4; ni++) {
            int col = cbase + ni*8;
            float b0 = bias ? bias[col] : 0.0f;
            float b1 = bias ? bias[col + 1] : 0.0f;
            float v0 = acc[mi][ni][0] + b0;
            float v1 = acc[mi][ni][1] + b1;
            float v2 = acc[mi][ni][2] + b0;
            float v3 = acc[mi][ni][3] + b1;
            if (act) {
                v0 = (v0 >= 0.0f) ? v0 : 0.01f * v0;
                v1 = (v1 >= 0.0f) ? v1 : 0.01f * v1;
                v2 = (v2 >= 0.0f) ? v2 : 0.01f * v2;
                v3 = (v3 >= 0.0f) ? v3 : 0.01f * v3;
            }
            int row = rbase + mi*16;
            *(float2*)&C[(size_t)row * 256 + col]       = make_float2(v0, v1);
            *(float2*)&C[(size_t)(row + 8) * 256 + col] = make_float2(v2, v3);
        }
    }
}

// ---------------------------------------------------------------------------
// V transpose + split: g_vraw [bt][h*32+c] -> g_vthi/lo [bh][c][t]
// ---------------------------------------------------------------------------
__global__ __launch_bounds__(256) void vtrans_kernel()
{
    __shared__ float sT[32*72];
    int tid = threadIdx.x;
    int bh = blockIdx.y, b = bh >> 3, h = bh & 7;
    int t0 = blockIdx.x << 6;
    {
        int row = tid >> 2, cg = (tid & 3) * 8;
        const float* src = &g_vraw[((size_t)(b*1024) + t0 + row) * 256 + h * 32 + cg];
        float4 a = *(const float4*)src;
        float4 c = *(const float4*)(src + 4);
        sT[(cg+0)*72 + row] = a.x; sT[(cg+1)*72 + row] = a.y;
        sT[(cg+2)*72 + row] = a.z; sT[(cg+3)*72 + row] = a.w;
        sT[(cg+4)*72 + row] = c.x; sT[(cg+5)*72 + row] = c.y;
        sT[(cg+6)*72 + row] = c.z; sT[(cg+7)*72 + row] = c.w;
    }
    __syncthreads();
    {
        int c = tid >> 3, sg = (tid & 7) * 8;
        float v[8];
        #pragma unroll
        for (int j = 0; j < 8; j++) v[j] = sT[c*72 + sg + j];
        unsigned hp[4], lp[4];
        #pragma unroll
        for (int j = 0; j < 4; j++) {
            unsigned hh = cvt2bf(v[2*j+1], v[2*j]);
            float f0 = __uint_as_float(hh << 16);
            float f1 = __uint_as_float(hh & 0xFFFF0000u);
            hp[j] = hh;
            lp[j] = cvt2bf(v[2*j+1] - f1, v[2*j] - f0);
        }
        size_t o = ((size_t)bh * 32 + c) * 1024 + t0 + sg;
        *(uint4*)&g_vthi[o] = make_uint4(hp[0], hp[1], hp[2], hp[3]);
        *(uint4*)&g_vtlo[o] = make_uint4(lp[0], lp[1], lp[2], lp[3]);
    }
}

// ---------------------------------------------------------------------------
// HMMA attention (unchanged from 184us round)
// ---------------------------------------------------------------------------
#define AT_QHI 0
#define AT_QLO 5120
#define AT_KHI 10240
#define AT_KLO 15360
#define AT_VTHI 20480
#define AT_VTLO 25088
#define AT_LUT 29696

__global__ __launch_bounds__(256) void attn_mma_kernel()
{
    __shared__ __align__(16) char SM_[33792];
    unsigned smb = smem_u32(SM_);
    float* sLUT = (float*)(SM_ + AT_LUT);

    int tid = threadIdx.x;
    int lane = tid & 31;
    int wid = tid >> 5;
    int wq = wid & 3;
    int ws = wid >> 2;
    int bh = blockIdx.y, b = bh >> 3, h = bh & 7;
    int t0 = blockIdx.x << 6;

    #pragma unroll
    for (int r = 0; r < 4; r++)
        sLUT[tid + r*256] = g_lutv[h*1024 + tid + r*256];
    {
        int row = tid >> 2, cg = (tid & 3) * 8;
        size_t gofs = (((size_t)bh * TT) + t0 + row) * 32 + cg;
        *(uint4*)(SM_ + AT_QHI + row*80 + cg*2) = *(const uint4*)&g_qh2[gofs];
        *(uint4*)(SM_ + AT_QLO + row*80 + cg*2) = *(const uint4*)&g_ql2[gofs];
    }
    __syncthreads();

    float oacc[4][4];
    #pragma unroll
    for (int i = 0; i < 4; i++)
        #pragma unroll
        for (int j = 0; j < 4; j++) oacc[i][j] = 0.0f;
    float zs0 = 0.0f, zs8 = 0.0f;

    int qrow_f = (lane >> 2);
    int ccol_f = (lane & 3) * 2;

    #pragma unroll 1
    for (int st = 0; st < 16; st++) {
        int s0 = st << 6;
        ushort2 md[4][2];
        {
            size_t mb = (size_t)b * TT * TT;
            int gr = t0 + wq*16 + qrow_f;
            int gcb = s0 + ws*32 + ccol_f;
            #pragma unroll
            for (int ni = 0; ni < 4; ni++) {
                md[ni][0] = *(const ushort2*)&g_mdx[mb + (size_t)gr * TT + gcb + ni*8];
                md[ni][1] = *(const ushort2*)&g_mdx[mb + (size_t)(gr+8) * TT + gcb + ni*8];
            }
        }
        {
            int row = tid >> 2, cg = (tid & 3) * 8;
            size_t gofs = (((size_t)bh * TT) + s0 + row) * 32 + cg;
            *(uint4*)(SM_ + AT_KHI + row*80 + cg*2) = *(const uint4*)&g_kh2[gofs];
            *(uint4*)(SM_ + AT_KLO + row*80 + cg*2) = *(const uint4*)&g_kl2[gofs];
        }
        {
            int c = tid >> 3, sg = (tid & 7) * 8;
            size_t gofs = ((size_t)bh * 32 + c) * 1024 + s0 + sg;
            *(uint4*)(SM_ + AT_VTHI + c*144 + sg*2) = *(const uint4*)&g_vthi[gofs];
            *(uint4*)(SM_ + AT_VTLO + c*144 + sg*2) = *(const uint4*)&g_vtlo[gofs];
        }
        __syncthreads();

        float sacc[4][4];
        #pragma unroll
        for (int i = 0; i < 4; i++)
            #pragma unroll
            for (int j = 0; j < 4; j++) sacc[i][j] = 0.0f;

        #pragma unroll
        for (int ks = 0; ks < 2; ks++) {
            int kb = ks * 16;
            unsigned ah[4], al[4], bhf[2][4], blf[2][4];
            {
                int row = wq*16 + (lane & 15);
                unsigned ad = smb + AT_QHI + row*80 + (kb + ((lane >> 4) << 3)) * 2;
                ldsm4(ah, ad);
                ldsm4(al, ad + (AT_QLO - AT_QHI));
            }
            #pragma unroll
            for (int gi = 0; gi < 2; gi++) {
                int nrow = ws*32 + gi*16 + (lane & 7) + ((lane >> 4) & 1) * 8;
                unsigned bd = smb + AT_KHI + nrow*80 + (kb + (((lane >> 3) & 1) << 3)) * 2;
                ldsm4(bhf[gi], bd);
                ldsm4(blf[gi], bd + (AT_KLO - AT_KHI));
            }
            #pragma unroll
            for (int ni = 0; ni < 4; ni++) {
                int gi = ni >> 1, hf = (ni & 1) * 2;
                mma16816(sacc[ni], ah, &bhf[gi][hf]);
                mma16816(sacc[ni], ah, &blf[gi][hf]);
                mma16816(sacc[ni], al, &bhf[gi][hf]);
            }
        }

        unsigned phi[8], plo[8];
        #pragma unroll
        for (int ni = 0; ni < 4; ni++) {
            ushort2 m0 = md[ni][0], m1 = md[ni][1];
            float z0 = (m0.x >= 1024) ? 0.0f : __expf(sacc[ni][0] + sLUT[m0.x & 1023]);
            float z1 = (m0.y >= 1024) ? 0.0f : __expf(sacc[ni][1] + sLUT[m0.y & 1023]);
            float z2 = (m1.x >= 1024) ? 0.0f : __expf(sacc[ni][2] + sLUT[m1.x & 1023]);
            float z3 = (m1.y >= 1024) ? 0.0f : __expf(sacc[ni][3] + sLUT[m1.y & 1023]);
            zs0 += z0 + z1;
            zs8 += z2 + z3;
            unsigned p01 = cvt2bf(z1, z0);
            unsigned p23 = cvt2bf(z3, z2);
            phi[ni*2]   = p01;
            phi[ni*2+1] = p23;
            float f0 = __uint_as_float(p01 << 16), f1 = __uint_as_float(p01 & 0xFFFF0000u);
            float f2 = __uint_as_float(p23 << 16), f3 = __uint_as_float(p23 & 0xFFFF0000u);
            plo[ni*2]   = cvt2bf(z1 - f1, z0 - f0);
            plo[ni*2+1] = cvt2bf(z3 - f3, z2 - f2);
        }

        #pragma unroll
        for (int kf = 0; kf < 2; kf++) {
            unsigned vbh[2][4], vbl[2][4];
            #pragma unroll
            for (int gi = 0; gi < 2; gi++) {
                int nrow = gi*16 + (lane & 7) + ((lane >> 4) & 1) * 8;
                int col = ws*32 + kf*16 + (((lane >> 3) & 1) << 3);
                unsigned bd = smb + AT_VTHI + nrow*144 + col*2;
                ldsm4(vbh[gi], bd);
                ldsm4(vbl[gi], bd + (AT_VTLO - AT_VTHI));
            }
            #pragma unroll
            for (int ni = 0; ni < 4; ni++) {
                int gi = ni >> 1, hf = (ni & 1) * 2;
                mma16816(oacc[ni], &phi[4*kf], &vbh[gi][hf]);
                mma16816(oacc[ni], &plo[4*kf], &vbh[gi][hf]);
                mma16816(oacc[ni], &phi[4*kf], &vbl[gi][hf]);
            }
        }
        __syncthreads();
    }

    zs0 += __shfl_xor_sync(0xffffffffu, zs0, 1);
    zs0 += __shfl_xor_sync(0xffffffffu, zs0, 2);
    zs8 += __shfl_xor_sync(0xffffffffu, zs8, 1);
    zs8 += __shfl_xor_sync(0xffffffffu, zs8, 2);

    float* sO  = (float*)(SM_ + 0);
    float* sRS = (float*)(SM_ + AT_KHI);
    int r = wq*16 + qrow_f;
    if (ws == 1) {
        if ((lane & 3) == 0) {
            sRS[r]     = zs0;
            sRS[r + 8] = zs8;
        }
        #pragma unroll
        for (int ni = 0; ni < 4; ni++) {
            int c = ni*8 + ccol_f;
            *(float2*)&sO[r*34 + c]     = make_float2(oacc[ni][0], oacc[ni][1]);
            *(float2*)&sO[(r+8)*34 + c] = make_float2(oacc[ni][2], oacc[ni][3]);
        }
    }
    __syncthreads();
    if (ws == 0) {
        float inv0 = 1.0f / (zs0 + sRS[r]     + 1e-5f);
        float inv8 = 1.0f / (zs8 + sRS[r + 8] + 1e-5f);
        size_t o0 = ((size_t)b * TT + t0 + r)     * DD + h * 32;
        size_t o8 = ((size_t)b * TT + t0 + r + 8) * DD + h * 32;
        #pragma unroll
        for (int ni = 0; ni < 4; ni++) {
            int c = ni*8 + ccol_f;
            float2 p0 = *(const float2*)&sO[r*34 + c];
            float2 p8 = *(const float2*)&sO[(r+8)*34 + c];
            float v0 = (oacc[ni][0] + p0.x) * inv0;
            float v1 = (oacc[ni][1] + p0.y) * inv0;
            float v2 = (oacc[ni][2] + p8.x) * inv8;
            float v3 = (oacc[ni][3] + p8.y) * inv8;
            unsigned h0 = cvt2bf(v1, v0);
            unsigned h8 = cvt2bf(v3, v2);
            float f0 = __uint_as_float(h0 << 16), f1 = __uint_as_float(h0 & 0xFFFF0000u);
            float f2 = __uint_as_float(h8 << 16), f3 = __uint_as_float(h8 & 0xFFFF0000u);
            *(unsigned*)&g_athi[o0 + c] = h0;
            *(unsigned*)&g_atlo[o0 + c] = cvt2bf(v1 - f1, v0 - f0);
            *(unsigned*)&g_athi[o8 + c] = h8;
            *(unsigned*)&g_atlo[o8 + c] = cvt2bf(v3 - f3, v2 - f2);
        }
    }
}

// ---------------------------------------------------------------------------
// out = LayerNorm(a + b) * g + beta. dosplit: also emit bf16 hi/lo (g_zhi/zlo).
// ---------------------------------------------------------------------------
__global__ __launch_bounds__(256) void ln_kernel(const float* __restrict__ a,
                                                 const float* __restrict__ b,
                                                 const float* __restrict__ g,
                                                 const float* __restrict__ be,
                                                 float* __restrict__ out,
                                                 int dosplit)
{
    int w    = (blockIdx.x * 256 + threadIdx.x) >> 5;
    int lane = threadIdx.x & 31;
    const float* ap = a + (size_t)w * 256;
    const float* bp = b + (size_t)w * 256;
    float v[8]; float s = 0.0f;
    #pragma unroll
    for (int u = 0; u < 8; u++) { v[u] = ap[lane + 32*u] + bp[lane + 32*u]; s += v[u]; }
    #pragma unroll
    for (int off = 16; off; off >>= 1) s += __shfl_xor_sync(0xffffffffu, s, off);
    float mu = s * (1.0f / 256.0f);
    float vs = 0.0f;
    #pragma unroll
    for (int u = 0; u < 8; u++) { float d = v[u] - mu; vs = fmaf(d, d, vs); }
    #pragma unroll
    for (int off = 16; off; off >>= 1) vs += __shfl_xor_sync(0xffffffffu, vs, off);
    float rstd = rsqrtf(vs * (1.0f / 256.0f) + 1e-5f);
    #pragma unroll
    for (int u = 0; u < 8; u++) {
        int col = lane + 32*u;
        float o = (v[u] - mu) * rstd * g[col] + be[col];
        out[(size_t)w * 256 + col] = o;
        if (dosplit) {
            __nv_bfloat16 hh = __float2bfloat16(o);
            g_zhi[(size_t)w * 256 + col] = hh;
            g_zlo[(size_t)w * 256 + col] = __float2bfloat16(o - __bfloat162float(hh));
        }
    }
}

extern "C" void kernel_launch(void* const* d_in, const int* in_sizes, int n_in,
                              void* d_out, int out_size)
{
    const float* x    = (const float*)d_in[0];
    const void*  mask = d_in[1];
    const float* rel  = (const float*)d_in[2];
    const float* pw1  = (const float*)d_in[6];
    const float* pb1  = (const float*)d_in[7];
    const float* pw2  = (const float*)d_in[8];
    const float* pb2  = (const float*)d_in[9];
    const float* bo   = (const float*)d_in[11];
    const float* bfv  = (const float*)d_in[13];
    const float* g1   = (const float*)d_in[14];
    const float* be1  = (const float*)d_in[15];
    const float* g2   = (const float*)d_in[16];
    const float* be2  = (const float*)d_in[17];

    float *qraw, *vraw, *y, *zz;
    __nv_bfloat16 *xhi, *xlo, *athi, *atlo, *zhi, *zlo;
    cudaGetSymbolAddress((void**)&qraw, g_qraw);
    cudaGetSymbolAddress((void**)&vraw, g_vraw);
    cudaGetSymbolAddress((void**)&y,    g_y);
    cudaGetSymbolAddress((void**)&zz,   g_zz);
    cudaGetSymbolAddress((void**)&xhi,  g_xhi);
    cudaGetSymbolAddress((void**)&xlo,  g_xlo);
    cudaGetSymbolAddress((void**)&athi, g_athi);
    cudaGetSymbolAddress((void**)&atlo, g_atlo);
    cudaGetSymbolAddress((void**)&zhi,  g_zhi);
    cudaGetSymbolAddress((void**)&zlo,  g_zlo);

    cudaFuncSetAttribute(tcmma, cudaFuncAttributeMaxDynamicSharedMemorySize, MM_SMEM);

    prep_kernel<<<1, 128>>>(pw1, pb1, pw2, pb2);
    lut_kernel<<<8, 1024>>>();
    detect_kernel<<<256, 256>>>((const unsigned*)mask);
    maskfuse_kernel<<<4096, 256>>>(rel, mask);
    splitw_kernel<<<640, 256>>>((const float*)d_in[3], (const float*)d_in[4],
                                (const float*)d_in[5], (const float*)d_in[10],
                                (const float*)d_in[12]);
    split_kernel<<<2048, 256>>>(x, xhi, xlo);

    // QKV: q,k get fused normalize+split epilogue; v lands fp32 in vraw
    tcmma<<<dim3(32, 4, 3), 256, MM_SMEM>>>(xhi, xlo, 0, nullptr, vraw, vraw, vraw, 0, 1);
    vtrans_kernel<<<dim3(16, 32), 256>>>();

    attn_mma_kernel<<<dim3(16, 32), 256>>>();

    tcmma<<<dim3(32, 4, 1), 256, MM_SMEM>>>(athi, atlo, 3, bo, y, y, y, 0, 0);
    ln_kernel<<<512, 256>>>(x, y, g1, be1, zz, 1);
    tcmma<<<dim3(32, 4, 1), 256, MM_SMEM>>>(zhi, zlo, 4, bfv, qraw, qraw, qraw, 1, 0);
    ln_kernel<<<512, 256>>>(zz, qraw, g2, be2, (float*)d_out, 0);
}

// round 10
// speedup vs baseline: 2.4640x; 1.1005x over previous
#include <cuda_runtime.h>
#include <cuda_bf16.h>

#define BB  4
#define TT  1024
#define DD  256
#define HH  8
#define CC  16
#define BT  (BB*TT)

typedef unsigned long long ull;

__device__ __forceinline__ unsigned smem_u32(const void* p) {
    unsigned a;
    asm("{ .reg .u64 t; cvta.to.shared.u64 t, %1; cvt.u32.u64 %0, t; }" : "=r"(a) : "l"(p));
    return a;
}
__device__ __forceinline__ void ldsm4(unsigned* r, unsigned addr) {
    asm volatile("ldmatrix.sync.aligned.m8n8.x4.shared.b16 {%0,%1,%2,%3}, [%4];"
                 : "=r"(r[0]), "=r"(r[1]), "=r"(r[2]), "=r"(r[3]) : "r"(addr));
}
__device__ __forceinline__ void mma16816(float* c, const unsigned* a, const unsigned* b) {
    asm volatile("mma.sync.aligned.m16n8k16.row.col.f32.bf16.bf16.f32 "
                 "{%0,%1,%2,%3}, {%4,%5,%6,%7}, {%8,%9}, {%0,%1,%2,%3};"
                 : "+f"(c[0]), "+f"(c[1]), "+f"(c[2]), "+f"(c[3])
                 : "r"(a[0]), "r"(a[1]), "r"(a[2]), "r"(a[3]), "r"(b[0]), "r"(b[1]));
}
__device__ __forceinline__ unsigned cvt2bf(float hi, float lo) {
    unsigned r;
    asm("cvt.rn.bf16x2.f32 %0, %1, %2;" : "=r"(r) : "f"(hi), "f"(lo));
    return r;
}

// ---------------- scratch ----------------
__device__ float g_qraw[BT*DD];          // FFN scratch
__device__ float g_vraw[BT*DD];
__device__ float g_y[BT*DD];
__device__ float g_zz[BT*DD];
__device__ unsigned char g_mdx[BB*TT*TT];   // u8: 255=masked, else idx 0..254
__device__ float g_coef[HH*34];
__device__ float g_lutv[HH*256];            // per head: -bias at cell midpoints (255 cells; [255]=0)
__device__ int   g_mask_flags;
__device__ __nv_bfloat16 g_xhi[BT*DD],  g_xlo[BT*DD];
__device__ __nv_bfloat16 g_athi[BT*DD], g_atlo[BT*DD];
__device__ __nv_bfloat16 g_zhi[BT*DD],  g_zlo[BT*DD];
__device__ __nv_bfloat16 g_whi[5*DD*DD], g_wlo[5*DD*DD];
__device__ __nv_bfloat16 g_vthi[32*HH*BB*TT], g_vtlo[32*HH*BB*TT]; // [bh][32][1024]
__device__ __nv_bfloat16 g_qh2[HH*BB*TT*32], g_ql2[HH*BB*TT*32];   // [bh][t][32]
__device__ __nv_bfloat16 g_kh2[HH*BB*TT*32], g_kl2[HH*BB*TT*32];

__global__ void prep_kernel(const float* __restrict__ pw1, const float* __restrict__ pb1,
                            const float* __restrict__ pw2, const float* __restrict__ pb2)
{
    if (threadIdx.x == 0) g_mask_flags = 0;
    int h = threadIdx.x >> 4;
    int c = threadIdx.x & 15;
    if (h >= HH) return;
    float w1 = pw1[h*CC + c], b1 = pb1[h*CC + c], w2 = pw2[h*CC + c];
    float beta, delta, k0add, k1add;
    if (w1 != 0.0f) {
        beta  = 0.495f * w2 * fabsf(w1);
        delta = -b1 / w1;
        k0add = 0.505f * w2 * b1;
        k1add = 0.505f * w2 * w1;
    } else {
        beta = 0.0f; delta = 0.0f;
        k0add = w2 * (0.505f * b1 + 0.495f * fabsf(b1));
        k1add = 0.0f;
    }
    #pragma unroll
    for (int off = 1; off < 16; off <<= 1) {
        k0add += __shfl_xor_sync(0xffffffffu, k0add, off);
        k1add += __shfl_xor_sync(0xffffffffu, k1add, off);
    }
    g_coef[h*34 + 2  + c] = beta;
    g_coef[h*34 + 18 + c] = delta;
    if (c == 0) {
        g_coef[h*34 + 0] = pb2[h] + k0add;
        g_coef[h*34 + 1] = k1add;
    }
}

// 255-cell LUT of -bias at midpoints; entry 255 = 0 (masked gathers are discarded).
__global__ void lut_kernel()
{
    int h = blockIdx.x, cell = threadIdx.x;
    if (cell == 255) { g_lutv[h*256 + 255] = 0.0f; return; }
    float m = (cell + 0.5f) * (1.0f / 255.0f);
    float v = g_coef[h*34 + 0] + g_coef[h*34 + 1] * m;
    #pragma unroll
    for (int c = 0; c < 16; c++) {
        float be = g_coef[h*34 + 2 + c], de = g_coef[h*34 + 18 + c];
        v += be * fabsf(m - de);
    }
    g_lutv[h*256 + cell] = -v;
}

__global__ void detect_kernel(const unsigned* __restrict__ w)
{
    int i = blockIdx.x * blockDim.x + threadIdx.x;
    unsigned x = w[i];
    int f = 0;
    if (x == 0x3F800000u)               f = 2;
    else if ((x & 0xFFFFu) == 0x3F80u)  f = 4;
    else if (x > 1u)                    f = 1;
    if (f) atomicOr(&g_mask_flags, f);
}

__global__ __launch_bounds__(256) void maskfuse_kernel(const float* __restrict__ rd,
                                                       const void* __restrict__ maskp)
{
    int i = blockIdx.x * 256 + threadIdx.x;
    size_t base = (size_t)i * 4;
    int mf = g_mask_flags;
    int mode = (mf & 4) ? 3 : (mf & 2) ? 2 : (mf & 1) ? 1 : 0;
    float4 d4 = *(const float4*)&rd[base];
    int m0, m1, m2, m3;
    if (mode == 0) {
        int4 m = *(const int4*)((const int*)maskp + base);
        m0 = m.x != 0; m1 = m.y != 0; m2 = m.z != 0; m3 = m.w != 0;
    } else if (mode == 1) {
        uchar4 m = *(const uchar4*)((const unsigned char*)maskp + base);
        m0 = m.x != 0; m1 = m.y != 0; m2 = m.z != 0; m3 = m.w != 0;
    } else if (mode == 2) {
        float4 m = *(const float4*)((const float*)maskp + base);
        m0 = m.x != 0.0f; m1 = m.y != 0.0f; m2 = m.z != 0.0f; m3 = m.w != 0.0f;
    } else {
        ushort4 m = *(const ushort4*)((const unsigned short*)maskp + base);
        m0 = m.x != 0; m1 = m.y != 0; m2 = m.z != 0; m3 = m.w != 0;
    }
    int i0 = min(max(__float2int_rd(d4.x * 255.0f), 0), 254);
    int i1 = min(max(__float2int_rd(d4.y * 255.0f), 0), 254);
    int i2 = min(max(__float2int_rd(d4.z * 255.0f), 0), 254);
    int i3 = min(max(__float2int_rd(d4.w * 255.0f), 0), 254);
    uchar4 o;
    o.x = (unsigned char)(m0 ? 255 : i0);
    o.y = (unsigned char)(m1 ? 255 : i1);
    o.z = (unsigned char)(m2 ? 255 : i2);
    o.w = (unsigned char)(m3 ? 255 : i3);
    *(uchar4*)&g_mdx[base] = o;
}

__global__ __launch_bounds__(256) void split_kernel(const float* __restrict__ src,
                                                    __nv_bfloat16* __restrict__ hi,
                                                    __nv_bfloat16* __restrict__ lo)
{
    int i = blockIdx.x * 256 + threadIdx.x;
    float2 v = *(const float2*)&src[(size_t)i * 2];
    __nv_bfloat16 hx = __float2bfloat16(v.x), hy = __float2bfloat16(v.y);
    __nv_bfloat162 h2; h2.x = hx; h2.y = hy;
    __nv_bfloat162 l2;
    l2.x = __float2bfloat16(v.x - __bfloat162float(hx));
    l2.y = __float2bfloat16(v.y - __bfloat162float(hy));
    *(__nv_bfloat162*)&hi[(size_t)i * 2] = h2;
    *(__nv_bfloat162*)&lo[(size_t)i * 2] = l2;
}

__global__ __launch_bounds__(256) void splitw_kernel(const float* __restrict__ w0,
                                                     const float* __restrict__ w1,
                                                     const float* __restrict__ w2,
                                                     const float* __restrict__ w3,
                                                     const float* __restrict__ w4)
{
    int i = blockIdx.x * 256 + threadIdx.x;
    size_t e = (size_t)i * 2;
    int w = (int)(e >> 16);
    size_t off = e & 65535;
    const float* src = (w == 0) ? w0 : (w == 1) ? w1 : (w == 2) ? w2 : (w == 3) ? w3 : w4;
    float2 v = *(const float2*)&src[off];
    __nv_bfloat16 hx = __float2bfloat16(v.x), hy = __float2bfloat16(v.y);
    __nv_bfloat162 h2; h2.x = hx; h2.y = hy;
    __nv_bfloat162 l2;
    l2.x = __float2bfloat16(v.x - __bfloat162float(hx));
    l2.y = __float2bfloat16(v.y - __bfloat162float(hy));
    *(__nv_bfloat162*)&g_whi[e] = h2;
    *(__nv_bfloat162*)&g_wlo[e] = l2;
}

// ---------------------------------------------------------------------------
// HMMA GEMM (bf16x3) - unchanged structure; qkv=1,z<2 -> fused norm+split.
// ---------------------------------------------------------------------------
#define MM_AHI 0
#define MM_ALO 18432
#define MM_WHI 36864
#define MM_WLO 46080
#define MM_SMEM 55296

__global__ __launch_bounds__(256) void tcmma(const __nv_bfloat16* __restrict__ Ahi,
                                             const __nv_bfloat16* __restrict__ Alo,
                                             int widx0,
                                             const float* __restrict__ bias,
                                             float* __restrict__ C0,
                                             float* __restrict__ C1,
                                             float* __restrict__ C2,
                                             int act, int qkv)
{
    extern __shared__ char sm[];
    unsigned smb = smem_u32(sm);
    int tid = threadIdx.x;
    int lane = tid & 31;
    int wid = tid >> 5;
    int wm = wid & 3;
    int wn = wid >> 2;
    int m0 = blockIdx.x * 128, n0 = blockIdx.y * 64;
    int z = blockIdx.z;
    const __nv_bfloat16* Whi = g_whi + (size_t)(widx0 + z) * (DD*DD);
    const __nv_bfloat16* Wlo = g_wlo + (size_t)(widx0 + z) * (DD*DD);
    float* C = (z == 0) ? C0 : (z == 1) ? C1 : C2;

    float acc[2][4][4];
    #pragma unroll
    for (int a = 0; a < 2; a++)
        #pragma unroll
        for (int b = 0; b < 4; b++)
            #pragma unroll
            for (int c = 0; c < 4; c++) acc[a][b][c] = 0.0f;

    for (int kc = 0; kc < 4; kc++) {
        #pragma unroll
        for (int it = 0; it < 4; it++) {
            int v = tid + it * 256;
            int row = v >> 3, cg = (v & 7) * 8;
            size_t gofs = (size_t)(m0 + row) * 256 + kc * 64 + cg;
            *(uint4*)(sm + MM_AHI + row*144 + cg*2) = *(const uint4*)&Ahi[gofs];
            *(uint4*)(sm + MM_ALO + row*144 + cg*2) = *(const uint4*)&Alo[gofs];
        }
        #pragma unroll
        for (int it = 0; it < 2; it++) {
            int v = tid + it * 256;
            int row = v >> 3, cg = (v & 7) * 8;
            size_t gofs = (size_t)(n0 + row) * 256 + kc * 64 + cg;
            *(uint4*)(sm + MM_WHI + row*144 + cg*2) = *(const uint4*)&Whi[gofs];
            *(uint4*)(sm + MM_WLO + row*144 + cg*2) = *(const uint4*)&Wlo[gofs];
        }
        __syncthreads();

        #pragma unroll
        for (int ks = 0; ks < 4; ks++) {
            int kb = ks * 16;
            unsigned ah[2][4], al[2][4], bh[2][4], bl[2][4];
            #pragma unroll
            for (int mi = 0; mi < 2; mi++) {
                int row = wm*32 + mi*16 + (lane & 15);
                unsigned ad = smb + MM_AHI + row*144 + (kb + ((lane >> 4) << 3)) * 2;
                ldsm4(ah[mi], ad);
                ldsm4(al[mi], ad + (MM_ALO - MM_AHI));
            }
            #pragma unroll
            for (int gi = 0; gi < 2; gi++) {
                int nrow = wn*32 + gi*16 + (lane & 7) + ((lane >> 4) & 1) * 8;
                unsigned bd = smb + MM_WHI + nrow*144 + (kb + (((lane >> 3) & 1) << 3)) * 2;
                ldsm4(bh[gi], bd);
                ldsm4(bl[gi], bd + (MM_WLO - MM_WHI));
            }
            #pragma unroll
            for (int mi = 0; mi < 2; mi++) {
                #pragma unroll
                for (int ni = 0; ni < 4; ni++) {
                    int gi = ni >> 1, hf = (ni & 1) * 2;
                    mma16816(acc[mi][ni], ah[mi], &bh[gi][hf]);
                    mma16816(acc[mi][ni], ah[mi], &bl[gi][hf]);
                    mma16816(acc[mi][ni], al[mi], &bh[gi][hf]);
                }
            }
        }
        __syncthreads();
    }

    if (qkv && z != 2) {
        __nv_bfloat16* dsthi = (z == 0) ? g_qh2 : g_kh2;
        __nv_bfloat16* dstlo = (z == 0) ? g_ql2 : g_kl2;
        int head = blockIdx.y * 2 + wn;
        #pragma unroll
        for (int mi = 0; mi < 2; mi++) {
            #pragma unroll
            for (int rr = 0; rr < 2; rr++) {
                float v[8];
                #pragma unroll
                for (int ni = 0; ni < 4; ni++) {
                    v[ni*2]   = acc[mi][ni][rr*2];
                    v[ni*2+1] = acc[mi][ni][rr*2+1];
                }
                float ss = 0.0f;
                #pragma unroll
                for (int j = 0; j < 8; j++) ss = fmaf(v[j], v[j], ss);
                ss += __shfl_xor_sync(0xffffffffu, ss, 1);
                ss += __shfl_xor_sync(0xffffffffu, ss, 2);
                float inv = 1.0f / fmaxf(sqrtf(ss), 1e-12f);
                int row = m0 + wm*32 + mi*16 + rr*8 + (lane >> 2);
                int b = row >> 10, t = row & 1023;
                size_t base = (((size_t)(b*8 + head)) * 1024 + t) * 32 + (lane & 3) * 2;
                #pragma unroll
                for (int ni = 0; ni < 4; ni++) {
                    float v0 = v[ni*2] * inv, v1 = v[ni*2+1] * inv;
                    unsigned hh = cvt2bf(v1, v0);
                    float f0 = __uint_as_float(hh << 16), f1 = __uint_as_float(hh & 0xFFFF0000u);
                    *(unsigned*)&dsthi[base + ni*8] = hh;
                    *(unsigned*)&dstlo[base + ni*8] = cvt2bf(v1 - f1, v0 - f0);
                }
            }
        }
        return;
    }

    int rbase = m0 + wm*32 + (lane >> 2);
    int cbase = n0 + wn*32 + (lane & 3) * 2;
    #pragma unroll
    for (int mi = 0; mi < 2; mi++) {
        #pragma unroll
        for (int ni = 0; ni < 4; ni++) {
            int col = cbase + ni*8;
            float b0 = bias ? bias[col] : 0.0f;
            float b1 = bias ? bias[col + 1] : 0.0f;
            float v0 = acc[mi][ni][0] + b0;
            float v1 = acc[mi][ni][1] + b1;
            float v2 = acc[mi][ni][2] + b0;
            float v3 = acc[mi][ni][3] + b1;
            if (act) {
                v0 = (v0 >= 0.0f) ? v0 : 0.01f * v0;
                v1 = (v1 >= 0.0f) ? v1 : 0.01f * v1;
                v2 = (v2 >= 0.0f) ? v2 : 0.01f * v2;
                v3 = (v3 >= 0.0f) ? v3 : 0.01f * v3;
            }
            int row = rbase + mi*16;
            *(float2*)&C[(size_t)row * 256 + col]       = make_float2(v0, v1);
            *(float2*)&C[(size_t)(row + 8) * 256 + col] = make_float2(v2, v3);
        }
    }
}

// ---------------------------------------------------------------------------
// V transpose + split (unchanged)
// ---------------------------------------------------------------------------
__global__ __launch_bounds__(256) void vtrans_kernel()
{
    __shared__ float sT[32*72];
    int tid = threadIdx.x;
    int bh = blockIdx.y, b = bh >> 3, h = bh & 7;
    int t0 = blockIdx.x << 6;
    {
        int row = tid >> 2, cg = (tid & 3) * 8;
        const float* src = &g_vraw[((size_t)(b*1024) + t0 + row) * 256 + h * 32 + cg];
        float4 a = *(const float4*)src;
        float4 c = *(const float4*)(src + 4);
        sT[(cg+0)*72 + row] = a.x; sT[(cg+1)*72 + row] = a.y;
        sT[(cg+2)*72 + row] = a.z; sT[(cg+3)*72 + row] = a.w;
        sT[(cg+4)*72 + row] = c.x; sT[(cg+5)*72 + row] = c.y;
        sT[(cg+6)*72 + row] = c.z; sT[(cg+7)*72 + row] = c.w;
    }
    __syncthreads();
    {
        int c = tid >> 3, sg = (tid & 7) * 8;
        float v[8];
        #pragma unroll
        for (int j = 0; j < 8; j++) v[j] = sT[c*72 + sg + j];
        unsigned hp[4], lp[4];
        #pragma unroll
        for (int j = 0; j < 4; j++) {
            unsigned hh = cvt2bf(v[2*j+1], v[2*j]);
            float f0 = __uint_as_float(hh << 16);
            float f1 = __uint_as_float(hh & 0xFFFF0000u);
            hp[j] = hh;
            lp[j] = cvt2bf(v[2*j+1] - f1, v[2*j] - f0);
        }
        size_t o = ((size_t)bh * 32 + c) * 1024 + t0 + sg;
        *(uint4*)&g_vthi[o] = make_uint4(hp[0], hp[1], hp[2], hp[3]);
        *(uint4*)&g_vtlo[o] = make_uint4(lp[0], lp[1], lp[2], lp[3]);
    }
}

// ---------------------------------------------------------------------------
// HMMA attention, 128 q rows per CTA. 8 warps = 4(q, 32 rows each) x 2(s-half).
// smem (bytes): QHI 0 (128x80=10240) | QLO 10240 | KHI 20480 (5120) | KLO 25600
//               VTHI 30720 (4608) | VTLO 35328 | LUT 39936 (1024)  -> 40960
// post-loop: sO f32[128][34] at 0 (17408), sRS f32[128] at 18432.
// ---------------------------------------------------------------------------
#define AT_QHI 0
#define AT_QLO 10240
#define AT_KHI 20480
#define AT_KLO 25600
#define AT_VTHI 30720
#define AT_VTLO 35328
#define AT_LUT 39936

__global__ __launch_bounds__(256) void attn_mma_kernel()
{
    __shared__ __align__(16) char SM_[40960];
    unsigned smb = smem_u32(SM_);
    float* sLUT = (float*)(SM_ + AT_LUT);

    int tid = threadIdx.x;
    int lane = tid & 31;
    int wid = tid >> 5;
    int wq = wid & 3;
    int ws = wid >> 2;
    int bh = blockIdx.y, b = bh >> 3, h = bh & 7;
    int t0 = blockIdx.x << 7;

    if (tid < 256) sLUT[tid] = g_lutv[h*256 + tid];
    #pragma unroll
    for (int r2 = 0; r2 < 2; r2++) {
        int row = (tid >> 2) + r2*64, cg = (tid & 3) * 8;
        size_t gofs = (((size_t)bh * TT) + t0 + row) * 32 + cg;
        *(uint4*)(SM_ + AT_QHI + row*80 + cg*2) = *(const uint4*)&g_qh2[gofs];
        *(uint4*)(SM_ + AT_QLO + row*80 + cg*2) = *(const uint4*)&g_ql2[gofs];
    }
    __syncthreads();

    float oacc[2][4][4];
    #pragma unroll
    for (int mi = 0; mi < 2; mi++)
        #pragma unroll
        for (int i = 0; i < 4; i++)
            #pragma unroll
            for (int j = 0; j < 4; j++) oacc[mi][i][j] = 0.0f;
    float zs[2][2] = {{0.f,0.f},{0.f,0.f}};

    int qrow_f = (lane >> 2);
    int ccol_f = (lane & 3) * 2;

    #pragma unroll 1
    for (int st = 0; st < 16; st++) {
        int s0 = st << 6;
        uchar2 md[2][4][2];
        {
            size_t mb = (size_t)b * TT * TT;
            int gcb = s0 + ws*32 + ccol_f;
            #pragma unroll
            for (int mi = 0; mi < 2; mi++) {
                int gr = t0 + wq*32 + mi*16 + qrow_f;
                #pragma unroll
                for (int ni = 0; ni < 4; ni++) {
                    md[mi][ni][0] = *(const uchar2*)&g_mdx[mb + (size_t)gr * TT + gcb + ni*8];
                    md[mi][ni][1] = *(const uchar2*)&g_mdx[mb + (size_t)(gr+8) * TT + gcb + ni*8];
                }
            }
        }
        {
            int row = tid >> 2, cg = (tid & 3) * 8;
            size_t gofs = (((size_t)bh * TT) + s0 + row) * 32 + cg;
            *(uint4*)(SM_ + AT_KHI + row*80 + cg*2) = *(const uint4*)&g_kh2[gofs];
            *(uint4*)(SM_ + AT_KLO + row*80 + cg*2) = *(const uint4*)&g_kl2[gofs];
        }
        {
            int c = tid >> 3, sg = (tid & 7) * 8;
            size_t gofs = ((size_t)bh * 32 + c) * 1024 + s0 + sg;
            *(uint4*)(SM_ + AT_VTHI + c*144 + sg*2) = *(const uint4*)&g_vthi[gofs];
            *(uint4*)(SM_ + AT_VTLO + c*144 + sg*2) = *(const uint4*)&g_vtlo[gofs];
        }
        __syncthreads();

        // ---- QK for both 16-row fragments ----
        float sacc[2][4][4];
        #pragma unroll
        for (int mi = 0; mi < 2; mi++)
            #pragma unroll
            for (int i = 0; i < 4; i++)
                #pragma unroll
                for (int j = 0; j < 4; j++) sacc[mi][i][j] = 0.0f;

        #pragma unroll
        for (int ks = 0; ks < 2; ks++) {
            int kb = ks * 16;
            unsigned ah[2][4], al[2][4], bhf[2][4], blf[2][4];
            #pragma unroll
            for (int mi = 0; mi < 2; mi++) {
                int row = wq*32 + mi*16 + (lane & 15);
                unsigned ad = smb + AT_QHI + row*80 + (kb + ((lane >> 4) << 3)) * 2;
                ldsm4(ah[mi], ad);
                ldsm4(al[mi], ad + (AT_QLO - AT_QHI));
            }
            #pragma unroll
            for (int gi = 0; gi < 2; gi++) {
                int nrow = ws*32 + gi*16 + (lane & 7) + ((lane >> 4) & 1) * 8;
                unsigned bd = smb + AT_KHI + nrow*80 + (kb + (((lane >> 3) & 1) << 3)) * 2;
                ldsm4(bhf[gi], bd);
                ldsm4(blf[gi], bd + (AT_KLO - AT_KHI));
            }
            #pragma unroll
            for (int mi = 0; mi < 2; mi++) {
                #pragma unroll
                for (int ni = 0; ni < 4; ni++) {
                    int gi = ni >> 1, hf = (ni & 1) * 2;
                    mma16816(sacc[mi][ni], ah[mi], &bhf[gi][hf]);
                    mma16816(sacc[mi][ni], ah[mi], &blf[gi][hf]);
                    mma16816(sacc[mi][ni], al[mi], &bhf[gi][hf]);
                }
            }
        }

        // ---- bias + exp + pack P hi/lo (per mi) ----
        unsigned phi[2][8], plo[2][8];
        #pragma unroll
        for (int mi = 0; mi < 2; mi++) {
            #pragma unroll
            for (int ni = 0; ni < 4; ni++) {
                uchar2 m0 = md[mi][ni][0], m1 = md[mi][ni][1];
                float z0 = (m0.x == 255) ? 0.0f : __expf(sacc[mi][ni][0] + sLUT[m0.x]);
                float z1 = (m0.y == 255) ? 0.0f : __expf(sacc[mi][ni][1] + sLUT[m0.y]);
                float z2 = (m1.x == 255) ? 0.0f : __expf(sacc[mi][ni][2] + sLUT[m1.x]);
                float z3 = (m1.y == 255) ? 0.0f : __expf(sacc[mi][ni][3] + sLUT[m1.y]);
                zs[mi][0] += z0 + z1;
                zs[mi][1] += z2 + z3;
                unsigned p01 = cvt2bf(z1, z0);
                unsigned p23 = cvt2bf(z3, z2);
                phi[mi][ni*2]   = p01;
                phi[mi][ni*2+1] = p23;
                float f0 = __uint_as_float(p01 << 16), f1 = __uint_as_float(p01 & 0xFFFF0000u);
                float f2 = __uint_as_float(p23 << 16), f3 = __uint_as_float(p23 & 0xFFFF0000u);
                plo[mi][ni*2]   = cvt2bf(z1 - f1, z0 - f0);
                plo[mi][ni*2+1] = cvt2bf(z3 - f3, z2 - f2);
            }
        }

        // ---- PV (V fragments shared across mi) ----
        #pragma unroll
        for (int kf = 0; kf < 2; kf++) {
            unsigned vbh[2][4], vbl[2][4];
            #pragma unroll
            for (int gi = 0; gi < 2; gi++) {
                int nrow = gi*16 + (lane & 7) + ((lane >> 4) & 1) * 8;
                int col = ws*32 + kf*16 + (((lane >> 3) & 1) << 3);
                unsigned bd = smb + AT_VTHI + nrow*144 + col*2;
                ldsm4(vbh[gi], bd);
                ldsm4(vbl[gi], bd + (AT_VTLO - AT_VTHI));
            }
            #pragma unroll
            for (int mi = 0; mi < 2; mi++) {
                #pragma unroll
                for (int ni = 0; ni < 4; ni++) {
                    int gi = ni >> 1, hf = (ni & 1) * 2;
                    mma16816(oacc[mi][ni], &phi[mi][4*kf], &vbh[gi][hf]);
                    mma16816(oacc[mi][ni], &plo[mi][4*kf], &vbh[gi][hf]);
                    mma16816(oacc[mi][ni], &phi[mi][4*kf], &vbl[gi][hf]);
                }
            }
        }
        __syncthreads();
    }

    #pragma unroll
    for (int mi = 0; mi < 2; mi++) {
        zs[mi][0] += __shfl_xor_sync(0xffffffffu, zs[mi][0], 1);
        zs[mi][0] += __shfl_xor_sync(0xffffffffu, zs[mi][0], 2);
        zs[mi][1] += __shfl_xor_sync(0xffffffffu, zs[mi][1], 1);
        zs[mi][1] += __shfl_xor_sync(0xffffffffu, zs[mi][1], 2);
    }

    float* sO  = (float*)(SM_ + 0);        // [128][34]
    float* sRS = (float*)(SM_ + 18432);    // [128]
    if (ws == 1) {
        #pragma unroll
        for (int mi = 0; mi < 2; mi++) {
            int r = wq*32 + mi*16 + qrow_f;
            if ((lane & 3) == 0) {
                sRS[r]     = zs[mi][0];
                sRS[r + 8] = zs[mi][1];
            }
            #pragma unroll
            for (int ni = 0; ni < 4; ni++) {
                int c = ni*8 + ccol_f;
                *(float2*)&sO[r*34 + c]     = make_float2(oacc[mi][ni][0], oacc[mi][ni][1]);
                *(float2*)&sO[(r+8)*34 + c] = make_float2(oacc[mi][ni][2], oacc[mi][ni][3]);
            }
        }
    }
    __syncthreads();
    if (ws == 0) {
        #pragma unroll
        for (int mi = 0; mi < 2; mi++) {
            int r = wq*32 + mi*16 + qrow_f;
            float inv0 = 1.0f / (zs[mi][0] + sRS[r]     + 1e-5f);
            float inv8 = 1.0f / (zs[mi][1] + sRS[r + 8] + 1e-5f);
            size_t o0 = ((size_t)b * TT + t0 + r)     * DD + h * 32;
            size_t o8 = ((size_t)b * TT + t0 + r + 8) * DD + h * 32;
            #pragma unroll
            for (int ni = 0; ni < 4; ni++) {
                int c = ni*8 + ccol_f;
                float2 p0 = *(const float2*)&sO[r*34 + c];
                float2 p8 = *(const float2*)&sO[(r+8)*34 + c];
                float v0 = (oacc[mi][ni][0] + p0.x) * inv0;
                float v1 = (oacc[mi][ni][1] + p0.y) * inv0;
                float v2 = (oacc[mi][ni][2] + p8.x) * inv8;
                float v3 = (oacc[mi][ni][3] + p8.y) * inv8;
                unsigned h0 = cvt2bf(v1, v0);
                unsigned h8 = cvt2bf(v3, v2);
                float f0 = __uint_as_float(h0 << 16), f1 = __uint_as_float(h0 & 0xFFFF0000u);
                float f2 = __uint_as_float(h8 << 16), f3 = __uint_as_float(h8 & 0xFFFF0000u);
                *(unsigned*)&g_athi[o0 + c] = h0;
                *(unsigned*)&g_atlo[o0 + c] = cvt2bf(v1 - f1, v0 - f0);
                *(unsigned*)&g_athi[o8 + c] = h8;
                *(unsigned*)&g_atlo[o8 + c] = cvt2bf(v3 - f3, v2 - f2);
            }
        }
    }
}

__global__ __launch_bounds__(256) void ln_kernel(const float* __restrict__ a,
                                                 const float* __restrict__ b,
                                                 const float* __restrict__ g,
                                                 const float* __restrict__ be,
                                                 float* __restrict__ out,
                                                 int dosplit)
{
    int w    = (blockIdx.x * 256 + threadIdx.x) >> 5;
    int lane = threadIdx.x & 31;
    const float* ap = a + (size_t)w * 256;
    const float* bp = b + (size_t)w * 256;
    float v[8]; float s = 0.0f;
    #pragma unroll
    for (int u = 0; u < 8; u++) { v[u] = ap[lane + 32*u] + bp[lane + 32*u]; s += v[u]; }
    #pragma unroll
    for (int off = 16; off; off >>= 1) s += __shfl_xor_sync(0xffffffffu, s, off);
    float mu = s * (1.0f / 256.0f);
    float vs = 0.0f;
    #pragma unroll
    for (int u = 0; u < 8; u++) { float d = v[u] - mu; vs = fmaf(d, d, vs); }
    #pragma unroll
    for (int off = 16; off; off >>= 1) vs += __shfl_xor_sync(0xffffffffu, vs, off);
    float rstd = rsqrtf(vs * (1.0f / 256.0f) + 1e-5f);
    #pragma unroll
    for (int u = 0; u < 8; u++) {
        int col = lane + 32*u;
        float o = (v[u] - mu) * rstd * g[col] + be[col];
        out[(size_t)w * 256 + col] = o;
        if (dosplit) {
            __nv_bfloat16 hh = __float2bfloat16(o);
            g_zhi[(size_t)w * 256 + col] = hh;
            g_zlo[(size_t)w * 256 + col] = __float2bfloat16(o - __bfloat162float(hh));
        }
    }
}

extern "C" void kernel_launch(void* const* d_in, const int* in_sizes, int n_in,
                              void* d_out, int out_size)
{
    const float* x    = (const float*)d_in[0];
    const void*  mask = d_in[1];
    const float* rel  = (const float*)d_in[2];
    const float* pw1  = (const float*)d_in[6];
    const float* pb1  = (const float*)d_in[7];
    const float* pw2  = (const float*)d_in[8];
    const float* pb2  = (const float*)d_in[9];
    const float* bo   = (const float*)d_in[11];
    const float* bfv  = (const float*)d_in[13];
    const float* g1   = (const float*)d_in[14];
    const float* be1  = (const float*)d_in[15];
    const float* g2   = (const float*)d_in[16];
    const float* be2  = (const float*)d_in[17];

    float *qraw, *vraw, *y, *zz;
    __nv_bfloat16 *xhi, *xlo, *athi, *atlo, *zhi, *zlo;
    cudaGetSymbolAddress((void**)&qraw, g_qraw);
    cudaGetSymbolAddress((void**)&vraw, g_vraw);
    cudaGetSymbolAddress((void**)&y,    g_y);
    cudaGetSymbolAddress((void**)&zz,   g_zz);
    cudaGetSymbolAddress((void**)&xhi,  g_xhi);
    cudaGetSymbolAddress((void**)&xlo,  g_xlo);
    cudaGetSymbolAddress((void**)&athi, g_athi);
    cudaGetSymbolAddress((void**)&atlo, g_atlo);
    cudaGetSymbolAddress((void**)&zhi,  g_zhi);
    cudaGetSymbolAddress((void**)&zlo,  g_zlo);

    cudaFuncSetAttribute(tcmma, cudaFuncAttributeMaxDynamicSharedMemorySize, MM_SMEM);

    prep_kernel<<<1, 128>>>(pw1, pb1, pw2, pb2);
    lut_kernel<<<8, 256>>>();
    detect_kernel<<<256, 256>>>((const unsigned*)mask);
    maskfuse_kernel<<<4096, 256>>>(rel, mask);
    splitw_kernel<<<640, 256>>>((const float*)d_in[3], (const float*)d_in[4],
                                (const float*)d_in[5], (const float*)d_in[10],
                                (const float*)d_in[12]);
    split_kernel<<<2048, 256>>>(x, xhi, xlo);

    tcmma<<<dim3(32, 4, 3), 256, MM_SMEM>>>(xhi, xlo, 0, nullptr, vraw, vraw, vraw, 0, 1);
    vtrans_kernel<<<dim3(16, 32), 256>>>();

    attn_mma_kernel<<<dim3(8, 32), 256>>>();

    tcmma<<<dim3(32, 4, 1), 256, MM_SMEM>>>(athi, atlo, 3, bo, y, y, y, 0, 0);
    ln_kernel<<<512, 256>>>(x, y, g1, be1, zz, 1);
    tcmma<<<dim3(32, 4, 1), 256, MM_SMEM>>>(zhi, zlo, 4, bfv, qraw, qraw, qraw, 1, 0);
    ln_kernel<<<512, 256>>>(zz, qraw, g2, be2, (float*)d_out, 0);
}

// round 11
// speedup vs baseline: 2.5327x; 1.0279x over previous
#include <cuda_runtime.h>
#include <cuda_bf16.h>

#define BB  4
#define TT  1024
#define DD  256
#define HH  8
#define CC  16
#define BT  (BB*TT)

typedef unsigned long long ull;

__device__ __forceinline__ unsigned smem_u32(const void* p) {
    unsigned a;
    asm("{ .reg .u64 t; cvta.to.shared.u64 t, %1; cvt.u32.u64 %0, t; }" : "=r"(a) : "l"(p));
    return a;
}
__device__ __forceinline__ void ldsm4(unsigned* r, unsigned addr) {
    asm volatile("ldmatrix.sync.aligned.m8n8.x4.shared.b16 {%0,%1,%2,%3}, [%4];"
                 : "=r"(r[0]), "=r"(r[1]), "=r"(r[2]), "=r"(r[3]) : "r"(addr));
}
__device__ __forceinline__ void mma16816(float* c, const unsigned* a, const unsigned* b) {
    asm volatile("mma.sync.aligned.m16n8k16.row.col.f32.bf16.bf16.f32 "
                 "{%0,%1,%2,%3}, {%4,%5,%6,%7}, {%8,%9}, {%0,%1,%2,%3};"
                 : "+f"(c[0]), "+f"(c[1]), "+f"(c[2]), "+f"(c[3])
                 : "r"(a[0]), "r"(a[1]), "r"(a[2]), "r"(a[3]), "r"(b[0]), "r"(b[1]));
}
__device__ __forceinline__ unsigned cvt2bf(float hi, float lo) {
    unsigned r;
    asm("cvt.rn.bf16x2.f32 %0, %1, %2;" : "=r"(r) : "f"(hi), "f"(lo));
    return r;
}
__device__ __forceinline__ void cpa16(unsigned dst, const void* src) {
    asm volatile("cp.async.cg.shared.global [%0], [%1], 16;" :: "r"(dst), "l"(src));
}
#define CPA_COMMIT() asm volatile("cp.async.commit_group;" ::: "memory")
#define CPA_WAIT0()  asm volatile("cp.async.wait_group 0;" ::: "memory")

// ---------------- scratch ----------------
__device__ float g_qraw[BT*DD];          // FFN scratch
__device__ float g_vraw[BT*DD];
__device__ float g_y[BT*DD];
__device__ float g_zz[BT*DD];
__device__ unsigned char g_mdx[BB*TT*TT];   // u8: 255=masked, else idx 0..254
__device__ float g_coef[HH*34];
__device__ float g_lutv[HH*256];
__device__ int   g_mask_flags;
__device__ __nv_bfloat16 g_xhi[BT*DD],  g_xlo[BT*DD];
__device__ __nv_bfloat16 g_athi[BT*DD], g_atlo[BT*DD];
__device__ __nv_bfloat16 g_zhi[BT*DD],  g_zlo[BT*DD];
__device__ __nv_bfloat16 g_whi[5*DD*DD], g_wlo[5*DD*DD];
__device__ __nv_bfloat16 g_vthi[32*HH*BB*TT], g_vtlo[32*HH*BB*TT]; // [bh][32][1024]
__device__ __nv_bfloat16 g_qh2[HH*BB*TT*32], g_ql2[HH*BB*TT*32];   // [bh][t][32]
__device__ __nv_bfloat16 g_kh2[HH*BB*TT*32], g_kl2[HH*BB*TT*32];

__global__ void prep_kernel(const float* __restrict__ pw1, const float* __restrict__ pb1,
                            const float* __restrict__ pw2, const float* __restrict__ pb2)
{
    if (threadIdx.x == 0) g_mask_flags = 0;
    int h = threadIdx.x >> 4;
    int c = threadIdx.x & 15;
    if (h >= HH) return;
    float w1 = pw1[h*CC + c], b1 = pb1[h*CC + c], w2 = pw2[h*CC + c];
    float beta, delta, k0add, k1add;
    if (w1 != 0.0f) {
        beta  = 0.495f * w2 * fabsf(w1);
        delta = -b1 / w1;
        k0add = 0.505f * w2 * b1;
        k1add = 0.505f * w2 * w1;
    } else {
        beta = 0.0f; delta = 0.0f;
        k0add = w2 * (0.505f * b1 + 0.495f * fabsf(b1));
        k1add = 0.0f;
    }
    #pragma unroll
    for (int off = 1; off < 16; off <<= 1) {
        k0add += __shfl_xor_sync(0xffffffffu, k0add, off);
        k1add += __shfl_xor_sync(0xffffffffu, k1add, off);
    }
    g_coef[h*34 + 2  + c] = beta;
    g_coef[h*34 + 18 + c] = delta;
    if (c == 0) {
        g_coef[h*34 + 0] = pb2[h] + k0add;
        g_coef[h*34 + 1] = k1add;
    }
}

__global__ void lut_kernel()
{
    int h = blockIdx.x, cell = threadIdx.x;
    if (cell == 255) { g_lutv[h*256 + 255] = 0.0f; return; }
    float m = (cell + 0.5f) * (1.0f / 255.0f);
    float v = g_coef[h*34 + 0] + g_coef[h*34 + 1] * m;
    #pragma unroll
    for (int c = 0; c < 16; c++) {
        float be = g_coef[h*34 + 2 + c], de = g_coef[h*34 + 18 + c];
        v += be * fabsf(m - de);
    }
    g_lutv[h*256 + cell] = -v;
}

__global__ void detect_kernel(const unsigned* __restrict__ w)
{
    int i = blockIdx.x * blockDim.x + threadIdx.x;
    unsigned x = w[i];
    int f = 0;
    if (x == 0x3F800000u)               f = 2;
    else if ((x & 0xFFFFu) == 0x3F80u)  f = 4;
    else if (x > 1u)                    f = 1;
    if (f) atomicOr(&g_mask_flags, f);
}

__global__ __launch_bounds__(256) void maskfuse_kernel(const float* __restrict__ rd,
                                                       const void* __restrict__ maskp)
{
    int i = blockIdx.x * 256 + threadIdx.x;
    size_t base = (size_t)i * 4;
    int mf = g_mask_flags;
    int mode = (mf & 4) ? 3 : (mf & 2) ? 2 : (mf & 1) ? 1 : 0;
    float4 d4 = *(const float4*)&rd[base];
    int m0, m1, m2, m3;
    if (mode == 0) {
        int4 m = *(const int4*)((const int*)maskp + base);
        m0 = m.x != 0; m1 = m.y != 0; m2 = m.z != 0; m3 = m.w != 0;
    } else if (mode == 1) {
        uchar4 m = *(const uchar4*)((const unsigned char*)maskp + base);
        m0 = m.x != 0; m1 = m.y != 0; m2 = m.z != 0; m3 = m.w != 0;
    } else if (mode == 2) {
        float4 m = *(const float4*)((const float*)maskp + base);
        m0 = m.x != 0.0f; m1 = m.y != 0.0f; m2 = m.z != 0.0f; m3 = m.w != 0.0f;
    } else {
        ushort4 m = *(const ushort4*)((const unsigned short*)maskp + base);
        m0 = m.x != 0; m1 = m.y != 0; m2 = m.z != 0; m3 = m.w != 0;
    }
    int i0 = min(max(__float2int_rd(d4.x * 255.0f), 0), 254);
    int i1 = min(max(__float2int_rd(d4.y * 255.0f), 0), 254);
    int i2 = min(max(__float2int_rd(d4.z * 255.0f), 0), 254);
    int i3 = min(max(__float2int_rd(d4.w * 255.0f), 0), 254);
    uchar4 o;
    o.x = (unsigned char)(m0 ? 255 : i0);
    o.y = (unsigned char)(m1 ? 255 : i1);
    o.z = (unsigned char)(m2 ? 255 : i2);
    o.w = (unsigned char)(m3 ? 255 : i3);
    *(uchar4*)&g_mdx[base] = o;
}

__global__ __launch_bounds__(256) void split_kernel(const float* __restrict__ src,
                                                    __nv_bfloat16* __restrict__ hi,
                                                    __nv_bfloat16* __restrict__ lo)
{
    int i = blockIdx.x * 256 + threadIdx.x;
    float2 v = *(const float2*)&src[(size_t)i * 2];
    __nv_bfloat16 hx = __float2bfloat16(v.x), hy = __float2bfloat16(v.y);
    __nv_bfloat162 h2; h2.x = hx; h2.y = hy;
    __nv_bfloat162 l2;
    l2.x = __float2bfloat16(v.x - __bfloat162float(hx));
    l2.y = __float2bfloat16(v.y - __bfloat162float(hy));
    *(__nv_bfloat162*)&hi[(size_t)i * 2] = h2;
    *(__nv_bfloat162*)&lo[(size_t)i * 2] = l2;
}

__global__ __launch_bounds__(256) void splitw_kernel(const float* __restrict__ w0,
                                                     const float* __restrict__ w1,
                                                     const float* __restrict__ w2,
                                                     const float* __restrict__ w3,
                                                     const float* __restrict__ w4)
{
    int i = blockIdx.x * 256 + threadIdx.x;
    size_t e = (size_t)i * 2;
    int w = (int)(e >> 16);
    size_t off = e & 65535;
    const float* src = (w == 0) ? w0 : (w == 1) ? w1 : (w == 2) ? w2 : (w == 3) ? w3 : w4;
    float2 v = *(const float2*)&src[off];
    __nv_bfloat16 hx = __float2bfloat16(v.x), hy = __float2bfloat16(v.y);
    __nv_bfloat162 h2; h2.x = hx; h2.y = hy;
    __nv_bfloat162 l2;
    l2.x = __float2bfloat16(v.x - __bfloat162float(hx));
    l2.y = __float2bfloat16(v.y - __bfloat162float(hy));
    *(__nv_bfloat162*)&g_whi[e] = h2;
    *(__nv_bfloat162*)&g_wlo[e] = l2;
}

// ---------------------------------------------------------------------------
// HMMA GEMM (bf16x3), cp.async double-buffered.
// ---------------------------------------------------------------------------
#define MM_AHI 0
#define MM_ALO 18432
#define MM_WHI 36864
#define MM_WLO 46080
#define MM_BUF 55296
#define MM_SMEM (2*MM_BUF)

__global__ __launch_bounds__(256) void tcmma(const __nv_bfloat16* __restrict__ Ahi,
                                             const __nv_bfloat16* __restrict__ Alo,
                                             int widx0,
                                             const float* __restrict__ bias,
                                             float* __restrict__ C0,
                                             float* __restrict__ C1,
                                             float* __restrict__ C2,
                                             int act, int qkv)
{
    extern __shared__ char sm[];
    unsigned smb = smem_u32(sm);
    int tid = threadIdx.x;
    int lane = tid & 31;
    int wid = tid >> 5;
    int wm = wid & 3;
    int wn = wid >> 2;
    int m0 = blockIdx.x * 128, n0 = blockIdx.y * 64;
    int z = blockIdx.z;
    const __nv_bfloat16* Whi = g_whi + (size_t)(widx0 + z) * (DD*DD);
    const __nv_bfloat16* Wlo = g_wlo + (size_t)(widx0 + z) * (DD*DD);
    float* C = (z == 0) ? C0 : (z == 1) ? C1 : C2;

    auto stage = [&](int kc, unsigned bo) {
        #pragma unroll
        for (int it = 0; it < 4; it++) {
            int v = tid + it * 256;
            int row = v >> 3, cg = (v & 7) * 8;
            size_t gofs = (size_t)(m0 + row) * 256 + kc * 64 + cg;
            cpa16(smb + bo + MM_AHI + row*144 + cg*2, &Ahi[gofs]);
            cpa16(smb + bo + MM_ALO + row*144 + cg*2, &Alo[gofs]);
        }
        #pragma unroll
        for (int it = 0; it < 2; it++) {
            int v = tid + it * 256;
            int row = v >> 3, cg = (v & 7) * 8;
            size_t gofs = (size_t)(n0 + row) * 256 + kc * 64 + cg;
            cpa16(smb + bo + MM_WHI + row*144 + cg*2, &Whi[gofs]);
            cpa16(smb + bo + MM_WLO + row*144 + cg*2, &Wlo[gofs]);
        }
    };

    float acc[2][4][4];
    #pragma unroll
    for (int a = 0; a < 2; a++)
        #pragma unroll
        for (int b = 0; b < 4; b++)
            #pragma unroll
            for (int c = 0; c < 4; c++) acc[a][b][c] = 0.0f;

    stage(0, 0);
    CPA_COMMIT();

    for (int kc = 0; kc < 4; kc++) {
        CPA_WAIT0();
        __syncthreads();
        unsigned bo = (unsigned)(kc & 1) * MM_BUF;
        if (kc < 3) { stage(kc + 1, bo ^ MM_BUF); CPA_COMMIT(); }

        #pragma unroll
        for (int ks = 0; ks < 4; ks++) {
            int kb = ks * 16;
            unsigned ah[2][4], al[2][4], bh[2][4], bl[2][4];
            #pragma unroll
            for (int mi = 0; mi < 2; mi++) {
                int row = wm*32 + mi*16 + (lane & 15);
                unsigned ad = smb + bo + MM_AHI + row*144 + (kb + ((lane >> 4) << 3)) * 2;
                ldsm4(ah[mi], ad);
                ldsm4(al[mi], ad + (MM_ALO - MM_AHI));
            }
            #pragma unroll
            for (int gi = 0; gi < 2; gi++) {
                int nrow = wn*32 + gi*16 + (lane & 7) + ((lane >> 4) & 1) * 8;
                unsigned bd = smb + bo + MM_WHI + nrow*144 + (kb + (((lane >> 3) & 1) << 3)) * 2;
                ldsm4(bh[gi], bd);
                ldsm4(bl[gi], bd + (MM_WLO - MM_WHI));
            }
            #pragma unroll
            for (int mi = 0; mi < 2; mi++) {
                #pragma unroll
                for (int ni = 0; ni < 4; ni++) {
                    int gi = ni >> 1, hf = (ni & 1) * 2;
                    mma16816(acc[mi][ni], ah[mi], &bh[gi][hf]);
                    mma16816(acc[mi][ni], ah[mi], &bl[gi][hf]);
                    mma16816(acc[mi][ni], al[mi], &bh[gi][hf]);
                }
            }
        }
    }

    if (qkv && z != 2) {
        __nv_bfloat16* dsthi = (z == 0) ? g_qh2 : g_kh2;
        __nv_bfloat16* dstlo = (z == 0) ? g_ql2 : g_kl2;
        int head = blockIdx.y * 2 + wn;
        #pragma unroll
        for (int mi = 0; mi < 2; mi++) {
            #pragma unroll
            for (int rr = 0; rr < 2; rr++) {
                float v[8];
                #pragma unroll
                for (int ni = 0; ni < 4; ni++) {
                    v[ni*2]   = acc[mi][ni][rr*2];
                    v[ni*2+1] = acc[mi][ni][rr*2+1];
                }
                float ss = 0.0f;
                #pragma unroll
                for (int j = 0; j < 8; j++) ss = fmaf(v[j], v[j], ss);
                ss += __shfl_xor_sync(0xffffffffu, ss, 1);
                ss += __shfl_xor_sync(0xffffffffu, ss, 2);
                float inv = 1.0f / fmaxf(sqrtf(ss), 1e-12f);
                int row = m0 + wm*32 + mi*16 + rr*8 + (lane >> 2);
                int b = row >> 10, t = row & 1023;
                size_t base = (((size_t)(b*8 + head)) * 1024 + t) * 32 + (lane & 3) * 2;
                #pragma unroll
                for (int ni = 0; ni < 4; ni++) {
                    float v0 = v[ni*2] * inv, v1 = v[ni*2+1] * inv;
                    unsigned hh = cvt2bf(v1, v0);
                    float f0 = __uint_as_float(hh << 16), f1 = __uint_as_float(hh & 0xFFFF0000u);
                    *(unsigned*)&dsthi[base + ni*8] = hh;
                    *(unsigned*)&dstlo[base + ni*8] = cvt2bf(v1 - f1, v0 - f0);
                }
            }
        }
        return;
    }

    int rbase = m0 + wm*32 + (lane >> 2);
    int cbase = n0 + wn*32 + (lane & 3) * 2;
    #pragma unroll
    for (int mi = 0; mi < 2; mi++) {
        #pragma unroll
        for (int ni = 0; ni < 4; ni++) {
            int col = cbase + ni*8;
            float b0 = bias ? bias[col] : 0.0f;
            float b1 = bias ? bias[col + 1] : 0.0f;
            float v0 = acc[mi][ni][0] + b0;
            float v1 = acc[mi][ni][1] + b1;
            float v2 = acc[mi][ni][2] + b0;
            float v3 = acc[mi][ni][3] + b1;
            if (act) {
                v0 = (v0 >= 0.0f) ? v0 : 0.01f * v0;
                v1 = (v1 >= 0.0f) ? v1 : 0.01f * v1;
                v2 = (v2 >= 0.0f) ? v2 : 0.01f * v2;
                v3 = (v3 >= 0.0f) ? v3 : 0.01f * v3;
            }
            int row = rbase + mi*16;
            *(float2*)&C[(size_t)row * 256 + col]       = make_float2(v0, v1);
            *(float2*)&C[(size_t)(row + 8) * 256 + col] = make_float2(v2, v3);
        }
    }
}

// ---------------------------------------------------------------------------
// V transpose + split (unchanged)
// ---------------------------------------------------------------------------
__global__ __launch_bounds__(256) void vtrans_kernel()
{
    __shared__ float sT[32*72];
    int tid = threadIdx.x;
    int bh = blockIdx.y, b = bh >> 3, h = bh & 7;
    int t0 = blockIdx.x << 6;
    {
        int row = tid >> 2, cg = (tid & 3) * 8;
        const float* src = &g_vraw[((size_t)(b*1024) + t0 + row) * 256 + h * 32 + cg];
        float4 a = *(const float4*)src;
        float4 c = *(const float4*)(src + 4);
        sT[(cg+0)*72 + row] = a.x; sT[(cg+1)*72 + row] = a.y;
        sT[(cg+2)*72 + row] = a.z; sT[(cg+3)*72 + row] = a.w;
        sT[(cg+4)*72 + row] = c.x; sT[(cg+5)*72 + row] = c.y;
        sT[(cg+6)*72 + row] = c.z; sT[(cg+7)*72 + row] = c.w;
    }
    __syncthreads();
    {
        int c = tid >> 3, sg = (tid & 7) * 8;
        float v[8];
        #pragma unroll
        for (int j = 0; j < 8; j++) v[j] = sT[c*72 + sg + j];
        unsigned hp[4], lp[4];
        #pragma unroll
        for (int j = 0; j < 4; j++) {
            unsigned hh = cvt2bf(v[2*j+1], v[2*j]);
            float f0 = __uint_as_float(hh << 16);
            float f1 = __uint_as_float(hh & 0xFFFF0000u);
            hp[j] = hh;
            lp[j] = cvt2bf(v[2*j+1] - f1, v[2*j] - f0);
        }
        size_t o = ((size_t)bh * 32 + c) * 1024 + t0 + sg;
        *(uint4*)&g_vthi[o] = make_uint4(hp[0], hp[1], hp[2], hp[3]);
        *(uint4*)&g_vtlo[o] = make_uint4(lp[0], lp[1], lp[2], lp[3]);
    }
}

// ---------------------------------------------------------------------------
// HMMA attention, 128 q rows per CTA, cp.async double-buffered K/V.
// dynamic smem (bytes):
//  QHI 0 (10240) | QLO 10240 | KV buf0 20480 (19456: KHI 0, KLO 5120,
//  VTHI 10240, VTLO 14848) | KV buf1 39936 | LUT 59392 (1024) -> 60416
// post-loop: sO f32[128][34] at 0, sRS f32[128] at 18432.
// ---------------------------------------------------------------------------
#define AT_QHI 0
#define AT_QLO 10240
#define AT_KV  20480
#define AT_KVBUF 19456
#define AT_LUT 59392
#define AT_SMEM 60416

__global__ __launch_bounds__(256) void attn_mma_kernel()
{
    extern __shared__ __align__(16) char SM_[];
    unsigned smb = smem_u32(SM_);
    float* sLUT = (float*)(SM_ + AT_LUT);

    int tid = threadIdx.x;
    int lane = tid & 31;
    int wid = tid >> 5;
    int wq = wid & 3;
    int ws = wid >> 2;
    int bh = blockIdx.y, b = bh >> 3, h = bh & 7;
    int t0 = blockIdx.x << 7;

    auto stageKV = [&](int s0, unsigned gb) {
        int row = tid >> 2, cg = (tid & 3) * 8;
        size_t gofs = (((size_t)bh * TT) + s0 + row) * 32 + cg;
        cpa16(smb + gb + 0     + row*80 + cg*2, &g_kh2[gofs]);
        cpa16(smb + gb + 5120  + row*80 + cg*2, &g_kl2[gofs]);
        int c = tid >> 3, sg = (tid & 7) * 8;
        size_t vofs = ((size_t)bh * 32 + c) * 1024 + s0 + sg;
        cpa16(smb + gb + 10240 + c*144 + sg*2, &g_vthi[vofs]);
        cpa16(smb + gb + 14848 + c*144 + sg*2, &g_vtlo[vofs]);
    };

    if (tid < 256) sLUT[tid] = g_lutv[h*256 + tid];
    #pragma unroll
    for (int r2 = 0; r2 < 2; r2++) {
        int row = (tid >> 2) + r2*64, cg = (tid & 3) * 8;
        size_t gofs = (((size_t)bh * TT) + t0 + row) * 32 + cg;
        *(uint4*)(SM_ + AT_QHI + row*80 + cg*2) = *(const uint4*)&g_qh2[gofs];
        *(uint4*)(SM_ + AT_QLO + row*80 + cg*2) = *(const uint4*)&g_ql2[gofs];
    }
    stageKV(0, AT_KV);
    CPA_COMMIT();

    float oacc[2][4][4];
    #pragma unroll
    for (int mi = 0; mi < 2; mi++)
        #pragma unroll
        for (int i = 0; i < 4; i++)
            #pragma unroll
            for (int j = 0; j < 4; j++) oacc[mi][i][j] = 0.0f;
    float zs[2][2] = {{0.f,0.f},{0.f,0.f}};

    int qrow_f = (lane >> 2);
    int ccol_f = (lane & 3) * 2;

    #pragma unroll 1
    for (int st = 0; st < 16; st++) {
        int s0 = st << 6;
        CPA_WAIT0();
        __syncthreads();
        unsigned gb = AT_KV + (unsigned)(st & 1) * AT_KVBUF;
        if (st < 15) { stageKV(s0 + 64, gb == AT_KV ? AT_KV + AT_KVBUF : AT_KV); CPA_COMMIT(); }

        uchar2 md[2][4][2];
        {
            size_t mb = (size_t)b * TT * TT;
            int gcb = s0 + ws*32 + ccol_f;
            #pragma unroll
            for (int mi = 0; mi < 2; mi++) {
                int gr = t0 + wq*32 + mi*16 + qrow_f;
                #pragma unroll
                for (int ni = 0; ni < 4; ni++) {
                    md[mi][ni][0] = *(const uchar2*)&g_mdx[mb + (size_t)gr * TT + gcb + ni*8];
                    md[mi][ni][1] = *(const uchar2*)&g_mdx[mb + (size_t)(gr+8) * TT + gcb + ni*8];
                }
            }
        }

        float sacc[2][4][4];
        #pragma unroll
        for (int mi = 0; mi < 2; mi++)
            #pragma unroll
            for (int i = 0; i < 4; i++)
                #pragma unroll
                for (int j = 0; j < 4; j++) sacc[mi][i][j] = 0.0f;

        #pragma unroll
        for (int ks = 0; ks < 2; ks++) {
            int kb = ks * 16;
            unsigned ah[2][4], al[2][4], bhf[2][4], blf[2][4];
            #pragma unroll
            for (int mi = 0; mi < 2; mi++) {
                int row = wq*32 + mi*16 + (lane & 15);
                unsigned ad = smb + AT_QHI + row*80 + (kb + ((lane >> 4) << 3)) * 2;
                ldsm4(ah[mi], ad);
                ldsm4(al[mi], ad + (AT_QLO - AT_QHI));
            }
            #pragma unroll
            for (int gi = 0; gi < 2; gi++) {
                int nrow = ws*32 + gi*16 + (lane & 7) + ((lane >> 4) & 1) * 8;
                unsigned bd = smb + gb + 0 + nrow*80 + (kb + (((lane >> 3) & 1) << 3)) * 2;
                ldsm4(bhf[gi], bd);
                ldsm4(blf[gi], bd + 5120);
            }
            #pragma unroll
            for (int mi = 0; mi < 2; mi++) {
                #pragma unroll
                for (int ni = 0; ni < 4; ni++) {
                    int gi = ni >> 1, hf = (ni & 1) * 2;
                    mma16816(sacc[mi][ni], ah[mi], &bhf[gi][hf]);
                    mma16816(sacc[mi][ni], ah[mi], &blf[gi][hf]);
                    mma16816(sacc[mi][ni], al[mi], &bhf[gi][hf]);
                }
            }
        }

        unsigned phi[2][8], plo[2][8];
        #pragma unroll
        for (int mi = 0; mi < 2; mi++) {
            #pragma unroll
            for (int ni = 0; ni < 4; ni++) {
                uchar2 m0 = md[mi][ni][0], m1 = md[mi][ni][1];
                float z0 = (m0.x == 255) ? 0.0f : __expf(sacc[mi][ni][0] + sLUT[m0.x]);
                float z1 = (m0.y == 255) ? 0.0f : __expf(sacc[mi][ni][1] + sLUT[m0.y]);
                float z2 = (m1.x == 255) ? 0.0f : __expf(sacc[mi][ni][2] + sLUT[m1.x]);
                float z3 = (m1.y == 255) ? 0.0f : __expf(sacc[mi][ni][3] + sLUT[m1.y]);
                zs[mi][0] += z0 + z1;
                zs[mi][1] += z2 + z3;
                unsigned p01 = cvt2bf(z1, z0);
                unsigned p23 = cvt2bf(z3, z2);
                phi[mi][ni*2]   = p01;
                phi[mi][ni*2+1] = p23;
                float f0 = __uint_as_float(p01 << 16), f1 = __uint_as_float(p01 & 0xFFFF0000u);
                float f2 = __uint_as_float(p23 << 16), f3 = __uint_as_float(p23 & 0xFFFF0000u);
                plo[mi][ni*2]   = cvt2bf(z1 - f1, z0 - f0);
                plo[mi][ni*2+1] = cvt2bf(z3 - f3, z2 - f2);
            }
        }

        #pragma unroll
        for (int kf = 0; kf < 2; kf++) {
            unsigned vbh[2][4], vbl[2][4];
            #pragma unroll
            for (int gi = 0; gi < 2; gi++) {
                int nrow = gi*16 + (lane & 7) + ((lane >> 4) & 1) * 8;
                int col = ws*32 + kf*16 + (((lane >> 3) & 1) << 3);
                unsigned bd = smb + gb + 10240 + nrow*144 + col*2;
                ldsm4(vbh[gi], bd);
                ldsm4(vbl[gi], bd + 4608);
            }
            #pragma unroll
            for (int mi = 0; mi < 2; mi++) {
                #pragma unroll
                for (int ni = 0; ni < 4; ni++) {
                    int gi = ni >> 1, hf = (ni & 1) * 2;
                    mma16816(oacc[mi][ni], &phi[mi][4*kf], &vbh[gi][hf]);
                    mma16816(oacc[mi][ni], &plo[mi][4*kf], &vbh[gi][hf]);
                    mma16816(oacc[mi][ni], &phi[mi][4*kf], &vbl[gi][hf]);
                }
            }
        }
    }

    #pragma unroll
    for (int mi = 0; mi < 2; mi++) {
        zs[mi][0] += __shfl_xor_sync(0xffffffffu, zs[mi][0], 1);
        zs[mi][0] += __shfl_xor_sync(0xffffffffu, zs[mi][0], 2);
        zs[mi][1] += __shfl_xor_sync(0xffffffffu, zs[mi][1], 1);
        zs[mi][1] += __shfl_xor_sync(0xffffffffu, zs[mi][1], 2);
    }
    __syncthreads();   // all warps done with Q/K/V smem before reuse as sO/sRS

    float* sO  = (float*)(SM_ + 0);        // [128][34]
    float* sRS = (float*)(SM_ + 18432);    // [128]
    if (ws == 1) {
        #pragma unroll
        for (int mi = 0; mi < 2; mi++) {
            int r = wq*32 + mi*16 + qrow_f;
            if ((lane & 3) == 0) {
                sRS[r]     = zs[mi][0];
                sRS[r + 8] = zs[mi][1];
            }
            #pragma unroll
            for (int ni = 0; ni < 4; ni++) {
                int c = ni*8 + ccol_f;
                *(float2*)&sO[r*34 + c]     = make_float2(oacc[mi][ni][0], oacc[mi][ni][1]);
                *(float2*)&sO[(r+8)*34 + c] = make_float2(oacc[mi][ni][2], oacc[mi][ni][3]);
            }
        }
    }
    __syncthreads();
    if (ws == 0) {
        #pragma unroll
        for (int mi = 0; mi < 2; mi++) {
            int r = wq*32 + mi*16 + qrow_f;
            float inv0 = 1.0f / (zs[mi][0] + sRS[r]     + 1e-5f);
            float inv8 = 1.0f / (zs[mi][1] + sRS[r + 8] + 1e-5f);
            size_t o0 = ((size_t)b * TT + t0 + r)     * DD + h * 32;
            size_t o8 = ((size_t)b * TT + t0 + r + 8) * DD + h * 32;
            #pragma unroll
            for (int ni = 0; ni < 4; ni++) {
                int c = ni*8 + ccol_f;
                float2 p0 = *(const float2*)&sO[r*34 + c];
                float2 p8 = *(const float2*)&sO[(r+8)*34 + c];
                float v0 = (oacc[mi][ni][0] + p0.x) * inv0;
                float v1 = (oacc[mi][ni][1] + p0.y) * inv0;
                float v2 = (oacc[mi][ni][2] + p8.x) * inv8;
                float v3 = (oacc[mi][ni][3] + p8.y) * inv8;
                unsigned h0 = cvt2bf(v1, v0);
                unsigned h8 = cvt2bf(v3, v2);
                float f0 = __uint_as_float(h0 << 16), f1 = __uint_as_float(h0 & 0xFFFF0000u);
                float f2 = __uint_as_float(h8 << 16), f3 = __uint_as_float(h8 & 0xFFFF0000u);
                *(unsigned*)&g_athi[o0 + c] = h0;
                *(unsigned*)&g_atlo[o0 + c] = cvt2bf(v1 - f1, v0 - f0);
                *(unsigned*)&g_athi[o8 + c] = h8;
                *(unsigned*)&g_atlo[o8 + c] = cvt2bf(v3 - f3, v2 - f2);
            }
        }
    }
}

__global__ __launch_bounds__(256) void ln_kernel(const float* __restrict__ a,
                                                 const float* __restrict__ b,
                                                 const float* __restrict__ g,
                                                 const float* __restrict__ be,
                                                 float* __restrict__ out,
                                                 int dosplit)
{
    int w    = (blockIdx.x * 256 + threadIdx.x) >> 5;
    int lane = threadIdx.x & 31;
    const float* ap = a + (size_t)w * 256;
    const float* bp = b + (size_t)w * 256;
    float v[8]; float s = 0.0f;
    #pragma unroll
    for (int u = 0; u < 8; u++) { v[u] = ap[lane + 32*u] + bp[lane + 32*u]; s += v[u]; }
    #pragma unroll
    for (int off = 16; off; off >>= 1) s += __shfl_xor_sync(0xffffffffu, s, off);
    float mu = s * (1.0f / 256.0f);
    float vs = 0.0f;
    #pragma unroll
    for (int u = 0; u < 8; u++) { float d = v[u] - mu; vs = fmaf(d, d, vs); }
    #pragma unroll
    for (int off = 16; off; off >>= 1) vs += __shfl_xor_sync(0xffffffffu, vs, off);
    float rstd = rsqrtf(vs * (1.0f / 256.0f) + 1e-5f);
    #pragma unroll
    for (int u = 0; u < 8; u++) {
        int col = lane + 32*u;
        float o = (v[u] - mu) * rstd * g[col] + be[col];
        out[(size_t)w * 256 + col] = o;
        if (dosplit) {
            __nv_bfloat16 hh = __float2bfloat16(o);
            g_zhi[(size_t)w * 256 + col] = hh;
            g_zlo[(size_t)w * 256 + col] = __float2bfloat16(o - __bfloat162float(hh));
        }
    }
}

extern "C" void kernel_launch(void* const* d_in, const int* in_sizes, int n_in,
                              void* d_out, int out_size)
{
    const float* x    = (const float*)d_in[0];
    const void*  mask = d_in[1];
    const float* rel  = (const float*)d_in[2];
    const float* pw1  = (const float*)d_in[6];
    const float* pb1  = (const float*)d_in[7];
    const float* pw2  = (const float*)d_in[8];
    const float* pb2  = (const float*)d_in[9];
    const float* bo   = (const float*)d_in[11];
    const float* bfv  = (const float*)d_in[13];
    const float* g1   = (const float*)d_in[14];
    const float* be1  = (const float*)d_in[15];
    const float* g2   = (const float*)d_in[16];
    const float* be2  = (const float*)d_in[17];

    float *qraw, *vraw, *y, *zz;
    __nv_bfloat16 *xhi, *xlo, *athi, *atlo, *zhi, *zlo;
    cudaGetSymbolAddress((void**)&qraw, g_qraw);
    cudaGetSymbolAddress((void**)&vraw, g_vraw);
    cudaGetSymbolAddress((void**)&y,    g_y);
    cudaGetSymbolAddress((void**)&zz,   g_zz);
    cudaGetSymbolAddress((void**)&xhi,  g_xhi);
    cudaGetSymbolAddress((void**)&xlo,  g_xlo);
    cudaGetSymbolAddress((void**)&athi, g_athi);
    cudaGetSymbolAddress((void**)&atlo, g_atlo);
    cudaGetSymbolAddress((void**)&zhi,  g_zhi);
    cudaGetSymbolAddress((void**)&zlo,  g_zlo);

    cudaFuncSetAttribute(tcmma, cudaFuncAttributeMaxDynamicSharedMemorySize, MM_SMEM);
    cudaFuncSetAttribute(attn_mma_kernel, cudaFuncAttributeMaxDynamicSharedMemorySize, AT_SMEM);

    prep_kernel<<<1, 128>>>(pw1, pb1, pw2, pb2);
    lut_kernel<<<8, 256>>>();
    detect_kernel<<<256, 256>>>((const unsigned*)mask);
    maskfuse_kernel<<<4096, 256>>>(rel, mask);
    splitw_kernel<<<640, 256>>>((const float*)d_in[3], (const float*)d_in[4],
                                (const float*)d_in[5], (const float*)d_in[10],
                                (const float*)d_in[12]);
    split_kernel<<<2048, 256>>>(x, xhi, xlo);

    tcmma<<<dim3(32, 4, 3), 256, MM_SMEM>>>(xhi, xlo, 0, nullptr, vraw, vraw, vraw, 0, 1);
    vtrans_kernel<<<dim3(16, 32), 256>>>();

    attn_mma_kernel<<<dim3(8, 32), 256, AT_SMEM>>>();

    tcmma<<<dim3(32, 4, 1), 256, MM_SMEM>>>(athi, atlo, 3, bo, y, y, y, 0, 0);
    ln_kernel<<<512, 256>>>(x, y, g1, be1, zz, 1);
    tcmma<<<dim3(32, 4, 1), 256, MM_SMEM>>>(zhi, zlo, 4, bfv, qraw, qraw, qraw, 1, 0);
    ln_kernel<<<512, 256>>>(zz, qraw, g2, be2, (float*)d_out, 0);
}

// round 12
// speedup vs baseline: 2.6075x; 1.0295x over previous
#include <cuda_runtime.h>
#include <cuda_bf16.h>

#define BB  4
#define TT  1024
#define DD  256
#define HH  8
#define CC  16
#define BT  (BB*TT)

typedef unsigned long long ull;

__device__ __forceinline__ unsigned smem_u32(const void* p) {
    unsigned a;
    asm("{ .reg .u64 t; cvta.to.shared.u64 t, %1; cvt.u32.u64 %0, t; }" : "=r"(a) : "l"(p));
    return a;
}
__device__ __forceinline__ void ldsm4(unsigned* r, unsigned addr) {
    asm volatile("ldmatrix.sync.aligned.m8n8.x4.shared.b16 {%0,%1,%2,%3}, [%4];"
                 : "=r"(r[0]), "=r"(r[1]), "=r"(r[2]), "=r"(r[3]) : "r"(addr));
}
__device__ __forceinline__ void mma16816(float* c, const unsigned* a, const unsigned* b) {
    asm volatile("mma.sync.aligned.m16n8k16.row.col.f32.bf16.bf16.f32 "
                 "{%0,%1,%2,%3}, {%4,%5,%6,%7}, {%8,%9}, {%0,%1,%2,%3};"
                 : "+f"(c[0]), "+f"(c[1]), "+f"(c[2]), "+f"(c[3])
                 : "r"(a[0]), "r"(a[1]), "r"(a[2]), "r"(a[3]), "r"(b[0]), "r"(b[1]));
}
__device__ __forceinline__ unsigned cvt2bf(float hi, float lo) {
    unsigned r;
    asm("cvt.rn.bf16x2.f32 %0, %1, %2;" : "=r"(r) : "f"(hi), "f"(lo));
    return r;
}
__device__ __forceinline__ void cpa16(unsigned dst, const void* src) {
    asm volatile("cp.async.cg.shared.global [%0], [%1], 16;" :: "r"(dst), "l"(src));
}
#define CPA_COMMIT() asm volatile("cp.async.commit_group;" ::: "memory")
#define CPA_WAIT0()  asm volatile("cp.async.wait_group 0;" ::: "memory")

// ---------------- scratch ----------------
__device__ float g_qraw[BT*DD];          // FFN scratch
__device__ float g_y[BT*DD];
__device__ float g_zz[BT*DD];
__device__ unsigned char g_mdx[BB*TT*TT];   // u8: 255=masked, else idx 0..254
__device__ float g_lutv[HH*256];
__device__ int   g_mask_flags;
__device__ __nv_bfloat16 g_xhi[BT*DD],  g_xlo[BT*DD];
__device__ __nv_bfloat16 g_athi[BT*DD], g_atlo[BT*DD];
__device__ __nv_bfloat16 g_zhi[BT*DD],  g_zlo[BT*DD];
__device__ __nv_bfloat16 g_whi[5*DD*DD], g_wlo[5*DD*DD];
__device__ __nv_bfloat16 g_vthi[32*HH*BB*TT], g_vtlo[32*HH*BB*TT]; // [bh][32][1024]
__device__ __nv_bfloat16 g_qh2[HH*BB*TT*32], g_ql2[HH*BB*TT*32];   // [bh][t][32]
__device__ __nv_bfloat16 g_kh2[HH*BB*TT*32], g_kl2[HH*BB*TT*32];

// ---------------------------------------------------------------------------
// Merged coef + LUT build. One block per head; block 0 zeroes mask flags.
// ---------------------------------------------------------------------------
__global__ void lut_all(const float* __restrict__ pw1, const float* __restrict__ pb1,
                        const float* __restrict__ pw2, const float* __restrict__ pb2)
{
    __shared__ float sc[34];
    int h = blockIdx.x;
    int t = threadIdx.x;
    if (h == 0 && t == 0) g_mask_flags = 0;
    if (t < 16) {
        float w1 = pw1[h*CC + t], b1 = pb1[h*CC + t], w2 = pw2[h*CC + t];
        float beta, delta, k0add, k1add;
        if (w1 != 0.0f) {
            beta  = 0.495f * w2 * fabsf(w1);
            delta = -b1 / w1;
            k0add = 0.505f * w2 * b1;
            k1add = 0.505f * w2 * w1;
        } else {
            beta = 0.0f; delta = 0.0f;
            k0add = w2 * (0.505f * b1 + 0.495f * fabsf(b1));
            k1add = 0.0f;
        }
        #pragma unroll
        for (int off = 1; off < 16; off <<= 1) {
            k0add += __shfl_xor_sync(0x0000FFFFu, k0add, off);
            k1add += __shfl_xor_sync(0x0000FFFFu, k1add, off);
        }
        sc[2 + t]  = beta;
        sc[18 + t] = delta;
        if (t == 0) {
            sc[0] = pb2[h] + k0add;
            sc[1] = k1add;
        }
    }
    __syncthreads();
    if (t == 255) { g_lutv[h*256 + 255] = 0.0f; return; }
    float m = (t + 0.5f) * (1.0f / 255.0f);
    float v = sc[0] + sc[1] * m;
    #pragma unroll
    for (int c = 0; c < 16; c++)
        v += sc[2 + c] * fabsf(m - sc[18 + c]);
    g_lutv[h*256 + t] = -v;
}

__global__ void detect_kernel(const unsigned* __restrict__ w)
{
    int i = blockIdx.x * blockDim.x + threadIdx.x;
    unsigned x = w[i];
    int f = 0;
    if (x == 0x3F800000u)               f = 2;
    else if ((x & 0xFFFFu) == 0x3F80u)  f = 4;
    else if (x > 1u)                    f = 1;
    if (f) atomicOr(&g_mask_flags, f);
}

__global__ __launch_bounds__(256) void maskfuse_kernel(const float* __restrict__ rd,
                                                       const void* __restrict__ maskp)
{
    int i = blockIdx.x * 256 + threadIdx.x;
    size_t base = (size_t)i * 4;
    int mf = g_mask_flags;
    int mode = (mf & 4) ? 3 : (mf & 2) ? 2 : (mf & 1) ? 1 : 0;
    float4 d4 = *(const float4*)&rd[base];
    int m0, m1, m2, m3;
    if (mode == 0) {
        int4 m = *(const int4*)((const int*)maskp + base);
        m0 = m.x != 0; m1 = m.y != 0; m2 = m.z != 0; m3 = m.w != 0;
    } else if (mode == 1) {
        uchar4 m = *(const uchar4*)((const unsigned char*)maskp + base);
        m0 = m.x != 0; m1 = m.y != 0; m2 = m.z != 0; m3 = m.w != 0;
    } else if (mode == 2) {
        float4 m = *(const float4*)((const float*)maskp + base);
        m0 = m.x != 0.0f; m1 = m.y != 0.0f; m2 = m.z != 0.0f; m3 = m.w != 0.0f;
    } else {
        ushort4 m = *(const ushort4*)((const unsigned short*)maskp + base);
        m0 = m.x != 0; m1 = m.y != 0; m2 = m.z != 0; m3 = m.w != 0;
    }
    int i0 = min(max(__float2int_rd(d4.x * 255.0f), 0), 254);
    int i1 = min(max(__float2int_rd(d4.y * 255.0f), 0), 254);
    int i2 = min(max(__float2int_rd(d4.z * 255.0f), 0), 254);
    int i3 = min(max(__float2int_rd(d4.w * 255.0f), 0), 254);
    uchar4 o;
    o.x = (unsigned char)(m0 ? 255 : i0);
    o.y = (unsigned char)(m1 ? 255 : i1);
    o.z = (unsigned char)(m2 ? 255 : i2);
    o.w = (unsigned char)(m3 ? 255 : i3);
    *(uchar4*)&g_mdx[base] = o;
}

__global__ __launch_bounds__(256) void split_kernel(const float* __restrict__ src,
                                                    __nv_bfloat16* __restrict__ hi,
                                                    __nv_bfloat16* __restrict__ lo)
{
    int i = blockIdx.x * 256 + threadIdx.x;
    float2 v = *(const float2*)&src[(size_t)i * 2];
    __nv_bfloat16 hx = __float2bfloat16(v.x), hy = __float2bfloat16(v.y);
    __nv_bfloat162 h2; h2.x = hx; h2.y = hy;
    __nv_bfloat162 l2;
    l2.x = __float2bfloat16(v.x - __bfloat162float(hx));
    l2.y = __float2bfloat16(v.y - __bfloat162float(hy));
    *(__nv_bfloat162*)&hi[(size_t)i * 2] = h2;
    *(__nv_bfloat162*)&lo[(size_t)i * 2] = l2;
}

__global__ __launch_bounds__(256) void splitw_kernel(const float* __restrict__ w0,
                                                     const float* __restrict__ w1,
                                                     const float* __restrict__ w2,
                                                     const float* __restrict__ w3,
                                                     const float* __restrict__ w4)
{
    int i = blockIdx.x * 256 + threadIdx.x;
    size_t e = (size_t)i * 2;
    int w = (int)(e >> 16);
    size_t off = e & 65535;
    const float* src = (w == 0) ? w0 : (w == 1) ? w1 : (w == 2) ? w2 : (w == 3) ? w3 : w4;
    float2 v = *(const float2*)&src[off];
    __nv_bfloat16 hx = __float2bfloat16(v.x), hy = __float2bfloat16(v.y);
    __nv_bfloat162 h2; h2.x = hx; h2.y = hy;
    __nv_bfloat162 l2;
    l2.x = __float2bfloat16(v.x - __bfloat162float(hx));
    l2.y = __float2bfloat16(v.y - __bfloat162float(hy));
    *(__nv_bfloat162*)&g_whi[e] = h2;
    *(__nv_bfloat162*)&g_wlo[e] = l2;
}

// ---------------------------------------------------------------------------
// HMMA GEMM (bf16x3), cp.async double-buffered.
// qkv=1: z<2 -> fused L2-norm + split to q/k layout; z==2 -> fused transpose
// + split to V^T layout (smem transpose). else: fp32 out (+bias)(+lrelu).
// ---------------------------------------------------------------------------
#define MM_AHI 0
#define MM_ALO 18432
#define MM_WHI 36864
#define MM_WLO 46080
#define MM_BUF 55296
#define MM_SMEM (2*MM_BUF)

__global__ __launch_bounds__(256) void tcmma(const __nv_bfloat16* __restrict__ Ahi,
                                             const __nv_bfloat16* __restrict__ Alo,
                                             int widx0,
                                             const float* __restrict__ bias,
                                             float* __restrict__ C0,
                                             float* __restrict__ C1,
                                             float* __restrict__ C2,
                                             int act, int qkv)
{
    extern __shared__ char sm[];
    unsigned smb = smem_u32(sm);
    int tid = threadIdx.x;
    int lane = tid & 31;
    int wid = tid >> 5;
    int wm = wid & 3;
    int wn = wid >> 2;
    int m0 = blockIdx.x * 128, n0 = blockIdx.y * 64;
    int z = blockIdx.z;
    const __nv_bfloat16* Whi = g_whi + (size_t)(widx0 + z) * (DD*DD);
    const __nv_bfloat16* Wlo = g_wlo + (size_t)(widx0 + z) * (DD*DD);
    float* C = (z == 0) ? C0 : (z == 1) ? C1 : C2;

    auto stage = [&](int kc, unsigned bo) {
        #pragma unroll
        for (int it = 0; it < 4; it++) {
            int v = tid + it * 256;
            int row = v >> 3, cg = (v & 7) * 8;
            size_t gofs = (size_t)(m0 + row) * 256 + kc * 64 + cg;
            cpa16(smb + bo + MM_AHI + row*144 + cg*2, &Ahi[gofs]);
            cpa16(smb + bo + MM_ALO + row*144 + cg*2, &Alo[gofs]);
        }
        #pragma unroll
        for (int it = 0; it < 2; it++) {
            int v = tid + it * 256;
            int row = v >> 3, cg = (v & 7) * 8;
            size_t gofs = (size_t)(n0 + row) * 256 + kc * 64 + cg;
            cpa16(smb + bo + MM_WHI + row*144 + cg*2, &Whi[gofs]);
            cpa16(smb + bo + MM_WLO + row*144 + cg*2, &Wlo[gofs]);
        }
    };

    float acc[2][4][4];
    #pragma unroll
    for (int a = 0; a < 2; a++)
        #pragma unroll
        for (int b = 0; b < 4; b++)
            #pragma unroll
            for (int c = 0; c < 4; c++) acc[a][b][c] = 0.0f;

    stage(0, 0);
    CPA_COMMIT();

    for (int kc = 0; kc < 4; kc++) {
        CPA_WAIT0();
        __syncthreads();
        unsigned bo = (unsigned)(kc & 1) * MM_BUF;
        if (kc < 3) { stage(kc + 1, bo ^ MM_BUF); CPA_COMMIT(); }

        #pragma unroll
        for (int ks = 0; ks < 4; ks++) {
            int kb = ks * 16;
            unsigned ah[2][4], al[2][4], bh[2][4], bl[2][4];
            #pragma unroll
            for (int mi = 0; mi < 2; mi++) {
                int row = wm*32 + mi*16 + (lane & 15);
                unsigned ad = smb + bo + MM_AHI + row*144 + (kb + ((lane >> 4) << 3)) * 2;
                ldsm4(ah[mi], ad);
                ldsm4(al[mi], ad + (MM_ALO - MM_AHI));
            }
            #pragma unroll
            for (int gi = 0; gi < 2; gi++) {
                int nrow = wn*32 + gi*16 + (lane & 7) + ((lane >> 4) & 1) * 8;
                unsigned bd = smb + bo + MM_WHI + nrow*144 + (kb + (((lane >> 3) & 1) << 3)) * 2;
                ldsm4(bh[gi], bd);
                ldsm4(bl[gi], bd + (MM_WLO - MM_WHI));
            }
            #pragma unroll
            for (int mi = 0; mi < 2; mi++) {
                #pragma unroll
                for (int ni = 0; ni < 4; ni++) {
                    int gi = ni >> 1, hf = (ni & 1) * 2;
                    mma16816(acc[mi][ni], ah[mi], &bh[gi][hf]);
                    mma16816(acc[mi][ni], ah[mi], &bl[gi][hf]);
                    mma16816(acc[mi][ni], al[mi], &bh[gi][hf]);
                }
            }
        }
    }

    if (qkv && z != 2) {
        // fused: per-row L2 norm (warp tile = one head), hi/lo split, [bh][t][32]
        __nv_bfloat16* dsthi = (z == 0) ? g_qh2 : g_kh2;
        __nv_bfloat16* dstlo = (z == 0) ? g_ql2 : g_kl2;
        int head = blockIdx.y * 2 + wn;
        #pragma unroll
        for (int mi = 0; mi < 2; mi++) {
            #pragma unroll
            for (int rr = 0; rr < 2; rr++) {
                float v[8];
                #pragma unroll
                for (int ni = 0; ni < 4; ni++) {
                    v[ni*2]   = acc[mi][ni][rr*2];
                    v[ni*2+1] = acc[mi][ni][rr*2+1];
                }
                float ss = 0.0f;
                #pragma unroll
                for (int j = 0; j < 8; j++) ss = fmaf(v[j], v[j], ss);
                ss += __shfl_xor_sync(0xffffffffu, ss, 1);
                ss += __shfl_xor_sync(0xffffffffu, ss, 2);
                float inv = 1.0f / fmaxf(sqrtf(ss), 1e-12f);
                int row = m0 + wm*32 + mi*16 + rr*8 + (lane >> 2);
                int b = row >> 10, t = row & 1023;
                size_t base = (((size_t)(b*8 + head)) * 1024 + t) * 32 + (lane & 3) * 2;
                #pragma unroll
                for (int ni = 0; ni < 4; ni++) {
                    float v0 = v[ni*2] * inv, v1 = v[ni*2+1] * inv;
                    unsigned hh = cvt2bf(v1, v0);
                    float f0 = __uint_as_float(hh << 16), f1 = __uint_as_float(hh & 0xFFFF0000u);
                    *(unsigned*)&dsthi[base + ni*8] = hh;
                    *(unsigned*)&dstlo[base + ni*8] = cvt2bf(v1 - f1, v0 - f0);
                }
            }
        }
        return;
    }
    if (qkv) {
        // z == 2: V. Transpose via smem, split hi/lo, write [bh][c][t].
        __syncthreads();                 // all warps done with MMA smem reads
        float* sT = (float*)sm;          // [64 cols][132]
        int rbase_l = wm*32 + (lane >> 2);
        int cbase_l = wn*32 + (lane & 3) * 2;
        #pragma unroll
        for (int mi = 0; mi < 2; mi++) {
            #pragma unroll
            for (int ni = 0; ni < 4; ni++) {
                int col = cbase_l + ni*8;
                int row = rbase_l + mi*16;
                sT[(col+0)*132 + row]     = acc[mi][ni][0];
                sT[(col+1)*132 + row]     = acc[mi][ni][1];
                sT[(col+0)*132 + row + 8] = acc[mi][ni][2];
                sT[(col+1)*132 + row + 8] = acc[mi][ni][3];
            }
        }
        __syncthreads();
        int colg = tid >> 2;                  // 0..63
        int tr   = (tid & 3) * 32;            // 32-row run
        int head = blockIdx.y * 2 + (colg >> 5);
        int c    = colg & 31;
        int b    = m0 >> 10;
        size_t o = (((size_t)(b*8 + head)) * 32 + c) * 1024 + (m0 & 1023) + tr;
        const float* srcp = &sT[colg*132 + tr];
        unsigned hp[16], lp[16];
        #pragma unroll
        for (int j = 0; j < 16; j++) {
            float v0 = srcp[2*j], v1 = srcp[2*j+1];
            unsigned hh = cvt2bf(v1, v0);
            float f0 = __uint_as_float(hh << 16), f1 = __uint_as_float(hh & 0xFFFF0000u);
            hp[j] = hh;
            lp[j] = cvt2bf(v1 - f1, v0 - f0);
        }
        #pragma unroll
        for (int j = 0; j < 4; j++) {
            *(uint4*)&g_vthi[o + j*8] = make_uint4(hp[j*4], hp[j*4+1], hp[j*4+2], hp[j*4+3]);
            *(uint4*)&g_vtlo[o + j*8] = make_uint4(lp[j*4], lp[j*4+1], lp[j*4+2], lp[j*4+3]);
        }
        return;
    }

    int rbase = m0 + wm*32 + (lane >> 2);
    int cbase = n0 + wn*32 + (lane & 3) * 2;
    #pragma unroll
    for (int mi = 0; mi < 2; mi++) {
        #pragma unroll
        for (int ni = 0; ni < 4; ni++) {
            int col = cbase + ni*8;
            float b0 = bias ? bias[col] : 0.0f;
            float b1 = bias ? bias[col + 1] : 0.0f;
            float v0 = acc[mi][ni][0] + b0;
            float v1 = acc[mi][ni][1] + b1;
            float v2 = acc[mi][ni][2] + b0;
            float v3 = acc[mi][ni][3] + b1;
            if (act) {
                v0 = (v0 >= 0.0f) ? v0 : 0.01f * v0;
                v1 = (v1 >= 0.0f) ? v1 : 0.01f * v1;
                v2 = (v2 >= 0.0f) ? v2 : 0.01f * v2;
                v3 = (v3 >= 0.0f) ? v3 : 0.01f * v3;
            }
            int row = rbase + mi*16;
            *(float2*)&C[(size_t)row * 256 + col]       = make_float2(v0, v1);
            *(float2*)&C[(size_t)(row + 8) * 256 + col] = make_float2(v2, v3);
        }
    }
}

// ---------------------------------------------------------------------------
// HMMA attention (unchanged from 156us round)
// ---------------------------------------------------------------------------
#define AT_QHI 0
#define AT_QLO 10240
#define AT_KV  20480
#define AT_KVBUF 19456
#define AT_LUT 59392
#define AT_SMEM 60416

__global__ __launch_bounds__(256) void attn_mma_kernel()
{
    extern __shared__ __align__(16) char SM_[];
    unsigned smb = smem_u32(SM_);
    float* sLUT = (float*)(SM_ + AT_LUT);

    int tid = threadIdx.x;
    int lane = tid & 31;
    int wid = tid >> 5;
    int wq = wid & 3;
    int ws = wid >> 2;
    int bh = blockIdx.y, b = bh >> 3, h = bh & 7;
    int t0 = blockIdx.x << 7;

    auto stageKV = [&](int s0, unsigned gb) {
        int row = tid >> 2, cg = (tid & 3) * 8;
        size_t gofs = (((size_t)bh * TT) + s0 + row) * 32 + cg;
        cpa16(smb + gb + 0     + row*80 + cg*2, &g_kh2[gofs]);
        cpa16(smb + gb + 5120  + row*80 + cg*2, &g_kl2[gofs]);
        int c = tid >> 3, sg = (tid & 7) * 8;
        size_t vofs = ((size_t)bh * 32 + c) * 1024 + s0 + sg;
        cpa16(smb + gb + 10240 + c*144 + sg*2, &g_vthi[vofs]);
        cpa16(smb + gb + 14848 + c*144 + sg*2, &g_vtlo[vofs]);
    };

    if (tid < 256) sLUT[tid] = g_lutv[h*256 + tid];
    #pragma unroll
    for (int r2 = 0; r2 < 2; r2++) {
        int row = (tid >> 2) + r2*64, cg = (tid & 3) * 8;
        size_t gofs = (((size_t)bh * TT) + t0 + row) * 32 + cg;
        *(uint4*)(SM_ + AT_QHI + row*80 + cg*2) = *(const uint4*)&g_qh2[gofs];
        *(uint4*)(SM_ + AT_QLO + row*80 + cg*2) = *(const uint4*)&g_ql2[gofs];
    }
    stageKV(0, AT_KV);
    CPA_COMMIT();

    float oacc[2][4][4];
    #pragma unroll
    for (int mi = 0; mi < 2; mi++)
        #pragma unroll
        for (int i = 0; i < 4; i++)
            #pragma unroll
            for (int j = 0; j < 4; j++) oacc[mi][i][j] = 0.0f;
    float zs[2][2] = {{0.f,0.f},{0.f,0.f}};

    int qrow_f = (lane >> 2);
    int ccol_f = (lane & 3) * 2;

    #pragma unroll 1
    for (int st = 0; st < 16; st++) {
        int s0 = st << 6;
        CPA_WAIT0();
        __syncthreads();
        unsigned gb = AT_KV + (unsigned)(st & 1) * AT_KVBUF;
        if (st < 15) { stageKV(s0 + 64, gb == AT_KV ? AT_KV + AT_KVBUF : AT_KV); CPA_COMMIT(); }

        uchar2 md[2][4][2];
        {
            size_t mb = (size_t)b * TT * TT;
            int gcb = s0 + ws*32 + ccol_f;
            #pragma unroll
            for (int mi = 0; mi < 2; mi++) {
                int gr = t0 + wq*32 + mi*16 + qrow_f;
                #pragma unroll
                for (int ni = 0; ni < 4; ni++) {
                    md[mi][ni][0] = *(const uchar2*)&g_mdx[mb + (size_t)gr * TT + gcb + ni*8];
                    md[mi][ni][1] = *(const uchar2*)&g_mdx[mb + (size_t)(gr+8) * TT + gcb + ni*8];
                }
            }
        }

        float sacc[2][4][4];
        #pragma unroll
        for (int mi = 0; mi < 2; mi++)
            #pragma unroll
            for (int i = 0; i < 4; i++)
                #pragma unroll
                for (int j = 0; j < 4; j++) sacc[mi][i][j] = 0.0f;

        #pragma unroll
        for (int ks = 0; ks < 2; ks++) {
            int kb = ks * 16;
            unsigned ah[2][4], al[2][4], bhf[2][4], blf[2][4];
            #pragma unroll
            for (int mi = 0; mi < 2; mi++) {
                int row = wq*32 + mi*16 + (lane & 15);
                unsigned ad = smb + AT_QHI + row*80 + (kb + ((lane >> 4) << 3)) * 2;
                ldsm4(ah[mi], ad);
                ldsm4(al[mi], ad + (AT_QLO - AT_QHI));
            }
            #pragma unroll
            for (int gi = 0; gi < 2; gi++) {
                int nrow = ws*32 + gi*16 + (lane & 7) + ((lane >> 4) & 1) * 8;
                unsigned bd = smb + gb + 0 + nrow*80 + (kb + (((lane >> 3) & 1) << 3)) * 2;
                ldsm4(bhf[gi], bd);
                ldsm4(blf[gi], bd + 5120);
            }
            #pragma unroll
            for (int mi = 0; mi < 2; mi++) {
                #pragma unroll
                for (int ni = 0; ni < 4; ni++) {
                    int gi = ni >> 1, hf = (ni & 1) * 2;
                    mma16816(sacc[mi][ni], ah[mi], &bhf[gi][hf]);
                    mma16816(sacc[mi][ni], ah[mi], &blf[gi][hf]);
                    mma16816(sacc[mi][ni], al[mi], &bhf[gi][hf]);
                }
            }
        }

        unsigned phi[2][8], plo[2][8];
        #pragma unroll
        for (int mi = 0; mi < 2; mi++) {
            #pragma unroll
            for (int ni = 0; ni < 4; ni++) {
                uchar2 m0 = md[mi][ni][0], m1 = md[mi][ni][1];
                float z0 = (m0.x == 255) ? 0.0f : __expf(sacc[mi][ni][0] + sLUT[m0.x]);
                float z1 = (m0.y == 255) ? 0.0f : __expf(sacc[mi][ni][1] + sLUT[m0.y]);
                float z2 = (m1.x == 255) ? 0.0f : __expf(sacc[mi][ni][2] + sLUT[m1.x]);
                float z3 = (m1.y == 255) ? 0.0f : __expf(sacc[mi][ni][3] + sLUT[m1.y]);
                zs[mi][0] += z0 + z1;
                zs[mi][1] += z2 + z3;
                unsigned p01 = cvt2bf(z1, z0);
                unsigned p23 = cvt2bf(z3, z2);
                phi[mi][ni*2]   = p01;
                phi[mi][ni*2+1] = p23;
                float f0 = __uint_as_float(p01 << 16), f1 = __uint_as_float(p01 & 0xFFFF0000u);
                float f2 = __uint_as_float(p23 << 16), f3 = __uint_as_float(p23 & 0xFFFF0000u);
                plo[mi][ni*2]   = cvt2bf(z1 - f1, z0 - f0);
                plo[mi][ni*2+1] = cvt2bf(z3 - f3, z2 - f2);
            }
        }

        #pragma unroll
        for (int kf = 0; kf < 2; kf++) {
            unsigned vbh[2][4], vbl[2][4];
            #pragma unroll
            for (int gi = 0; gi < 2; gi++) {
                int nrow = gi*16 + (lane & 7) + ((lane >> 4) & 1) * 8;
                int col = ws*32 + kf*16 + (((lane >> 3) & 1) << 3);
                unsigned bd = smb + gb + 10240 + nrow*144 + col*2;
                ldsm4(vbh[gi], bd);
                ldsm4(vbl[gi], bd + 4608);
            }
            #pragma unroll
            for (int mi = 0; mi < 2; mi++) {
                #pragma unroll
                for (int ni = 0; ni < 4; ni++) {
                    int gi = ni >> 1, hf = (ni & 1) * 2;
                    mma16816(oacc[mi][ni], &phi[mi][4*kf], &vbh[gi][hf]);
                    mma16816(oacc[mi][ni], &plo[mi][4*kf], &vbh[gi][hf]);
                    mma16816(oacc[mi][ni], &phi[mi][4*kf], &vbl[gi][hf]);
                }
            }
        }
    }

    #pragma unroll
    for (int mi = 0; mi < 2; mi++) {
        zs[mi][0] += __shfl_xor_sync(0xffffffffu, zs[mi][0], 1);
        zs[mi][0] += __shfl_xor_sync(0xffffffffu, zs[mi][0], 2);
        zs[mi][1] += __shfl_xor_sync(0xffffffffu, zs[mi][1], 1);
        zs[mi][1] += __shfl_xor_sync(0xffffffffu, zs[mi][1], 2);
    }
    __syncthreads();

    float* sO  = (float*)(SM_ + 0);        // [128][34]
    float* sRS = (float*)(SM_ + 18432);    // [128]
    if (ws == 1) {
        #pragma unroll
        for (int mi = 0; mi < 2; mi++) {
            int r = wq*32 + mi*16 + qrow_f;
            if ((lane & 3) == 0) {
                sRS[r]     = zs[mi][0];
                sRS[r + 8] = zs[mi][1];
            }
            #pragma unroll
            for (int ni = 0; ni < 4; ni++) {
                int c = ni*8 + ccol_f;
                *(float2*)&sO[r*34 + c]     = make_float2(oacc[mi][ni][0], oacc[mi][ni][1]);
                *(float2*)&sO[(r+8)*34 + c] = make_float2(oacc[mi][ni][2], oacc[mi][ni][3]);
            }
        }
    }
    __syncthreads();
    if (ws == 0) {
        #pragma unroll
        for (int mi = 0; mi < 2; mi++) {
            int r = wq*32 + mi*16 + qrow_f;
            float inv0 = 1.0f / (zs[mi][0] + sRS[r]     + 1e-5f);
            float inv8 = 1.0f / (zs[mi][1] + sRS[r + 8] + 1e-5f);
            size_t o0 = ((size_t)b * TT + t0 + r)     * DD + h * 32;
            size_t o8 = ((size_t)b * TT + t0 + r + 8) * DD + h * 32;
            #pragma unroll
            for (int ni = 0; ni < 4; ni++) {
                int c = ni*8 + ccol_f;
                float2 p0 = *(const float2*)&sO[r*34 + c];
                float2 p8 = *(const float2*)&sO[(r+8)*34 + c];
                float v0 = (oacc[mi][ni][0] + p0.x) * inv0;
                float v1 = (oacc[mi][ni][1] + p0.y) * inv0;
                float v2 = (oacc[mi][ni][2] + p8.x) * inv8;
                float v3 = (oacc[mi][ni][3] + p8.y) * inv8;
                unsigned h0 = cvt2bf(v1, v0);
                unsigned h8 = cvt2bf(v3, v2);
                float f0 = __uint_as_float(h0 << 16), f1 = __uint_as_float(h0 & 0xFFFF0000u);
                float f2 = __uint_as_float(h8 << 16), f3 = __uint_as_float(h8 & 0xFFFF0000u);
                *(unsigned*)&g_athi[o0 + c] = h0;
                *(unsigned*)&g_atlo[o0 + c] = cvt2bf(v1 - f1, v0 - f0);
                *(unsigned*)&g_athi[o8 + c] = h8;
                *(unsigned*)&g_atlo[o8 + c] = cvt2bf(v3 - f3, v2 - f2);
            }
        }
    }
}

__global__ __launch_bounds__(256) void ln_kernel(const float* __restrict__ a,
                                                 const float* __restrict__ b,
                                                 const float* __restrict__ g,
                                                 const float* __restrict__ be,
                                                 float* __restrict__ out,
                                                 int dosplit)
{
    int w    = (blockIdx.x * 256 + threadIdx.x) >> 5;
    int lane = threadIdx.x & 31;
    const float* ap = a + (size_t)w * 256;
    const float* bp = b + (size_t)w * 256;
    float v[8]; float s = 0.0f;
    #pragma unroll
    for (int u = 0; u < 8; u++) { v[u] = ap[lane + 32*u] + bp[lane + 32*u]; s += v[u]; }
    #pragma unroll
    for (int off = 16; off; off >>= 1) s += __shfl_xor_sync(0xffffffffu, s, off);
    float mu = s * (1.0f / 256.0f);
    float vs = 0.0f;
    #pragma unroll
    for (int u = 0; u < 8; u++) { float d = v[u] - mu; vs = fmaf(d, d, vs); }
    #pragma unroll
    for (int off = 16; off; off >>= 1) vs += __shfl_xor_sync(0xffffffffu, vs, off);
    float rstd = rsqrtf(vs * (1.0f / 256.0f) + 1e-5f);
    #pragma unroll
    for (int u = 0; u < 8; u++) {
        int col = lane + 32*u;
        float o = (v[u] - mu) * rstd * g[col] + be[col];
        out[(size_t)w * 256 + col] = o;
        if (dosplit) {
            __nv_bfloat16 hh = __float2bfloat16(o);
            g_zhi[(size_t)w * 256 + col] = hh;
            g_zlo[(size_t)w * 256 + col] = __float2bfloat16(o - __bfloat162float(hh));
        }
    }
}

extern "C" void kernel_launch(void* const* d_in, const int* in_sizes, int n_in,
                              void* d_out, int out_size)
{
    const float* x    = (const float*)d_in[0];
    const void*  mask = d_in[1];
    const float* rel  = (const float*)d_in[2];
    const float* pw1  = (const float*)d_in[6];
    const float* pb1  = (const float*)d_in[7];
    const float* pw2  = (const float*)d_in[8];
    const float* pb2  = (const float*)d_in[9];
    const float* bo   = (const float*)d_in[11];
    const float* bfv  = (const float*)d_in[13];
    const float* g1   = (const float*)d_in[14];
    const float* be1  = (const float*)d_in[15];
    const float* g2   = (const float*)d_in[16];
    const float* be2  = (const float*)d_in[17];

    float *qraw, *y, *zz;
    __nv_bfloat16 *xhi, *xlo, *athi, *atlo, *zhi, *zlo;
    cudaGetSymbolAddress((void**)&qraw, g_qraw);
    cudaGetSymbolAddress((void**)&y,    g_y);
    cudaGetSymbolAddress((void**)&zz,   g_zz);
    cudaGetSymbolAddress((void**)&xhi,  g_xhi);
    cudaGetSymbolAddress((void**)&xlo,  g_xlo);
    cudaGetSymbolAddress((void**)&athi, g_athi);
    cudaGetSymbolAddress((void**)&atlo, g_atlo);
    cudaGetSymbolAddress((void**)&zhi,  g_zhi);
    cudaGetSymbolAddress((void**)&zlo,  g_zlo);

    cudaFuncSetAttribute(tcmma, cudaFuncAttributeMaxDynamicSharedMemorySize, MM_SMEM);
    cudaFuncSetAttribute(attn_mma_kernel, cudaFuncAttributeMaxDynamicSharedMemorySize, AT_SMEM);

    lut_all<<<8, 256>>>(pw1, pb1, pw2, pb2);
    detect_kernel<<<256, 256>>>((const unsigned*)mask);
    maskfuse_kernel<<<4096, 256>>>(rel, mask);
    splitw_kernel<<<640, 256>>>((const float*)d_in[3], (const float*)d_in[4],
                                (const float*)d_in[5], (const float*)d_in[10],
                                (const float*)d_in[12]);
    split_kernel<<<2048, 256>>>(x, xhi, xlo);

    // QKV: q,k fused normalize+split; v fused transpose+split (no vtrans kernel)
    tcmma<<<dim3(32, 4, 3), 256, MM_SMEM>>>(xhi, xlo, 0, nullptr, qraw, qraw, qraw, 0, 1);

    attn_mma_kernel<<<dim3(8, 32), 256, AT_SMEM>>>();

    tcmma<<<dim3(32, 4, 1), 256, MM_SMEM>>>(athi, atlo, 3, bo, y, y, y, 0, 0);
    ln_kernel<<<512, 256>>>(x, y, g1, be1, zz, 1);
    tcmma<<<dim3(32, 4, 1), 256, MM_SMEM>>>(zhi, zlo, 4, bfv, qraw, qraw, qraw, 1, 0);
    ln_kernel<<<512, 256>>>(zz, qraw, g2, be2, (float*)d_out, 0);
}

// round 13
// speedup vs baseline: 2.7194x; 1.0429x over previous
#include <cuda_runtime.h>
#include <cuda_bf16.h>

#define BB  4
#define TT  1024
#define DD  256
#define HH  8
#define CC  16
#define BT  (BB*TT)

typedef unsigned long long ull;

__device__ __forceinline__ unsigned smem_u32(const void* p) {
    unsigned a;
    asm("{ .reg .u64 t; cvta.to.shared.u64 t, %1; cvt.u32.u64 %0, t; }" : "=r"(a) : "l"(p));
    return a;
}
__device__ __forceinline__ void ldsm4(unsigned* r, unsigned addr) {
    asm volatile("ldmatrix.sync.aligned.m8n8.x4.shared.b16 {%0,%1,%2,%3}, [%4];"
                 : "=r"(r[0]), "=r"(r[1]), "=r"(r[2]), "=r"(r[3]) : "r"(addr));
}
__device__ __forceinline__ void mma16816(float* c, const unsigned* a, const unsigned* b) {
    asm volatile("mma.sync.aligned.m16n8k16.row.col.f32.bf16.bf16.f32 "
                 "{%0,%1,%2,%3}, {%4,%5,%6,%7}, {%8,%9}, {%0,%1,%2,%3};"
                 : "+f"(c[0]), "+f"(c[1]), "+f"(c[2]), "+f"(c[3])
                 : "r"(a[0]), "r"(a[1]), "r"(a[2]), "r"(a[3]), "r"(b[0]), "r"(b[1]));
}
__device__ __forceinline__ unsigned cvt2bf(float hi, float lo) {
    unsigned r;
    asm("cvt.rn.bf16x2.f32 %0, %1, %2;" : "=r"(r) : "f"(hi), "f"(lo));
    return r;
}
__device__ __forceinline__ void cpa16(unsigned dst, const void* src) {
    asm volatile("cp.async.cg.shared.global [%0], [%1], 16;" :: "r"(dst), "l"(src));
}
#define CPA_COMMIT() asm volatile("cp.async.commit_group;" ::: "memory")
#define CPA_WAIT0()  asm volatile("cp.async.wait_group 0;" ::: "memory")

// ---------------- scratch ----------------
__device__ float g_qraw[BT*DD];          // FFN scratch
__device__ float g_y[BT*DD];
__device__ float g_zz[BT*DD];
__device__ unsigned char g_mdx[BB*TT*TT];   // u8: 255=masked, else idx 0..254
__device__ float g_lutv[HH*256];
__device__ int   g_mask_flags;
__device__ __nv_bfloat16 g_xhi[BT*DD],  g_xlo[BT*DD];
__device__ __nv_bfloat16 g_athi[BT*DD], g_atlo[BT*DD];
__device__ __nv_bfloat16 g_zhi[BT*DD],  g_zlo[BT*DD];
__device__ __nv_bfloat16 g_whi[5*DD*DD], g_wlo[5*DD*DD];
__device__ __nv_bfloat16 g_vthi[32*HH*BB*TT], g_vtlo[32*HH*BB*TT]; // [bh][32][1024]
__device__ __nv_bfloat16 g_qh2[HH*BB*TT*32], g_ql2[HH*BB*TT*32];   // [bh][t][32]
__device__ __nv_bfloat16 g_kh2[HH*BB*TT*32], g_kl2[HH*BB*TT*32];

// ---------------------------------------------------------------------------
// Merged coef + LUT build. One block per head; block 0 zeroes mask flags.
// ---------------------------------------------------------------------------
__global__ void lut_all(const float* __restrict__ pw1, const float* __restrict__ pb1,
                        const float* __restrict__ pw2, const float* __restrict__ pb2)
{
    __shared__ float sc[34];
    int h = blockIdx.x;
    int t = threadIdx.x;
    if (h == 0 && t == 0) g_mask_flags = 0;
    if (t < 16) {
        float w1 = pw1[h*CC + t], b1 = pb1[h*CC + t], w2 = pw2[h*CC + t];
        float beta, delta, k0add, k1add;
        if (w1 != 0.0f) {
            beta  = 0.495f * w2 * fabsf(w1);
            delta = -b1 / w1;
            k0add = 0.505f * w2 * b1;
            k1add = 0.505f * w2 * w1;
        } else {
            beta = 0.0f; delta = 0.0f;
            k0add = w2 * (0.505f * b1 + 0.495f * fabsf(b1));
            k1add = 0.0f;
        }
        #pragma unroll
        for (int off = 1; off < 16; off <<= 1) {
            k0add += __shfl_xor_sync(0x0000FFFFu, k0add, off);
            k1add += __shfl_xor_sync(0x0000FFFFu, k1add, off);
        }
        sc[2 + t]  = beta;
        sc[18 + t] = delta;
        if (t == 0) {
            sc[0] = pb2[h] + k0add;
            sc[1] = k1add;
        }
    }
    __syncthreads();
    if (t == 255) { g_lutv[h*256 + 255] = 0.0f; return; }
    float m = (t + 0.5f) * (1.0f / 255.0f);
    float v = sc[0] + sc[1] * m;
    #pragma unroll
    for (int c = 0; c < 16; c++)
        v += sc[2 + c] * fabsf(m - sc[18 + c]);
    g_lutv[h*256 + t] = -v;
}

__global__ void detect_kernel(const unsigned* __restrict__ w)
{
    int i = blockIdx.x * blockDim.x + threadIdx.x;
    unsigned x = w[i];
    int f = 0;
    if (x == 0x3F800000u)               f = 2;
    else if ((x & 0xFFFFu) == 0x3F80u)  f = 4;
    else if (x > 1u)                    f = 1;
    if (f) atomicOr(&g_mask_flags, f);
}

__global__ __launch_bounds__(256) void maskfuse_kernel(const float* __restrict__ rd,
                                                       const void* __restrict__ maskp)
{
    int i = blockIdx.x * 256 + threadIdx.x;
    size_t base = (size_t)i * 4;
    int mf = g_mask_flags;
    int mode = (mf & 4) ? 3 : (mf & 2) ? 2 : (mf & 1) ? 1 : 0;
    float4 d4 = *(const float4*)&rd[base];
    int m0, m1, m2, m3;
    if (mode == 0) {
        int4 m = *(const int4*)((const int*)maskp + base);
        m0 = m.x != 0; m1 = m.y != 0; m2 = m.z != 0; m3 = m.w != 0;
    } else if (mode == 1) {
        uchar4 m = *(const uchar4*)((const unsigned char*)maskp + base);
        m0 = m.x != 0; m1 = m.y != 0; m2 = m.z != 0; m3 = m.w != 0;
    } else if (mode == 2) {
        float4 m = *(const float4*)((const float*)maskp + base);
        m0 = m.x != 0.0f; m1 = m.y != 0.0f; m2 = m.z != 0.0f; m3 = m.w != 0.0f;
    } else {
        ushort4 m = *(const ushort4*)((const unsigned short*)maskp + base);
        m0 = m.x != 0; m1 = m.y != 0; m2 = m.z != 0; m3 = m.w != 0;
    }
    int i0 = min(max(__float2int_rd(d4.x * 255.0f), 0), 254);
    int i1 = min(max(__float2int_rd(d4.y * 255.0f), 0), 254);
    int i2 = min(max(__float2int_rd(d4.z * 255.0f), 0), 254);
    int i3 = min(max(__float2int_rd(d4.w * 255.0f), 0), 254);
    uchar4 o;
    o.x = (unsigned char)(m0 ? 255 : i0);
    o.y = (unsigned char)(m1 ? 255 : i1);
    o.z = (unsigned char)(m2 ? 255 : i2);
    o.w = (unsigned char)(m3 ? 255 : i3);
    *(uchar4*)&g_mdx[base] = o;
}

// ---------------------------------------------------------------------------
// Merged split: blocks [0,640) split the 5 weight matrices into g_whi/g_wlo;
// blocks [640,2688) split x into g_xhi/g_xlo.
// ---------------------------------------------------------------------------
__global__ __launch_bounds__(256) void prep_split(const float* __restrict__ x,
                                                  const float* __restrict__ w0,
                                                  const float* __restrict__ w1,
                                                  const float* __restrict__ w2,
                                                  const float* __restrict__ w3,
                                                  const float* __restrict__ w4)
{
    const float* src;
    __nv_bfloat16 *hi, *lo;
    size_t e;
    if (blockIdx.x < 640) {
        int i = blockIdx.x * 256 + threadIdx.x;
        e = (size_t)i * 2;
        int w = (int)(e >> 16);
        size_t off = e & 65535;
        src = ((w == 0) ? w0 : (w == 1) ? w1 : (w == 2) ? w2 : (w == 3) ? w3 : w4) + off - e;
        hi = g_whi; lo = g_wlo;
    } else {
        int i = (blockIdx.x - 640) * 256 + threadIdx.x;
        e = (size_t)i * 2;
        src = x;
        hi = g_xhi; lo = g_xlo;
    }
    float2 v = *(const float2*)&src[e];
    __nv_bfloat16 hx = __float2bfloat16(v.x), hy = __float2bfloat16(v.y);
    __nv_bfloat162 h2; h2.x = hx; h2.y = hy;
    __nv_bfloat162 l2;
    l2.x = __float2bfloat16(v.x - __bfloat162float(hx));
    l2.y = __float2bfloat16(v.y - __bfloat162float(hy));
    *(__nv_bfloat162*)&hi[e] = h2;
    *(__nv_bfloat162*)&lo[e] = l2;
}

// ---------------------------------------------------------------------------
// HMMA GEMM (bf16x3), cp.async double-buffered.
// qkv=1: z<2 -> fused L2-norm + split to q/k layout; z==2 -> fused transpose
// + split to V^T layout (smem transpose). else: fp32 out (+bias)(+lrelu).
// ---------------------------------------------------------------------------
#define MM_AHI 0
#define MM_ALO 18432
#define MM_WHI 36864
#define MM_WLO 46080
#define MM_BUF 55296
#define MM_SMEM (2*MM_BUF)

__global__ __launch_bounds__(256) void tcmma(const __nv_bfloat16* __restrict__ Ahi,
                                             const __nv_bfloat16* __restrict__ Alo,
                                             int widx0,
                                             const float* __restrict__ bias,
                                             float* __restrict__ C0,
                                             float* __restrict__ C1,
                                             float* __restrict__ C2,
                                             int act, int qkv)
{
    extern __shared__ char sm[];
    unsigned smb = smem_u32(sm);
    int tid = threadIdx.x;
    int lane = tid & 31;
    int wid = tid >> 5;
    int wm = wid & 3;
    int wn = wid >> 2;
    int m0 = blockIdx.x * 128, n0 = blockIdx.y * 64;
    int z = blockIdx.z;
    const __nv_bfloat16* Whi = g_whi + (size_t)(widx0 + z) * (DD*DD);
    const __nv_bfloat16* Wlo = g_wlo + (size_t)(widx0 + z) * (DD*DD);
    float* C = (z == 0) ? C0 : (z == 1) ? C1 : C2;

    auto stage = [&](int kc, unsigned bo) {
        #pragma unroll
        for (int it = 0; it < 4; it++) {
            int v = tid + it * 256;
            int row = v >> 3, cg = (v & 7) * 8;
            size_t gofs = (size_t)(m0 + row) * 256 + kc * 64 + cg;
            cpa16(smb + bo + MM_AHI + row*144 + cg*2, &Ahi[gofs]);
            cpa16(smb + bo + MM_ALO + row*144 + cg*2, &Alo[gofs]);
        }
        #pragma unroll
        for (int it = 0; it < 2; it++) {
            int v = tid + it * 256;
            int row = v >> 3, cg = (v & 7) * 8;
            size_t gofs = (size_t)(n0 + row) * 256 + kc * 64 + cg;
            cpa16(smb + bo + MM_WHI + row*144 + cg*2, &Whi[gofs]);
            cpa16(smb + bo + MM_WLO + row*144 + cg*2, &Wlo[gofs]);
        }
    };

    float acc[2][4][4];
    #pragma unroll
    for (int a = 0; a < 2; a++)
        #pragma unroll
        for (int b = 0; b < 4; b++)
            #pragma unroll
            for (int c = 0; c < 4; c++) acc[a][b][c] = 0.0f;

    stage(0, 0);
    CPA_COMMIT();

    for (int kc = 0; kc < 4; kc++) {
        CPA_WAIT0();
        __syncthreads();
        unsigned bo = (unsigned)(kc & 1) * MM_BUF;
        if (kc < 3) { stage(kc + 1, bo ^ MM_BUF); CPA_COMMIT(); }

        #pragma unroll
        for (int ks = 0; ks < 4; ks++) {
            int kb = ks * 16;
            unsigned ah[2][4], al[2][4], bh[2][4], bl[2][4];
            #pragma unroll
            for (int mi = 0; mi < 2; mi++) {
                int row = wm*32 + mi*16 + (lane & 15);
                unsigned ad = smb + bo + MM_AHI + row*144 + (kb + ((lane >> 4) << 3)) * 2;
                ldsm4(ah[mi], ad);
                ldsm4(al[mi], ad + (MM_ALO - MM_AHI));
            }
            #pragma unroll
            for (int gi = 0; gi < 2; gi++) {
                int nrow = wn*32 + gi*16 + (lane & 7) + ((lane >> 4) & 1) * 8;
                unsigned bd = smb + bo + MM_WHI + nrow*144 + (kb + (((lane >> 3) & 1) << 3)) * 2;
                ldsm4(bh[gi], bd);
                ldsm4(bl[gi], bd + (MM_WLO - MM_WHI));
            }
            #pragma unroll
            for (int mi = 0; mi < 2; mi++) {
                #pragma unroll
                for (int ni = 0; ni < 4; ni++) {
                    int gi = ni >> 1, hf = (ni & 1) * 2;
                    mma16816(acc[mi][ni], ah[mi], &bh[gi][hf]);
                    mma16816(acc[mi][ni], ah[mi], &bl[gi][hf]);
                    mma16816(acc[mi][ni], al[mi], &bh[gi][hf]);
                }
            }
        }
    }

    if (qkv && z != 2) {
        __nv_bfloat16* dsthi = (z == 0) ? g_qh2 : g_kh2;
        __nv_bfloat16* dstlo = (z == 0) ? g_ql2 : g_kl2;
        int head = blockIdx.y * 2 + wn;
        #pragma unroll
        for (int mi = 0; mi < 2; mi++) {
            #pragma unroll
            for (int rr = 0; rr < 2; rr++) {
                float v[8];
                #pragma unroll
                for (int ni = 0; ni < 4; ni++) {
                    v[ni*2]   = acc[mi][ni][rr*2];
                    v[ni*2+1] = acc[mi][ni][rr*2+1];
                }
                float ss = 0.0f;
                #pragma unroll
                for (int j = 0; j < 8; j++) ss = fmaf(v[j], v[j], ss);
                ss += __shfl_xor_sync(0xffffffffu, ss, 1);
                ss += __shfl_xor_sync(0xffffffffu, ss, 2);
                float inv = 1.0f / fmaxf(sqrtf(ss), 1e-12f);
                int row = m0 + wm*32 + mi*16 + rr*8 + (lane >> 2);
                int b = row >> 10, t = row & 1023;
                size_t base = (((size_t)(b*8 + head)) * 1024 + t) * 32 + (lane & 3) * 2;
                #pragma unroll
                for (int ni = 0; ni < 4; ni++) {
                    float v0 = v[ni*2] * inv, v1 = v[ni*2+1] * inv;
                    unsigned hh = cvt2bf(v1, v0);
                    float f0 = __uint_as_float(hh << 16), f1 = __uint_as_float(hh & 0xFFFF0000u);
                    *(unsigned*)&dsthi[base + ni*8] = hh;
                    *(unsigned*)&dstlo[base + ni*8] = cvt2bf(v1 - f1, v0 - f0);
                }
            }
        }
        return;
    }
    if (qkv) {
        __syncthreads();
        float* sT = (float*)sm;          // [64 cols][132]
        int rbase_l = wm*32 + (lane >> 2);
        int cbase_l = wn*32 + (lane & 3) * 2;
        #pragma unroll
        for (int mi = 0; mi < 2; mi++) {
            #pragma unroll
            for (int ni = 0; ni < 4; ni++) {
                int col = cbase_l + ni*8;
                int row = rbase_l + mi*16;
                sT[(col+0)*132 + row]     = acc[mi][ni][0];
                sT[(col+1)*132 + row]     = acc[mi][ni][1];
                sT[(col+0)*132 + row + 8] = acc[mi][ni][2];
                sT[(col+1)*132 + row + 8] = acc[mi][ni][3];
            }
        }
        __syncthreads();
        int colg = tid >> 2;
        int tr   = (tid & 3) * 32;
        int head = blockIdx.y * 2 + (colg >> 5);
        int c    = colg & 31;
        int b    = m0 >> 10;
        size_t o = (((size_t)(b*8 + head)) * 32 + c) * 1024 + (m0 & 1023) + tr;
        const float* srcp = &sT[colg*132 + tr];
        unsigned hp[16], lp[16];
        #pragma unroll
        for (int j = 0; j < 16; j++) {
            float v0 = srcp[2*j], v1 = srcp[2*j+1];
            unsigned hh = cvt2bf(v1, v0);
            float f0 = __uint_as_float(hh << 16), f1 = __uint_as_float(hh & 0xFFFF0000u);
            hp[j] = hh;
            lp[j] = cvt2bf(v1 - f1, v0 - f0);
        }
        #pragma unroll
        for (int j = 0; j < 4; j++) {
            *(uint4*)&g_vthi[o + j*8] = make_uint4(hp[j*4], hp[j*4+1], hp[j*4+2], hp[j*4+3]);
            *(uint4*)&g_vtlo[o + j*8] = make_uint4(lp[j*4], lp[j*4+1], lp[j*4+2], lp[j*4+3]);
        }
        return;
    }

    int rbase = m0 + wm*32 + (lane >> 2);
    int cbase = n0 + wn*32 + (lane & 3) * 2;
    #pragma unroll
    for (int mi = 0; mi < 2; mi++) {
        #pragma unroll
        for (int ni = 0; ni < 4; ni++) {
            int col = cbase + ni*8;
            float b0 = bias ? bias[col] : 0.0f;
            float b1 = bias ? bias[col + 1] : 0.0f;
            float v0 = acc[mi][ni][0] + b0;
            float v1 = acc[mi][ni][1] + b1;
            float v2 = acc[mi][ni][2] + b0;
            float v3 = acc[mi][ni][3] + b1;
            if (act) {
                v0 = (v0 >= 0.0f) ? v0 : 0.01f * v0;
                v1 = (v1 >= 0.0f) ? v1 : 0.01f * v1;
                v2 = (v2 >= 0.0f) ? v2 : 0.01f * v2;
                v3 = (v3 >= 0.0f) ? v3 : 0.01f * v3;
            }
            int row = rbase + mi*16;
            *(float2*)&C[(size_t)row * 256 + col]       = make_float2(v0, v1);
            *(float2*)&C[(size_t)(row + 8) * 256 + col] = make_float2(v2, v3);
        }
    }
}

// ---------------------------------------------------------------------------
// HMMA attention (unchanged)
// ---------------------------------------------------------------------------
#define AT_QHI 0
#define AT_QLO 10240
#define AT_KV  20480
#define AT_KVBUF 19456
#define AT_LUT 59392
#define AT_SMEM 60416

__global__ __launch_bounds__(256) void attn_mma_kernel()
{
    extern __shared__ __align__(16) char SM_[];
    unsigned smb = smem_u32(SM_);
    float* sLUT = (float*)(SM_ + AT_LUT);

    int tid = threadIdx.x;
    int lane = tid & 31;
    int wid = tid >> 5;
    int wq = wid & 3;
    int ws = wid >> 2;
    int bh = blockIdx.y, b = bh >> 3, h = bh & 7;
    int t0 = blockIdx.x << 7;

    auto stageKV = [&](int s0, unsigned gb) {
        int row = tid >> 2, cg = (tid & 3) * 8;
        size_t gofs = (((size_t)bh * TT) + s0 + row) * 32 + cg;
        cpa16(smb + gb + 0     + row*80 + cg*2, &g_kh2[gofs]);
        cpa16(smb + gb + 5120  + row*80 + cg*2, &g_kl2[gofs]);
        int c = tid >> 3, sg = (tid & 7) * 8;
        size_t vofs = ((size_t)bh * 32 + c) * 1024 + s0 + sg;
        cpa16(smb + gb + 10240 + c*144 + sg*2, &g_vthi[vofs]);
        cpa16(smb + gb + 14848 + c*144 + sg*2, &g_vtlo[vofs]);
    };

    if (tid < 256) sLUT[tid] = g_lutv[h*256 + tid];
    #pragma unroll
    for (int r2 = 0; r2 < 2; r2++) {
        int row = (tid >> 2) + r2*64, cg = (tid & 3) * 8;
        size_t gofs = (((size_t)bh * TT) + t0 + row) * 32 + cg;
        *(uint4*)(SM_ + AT_QHI + row*80 + cg*2) = *(const uint4*)&g_qh2[gofs];
        *(uint4*)(SM_ + AT_QLO + row*80 + cg*2) = *(const uint4*)&g_ql2[gofs];
    }
    stageKV(0, AT_KV);
    CPA_COMMIT();

    float oacc[2][4][4];
    #pragma unroll
    for (int mi = 0; mi < 2; mi++)
        #pragma unroll
        for (int i = 0; i < 4; i++)
            #pragma unroll
            for (int j = 0; j < 4; j++) oacc[mi][i][j] = 0.0f;
    float zs[2][2] = {{0.f,0.f},{0.f,0.f}};

    int qrow_f = (lane >> 2);
    int ccol_f = (lane & 3) * 2;

    #pragma unroll 1
    for (int st = 0; st < 16; st++) {
        int s0 = st << 6;
        CPA_WAIT0();
        __syncthreads();
        unsigned gb = AT_KV + (unsigned)(st & 1) * AT_KVBUF;
        if (st < 15) { stageKV(s0 + 64, gb == AT_KV ? AT_KV + AT_KVBUF : AT_KV); CPA_COMMIT(); }

        uchar2 md[2][4][2];
        {
            size_t mb = (size_t)b * TT * TT;
            int gcb = s0 + ws*32 + ccol_f;
            #pragma unroll
            for (int mi = 0; mi < 2; mi++) {
                int gr = t0 + wq*32 + mi*16 + qrow_f;
                #pragma unroll
                for (int ni = 0; ni < 4; ni++) {
                    md[mi][ni][0] = *(const uchar2*)&g_mdx[mb + (size_t)gr * TT + gcb + ni*8];
                    md[mi][ni][1] = *(const uchar2*)&g_mdx[mb + (size_t)(gr+8) * TT + gcb + ni*8];
                }
            }
        }

        float sacc[2][4][4];
        #pragma unroll
        for (int mi = 0; mi < 2; mi++)
            #pragma unroll
            for (int i = 0; i < 4; i++)
                #pragma unroll
                for (int j = 0; j < 4; j++) sacc[mi][i][j] = 0.0f;

        #pragma unroll
        for (int ks = 0; ks < 2; ks++) {
            int kb = ks * 16;
            unsigned ah[2][4], al[2][4], bhf[2][4], blf[2][4];
            #pragma unroll
            for (int mi = 0; mi < 2; mi++) {
                int row = wq*32 + mi*16 + (lane & 15);
                unsigned ad = smb + AT_QHI + row*80 + (kb + ((lane >> 4) << 3)) * 2;
                ldsm4(ah[mi], ad);
                ldsm4(al[mi], ad + (AT_QLO - AT_QHI));
            }
            #pragma unroll
            for (int gi = 0; gi < 2; gi++) {
                int nrow = ws*32 + gi*16 + (lane & 7) + ((lane >> 4) & 1) * 8;
                unsigned bd = smb + gb + 0 + nrow*80 + (kb + (((lane >> 3) & 1) << 3)) * 2;
                ldsm4(bhf[gi], bd);
                ldsm4(blf[gi], bd + 5120);
            }
            #pragma unroll
            for (int mi = 0; mi < 2; mi++) {
                #pragma unroll
                for (int ni = 0; ni < 4; ni++) {
                    int gi = ni >> 1, hf = (ni & 1) * 2;
                    mma16816(sacc[mi][ni], ah[mi], &bhf[gi][hf]);
                    mma16816(sacc[mi][ni], ah[mi], &blf[gi][hf]);
                    mma16816(sacc[mi][ni], al[mi], &bhf[gi][hf]);
                }
            }
        }

        unsigned phi[2][8], plo[2][8];
        #pragma unroll
        for (int mi = 0; mi < 2; mi++) {
            #pragma unroll
            for (int ni = 0; ni < 4; ni++) {
                uchar2 m0 = md[mi][ni][0], m1 = md[mi][ni][1];
                float z0 = (m0.x == 255) ? 0.0f : __expf(sacc[mi][ni][0] + sLUT[m0.x]);
                float z1 = (m0.y == 255) ? 0.0f : __expf(sacc[mi][ni][1] + sLUT[m0.y]);
                float z2 = (m1.x == 255) ? 0.0f : __expf(sacc[mi][ni][2] + sLUT[m1.x]);
                float z3 = (m1.y == 255) ? 0.0f : __expf(sacc[mi][ni][3] + sLUT[m1.y]);
                zs[mi][0] += z0 + z1;
                zs[mi][1] += z2 + z3;
                unsigned p01 = cvt2bf(z1, z0);
                unsigned p23 = cvt2bf(z3, z2);
                phi[mi][ni*2]   = p01;
                phi[mi][ni*2+1] = p23;
                float f0 = __uint_as_float(p01 << 16), f1 = __uint_as_float(p01 & 0xFFFF0000u);
                float f2 = __uint_as_float(p23 << 16), f3 = __uint_as_float(p23 & 0xFFFF0000u);
                plo[mi][ni*2]   = cvt2bf(z1 - f1, z0 - f0);
                plo[mi][ni*2+1] = cvt2bf(z3 - f3, z2 - f2);
            }
        }

        #pragma unroll
        for (int kf = 0; kf < 2; kf++) {
            unsigned vbh[2][4], vbl[2][4];
            #pragma unroll
            for (int gi = 0; gi < 2; gi++) {
                int nrow = gi*16 + (lane & 7) + ((lane >> 4) & 1) * 8;
                int col = ws*32 + kf*16 + (((lane >> 3) & 1) << 3);
                unsigned bd = smb + gb + 10240 + nrow*144 + col*2;
                ldsm4(vbh[gi], bd);
                ldsm4(vbl[gi], bd + 4608);
            }
            #pragma unroll
            for (int mi = 0; mi < 2; mi++) {
                #pragma unroll
                for (int ni = 0; ni < 4; ni++) {
                    int gi = ni >> 1, hf = (ni & 1) * 2;
                    mma16816(oacc[mi][ni], &phi[mi][4*kf], &vbh[gi][hf]);
                    mma16816(oacc[mi][ni], &plo[mi][4*kf], &vbh[gi][hf]);
                    mma16816(oacc[mi][ni], &phi[mi][4*kf], &vbl[gi][hf]);
                }
            }
        }
    }

    #pragma unroll
    for (int mi = 0; mi < 2; mi++) {
        zs[mi][0] += __shfl_xor_sync(0xffffffffu, zs[mi][0], 1);
        zs[mi][0] += __shfl_xor_sync(0xffffffffu, zs[mi][0], 2);
        zs[mi][1] += __shfl_xor_sync(0xffffffffu, zs[mi][1], 1);
        zs[mi][1] += __shfl_xor_sync(0xffffffffu, zs[mi][1], 2);
    }
    __syncthreads();

    float* sO  = (float*)(SM_ + 0);        // [128][34]
    float* sRS = (float*)(SM_ + 18432);    // [128]
    if (ws == 1) {
        #pragma unroll
        for (int mi = 0; mi < 2; mi++) {
            int r = wq*32 + mi*16 + qrow_f;
            if ((lane & 3) == 0) {
                sRS[r]     = zs[mi][0];
                sRS[r + 8] = zs[mi][1];
            }
            #pragma unroll
            for (int ni = 0; ni < 4; ni++) {
                int c = ni*8 + ccol_f;
                *(float2*)&sO[r*34 + c]     = make_float2(oacc[mi][ni][0], oacc[mi][ni][1]);
                *(float2*)&sO[(r+8)*34 + c] = make_float2(oacc[mi][ni][2], oacc[mi][ni][3]);
            }
        }
    }
    __syncthreads();
    if (ws == 0) {
        #pragma unroll
        for (int mi = 0; mi < 2; mi++) {
            int r = wq*32 + mi*16 + qrow_f;
            float inv0 = 1.0f / (zs[mi][0] + sRS[r]     + 1e-5f);
            float inv8 = 1.0f / (zs[mi][1] + sRS[r + 8] + 1e-5f);
            size_t o0 = ((size_t)b * TT + t0 + r)     * DD + h * 32;
            size_t o8 = ((size_t)b * TT + t0 + r + 8) * DD + h * 32;
            #pragma unroll
            for (int ni = 0; ni < 4; ni++) {
                int c = ni*8 + ccol_f;
                float2 p0 = *(const float2*)&sO[r*34 + c];
                float2 p8 = *(const float2*)&sO[(r+8)*34 + c];
                float v0 = (oacc[mi][ni][0] + p0.x) * inv0;
                float v1 = (oacc[mi][ni][1] + p0.y) * inv0;
                float v2 = (oacc[mi][ni][2] + p8.x) * inv8;
                float v3 = (oacc[mi][ni][3] + p8.y) * inv8;
                unsigned h0 = cvt2bf(v1, v0);
                unsigned h8 = cvt2bf(v3, v2);
                float f0 = __uint_as_float(h0 << 16), f1 = __uint_as_float(h0 & 0xFFFF0000u);
                float f2 = __uint_as_float(h8 << 16), f3 = __uint_as_float(h8 & 0xFFFF0000u);
                *(unsigned*)&g_athi[o0 + c] = h0;
                *(unsigned*)&g_atlo[o0 + c] = cvt2bf(v1 - f1, v0 - f0);
                *(unsigned*)&g_athi[o8 + c] = h8;
                *(unsigned*)&g_atlo[o8 + c] = cvt2bf(v3 - f3, v2 - f2);
            }
        }
    }
}

__global__ __launch_bounds__(256) void ln_kernel(const float* __restrict__ a,
                                                 const float* __restrict__ b,
                                                 const float* __restrict__ g,
                                                 const float* __restrict__ be,
                                                 float* __restrict__ out,
                                                 int dosplit)
{
    int w    = (blockIdx.x * 256 + threadIdx.x) >> 5;
    int lane = threadIdx.x & 31;
    const float* ap = a + (size_t)w * 256;
    const float* bp = b + (size_t)w * 256;
    float v[8]; float s = 0.0f;
    #pragma unroll
    for (int u = 0; u < 8; u++) { v[u] = ap[lane + 32*u] + bp[lane + 32*u]; s += v[u]; }
    #pragma unroll
    for (int off = 16; off; off >>= 1) s += __shfl_xor_sync(0xffffffffu, s, off);
    float mu = s * (1.0f / 256.0f);
    float vs = 0.0f;
    #pragma unroll
    for (int u = 0; u < 8; u++) { float d = v[u] - mu; vs = fmaf(d, d, vs); }
    #pragma unroll
    for (int off = 16; off; off >>= 1) vs += __shfl_xor_sync(0xffffffffu, vs, off);
    float rstd = rsqrtf(vs * (1.0f / 256.0f) + 1e-5f);
    #pragma unroll
    for (int u = 0; u < 8; u++) {
        int col = lane + 32*u;
        float o = (v[u] - mu) * rstd * g[col] + be[col];
        out[(size_t)w * 256 + col] = o;
        if (dosplit) {
            __nv_bfloat16 hh = __float2bfloat16(o);
            g_zhi[(size_t)w * 256 + col] = hh;
            g_zlo[(size_t)w * 256 + col] = __float2bfloat16(o - __bfloat162float(hh));
        }
    }
}

extern "C" void kernel_launch(void* const* d_in, const int* in_sizes, int n_in,
                              void* d_out, int out_size)
{
    const float* x    = (const float*)d_in[0];
    const void*  mask = d_in[1];
    const float* rel  = (const float*)d_in[2];
    const float* pw1  = (const float*)d_in[6];
    const float* pb1  = (const float*)d_in[7];
    const float* pw2  = (const float*)d_in[8];
    const float* pb2  = (const float*)d_in[9];
    const float* bo   = (const float*)d_in[11];
    const float* bfv  = (const float*)d_in[13];
    const float* g1   = (const float*)d_in[14];
    const float* be1  = (const float*)d_in[15];
    const float* g2   = (const float*)d_in[16];
    const float* be2  = (const float*)d_in[17];

    float *qraw, *y, *zz;
    __nv_bfloat16 *xhi, *xlo, *athi, *atlo, *zhi, *zlo;
    cudaGetSymbolAddress((void**)&qraw, g_qraw);
    cudaGetSymbolAddress((void**)&y,    g_y);
    cudaGetSymbolAddress((void**)&zz,   g_zz);
    cudaGetSymbolAddress((void**)&xhi,  g_xhi);
    cudaGetSymbolAddress((void**)&xlo,  g_xlo);
    cudaGetSymbolAddress((void**)&athi, g_athi);
    cudaGetSymbolAddress((void**)&atlo, g_atlo);
    cudaGetSymbolAddress((void**)&zhi,  g_zhi);
    cudaGetSymbolAddress((void**)&zlo,  g_zlo);

    static cudaStream_t s1;
    static cudaEvent_t evFork, evJoin;
    static int inited = 0;
    if (!inited) {
        cudaStreamCreateWithFlags(&s1, cudaStreamNonBlocking);
        cudaEventCreateWithFlags(&evFork, cudaEventDisableTiming);
        cudaEventCreateWithFlags(&evJoin, cudaEventDisableTiming);
        cudaFuncSetAttribute(tcmma, cudaFuncAttributeMaxDynamicSharedMemorySize, MM_SMEM);
        cudaFuncSetAttribute(attn_mma_kernel, cudaFuncAttributeMaxDynamicSharedMemorySize, AT_SMEM);
        inited = 1;
    }

    // fork: branch B (splits + QKV GEMM) on s1, branch A (lut/detect/maskfuse) on 0
    cudaEventRecord(evFork, 0);
    cudaStreamWaitEvent(s1, evFork, 0);

    prep_split<<<2688, 256, 0, s1>>>(x, (const float*)d_in[3], (const float*)d_in[4],
                                     (const float*)d_in[5], (const float*)d_in[10],
                                     (const float*)d_in[12]);
    tcmma<<<dim3(32, 4, 3), 256, MM_SMEM, s1>>>(xhi, xlo, 0, nullptr, qraw, qraw, qraw, 0, 1);

    lut_all<<<8, 256>>>(pw1, pb1, pw2, pb2);
    detect_kernel<<<256, 256>>>((const unsigned*)mask);
    maskfuse_kernel<<<4096, 256>>>(rel, mask);

    cudaEventRecord(evJoin, s1);
    cudaStreamWaitEvent(0, evJoin, 0);

    attn_mma_kernel<<<dim3(8, 32), 256, AT_SMEM>>>();

    tcmma<<<dim3(32, 4, 1), 256, MM_SMEM>>>(athi, atlo, 3, bo, y, y, y, 0, 0);
    ln_kernel<<<512, 256>>>(x, y, g1, be1, zz, 1);
    tcmma<<<dim3(32, 4, 1), 256, MM_SMEM>>>(zhi, zlo, 4, bfv, qraw, qraw, qraw, 1, 0);
    ln_kernel<<<512, 256>>>(zz, qraw, g2, be2, (float*)d_out, 0);
}